// round 2
// baseline (speedup 1.0000x reference)
#include <cuda_runtime.h>
#include <math.h>

// Problem constants (fixed shapes)
#define BB 2
#define TT 2048
#define CC 2048
#define HH 16
#define DD 128
#define MM (BB*TT)          // 4096 rows
#define QSCALE 0.08838834764831845f  // 1/sqrt(128)

// ---------------- scratch (device globals; no allocation allowed) ----------
__device__ float g_q [BB*HH*TT*DD];  // [B,H,T,D]
__device__ float g_k [BB*HH*TT*DD];
__device__ float g_v [BB*HH*TT*DD];
__device__ float g_y [MM*CC];        // attention output, [B,T,C]
__device__ float g_t0[MM*CC];        // proj out / fc out
__device__ float g_t1[MM*CC];        // x1

// ---------------------------------------------------------------------------
// NT GEMM: out[m,n] = sum_k A[m,k] * Wt[n,k]  (+bias, epilogue variants)
// A: [M,K] row-major, Wt: [N,K] row-major. BM=BN=128, BK=8, 256 thr, 8x8/thr.
// Double-buffered smem (one barrier per k-step, global prefetch overlapped).
// epi 0: scatter to [B,H,T,D] with *scale   (QKV projections)
// epi 1: out[m*N+n] = v                      (FC)
// epi 2: out[m*N+n] = v * mask[m]            (attn proj)
// ---------------------------------------------------------------------------
__global__ __launch_bounds__(256) void gemm_nt_kernel(
    const float* __restrict__ A, const float* __restrict__ Wt,
    const float* __restrict__ bias, const float* __restrict__ mask,
    float* __restrict__ out, int N, int K, float scale, int epi)
{
    __shared__ float As[2][8][128];
    __shared__ float Bs[2][8][128];

    const int tid = threadIdx.x;
    const int tx = tid & 15;
    const int ty = tid >> 4;
    const int m0 = blockIdx.y * 128;
    const int n0 = blockIdx.x * 128;

    float acc[8][8];
#pragma unroll
    for (int i = 0; i < 8; i++)
#pragma unroll
        for (int j = 0; j < 8; j++) acc[i][j] = 0.f;

    const int lr  = tid >> 1;          // 0..127
    const int lc4 = (tid & 1) * 4;     // 0 or 4
    const float* Ag = A  + (size_t)(m0 + lr) * K + lc4;
    const float* Bg = Wt + (size_t)(n0 + lr) * K + lc4;

    // preload tile 0
    float4 av = *(const float4*)(Ag);
    float4 bv = *(const float4*)(Bg);
    As[0][lc4+0][lr] = av.x; As[0][lc4+1][lr] = av.y;
    As[0][lc4+2][lr] = av.z; As[0][lc4+3][lr] = av.w;
    Bs[0][lc4+0][lr] = bv.x; Bs[0][lc4+1][lr] = bv.y;
    Bs[0][lc4+2][lr] = bv.z; Bs[0][lc4+3][lr] = bv.w;
    __syncthreads();

    int buf = 0;
    for (int k0 = 8; k0 <= K; k0 += 8) {
        // prefetch next tile into registers (overlaps with compute below)
        if (k0 < K) {
            av = *(const float4*)(Ag + k0);
            bv = *(const float4*)(Bg + k0);
        }
        // compute on current buffer
#pragma unroll
        for (int k = 0; k < 8; k++) {
            float a[8], b[8];
            *(float4*)(a)     = *(const float4*)&As[buf][k][ty*4];
            *(float4*)(a + 4) = *(const float4*)&As[buf][k][64 + ty*4];
            *(float4*)(b)     = *(const float4*)&Bs[buf][k][tx*4];
            *(float4*)(b + 4) = *(const float4*)&Bs[buf][k][64 + tx*4];
#pragma unroll
            for (int i = 0; i < 8; i++)
#pragma unroll
                for (int j = 0; j < 8; j++) acc[i][j] += a[i] * b[j];
        }
        if (k0 < K) {
            const int nb = buf ^ 1;
            As[nb][lc4+0][lr] = av.x; As[nb][lc4+1][lr] = av.y;
            As[nb][lc4+2][lr] = av.z; As[nb][lc4+3][lr] = av.w;
            Bs[nb][lc4+0][lr] = bv.x; Bs[nb][lc4+1][lr] = bv.y;
            Bs[nb][lc4+2][lr] = bv.z; Bs[nb][lc4+3][lr] = bv.w;
            __syncthreads();
            buf = nb;
        }
    }

#pragma unroll
    for (int i = 0; i < 8; i++) {
        const int row = (i < 4) ? (ty*4 + i) : (64 + ty*4 + i - 4);
        const int m   = m0 + row;
#pragma unroll
        for (int j = 0; j < 8; j++) {
            const int col = (j < 4) ? (tx*4 + j) : (64 + tx*4 + j - 4);
            const int n   = n0 + col;
            float v = acc[i][j] + bias[n];
            if (epi == 0) {
                const int b  = m >> 11;          // /T
                const int t  = m & (TT - 1);
                const int h  = n >> 7;           // /D
                const int dd = n & (DD - 1);
                out[(((size_t)(b*HH + h))*TT + t)*DD + dd] = v * scale;
            } else if (epi == 1) {
                out[(size_t)m * N + n] = v;
            } else {
                out[(size_t)m * N + n] = v * mask[m];
            }
        }
    }
}

// ---------------------------------------------------------------------------
// Causal flash attention, fp32. Br=Bc=64, D=128.
// grid: (T/64, B*H), 256 threads (16x16). Q pre-scaled by 1/sqrt(d).
// smem: Qs[64][128], Ks[64][129], Vs[64][129], Ps[64][65]  (padded strides
// chosen for conflict-free compute loads).
// ---------------------------------------------------------------------------
#define FLASH_SMEM ((64*128 + 64*129 + 64*129 + 64*65) * 4)   // 115456 B

__global__ __launch_bounds__(256) void flash_kernel(
    const float* __restrict__ Q, const float* __restrict__ K,
    const float* __restrict__ V, float* __restrict__ Y)
{
    extern __shared__ float sm[];
    float* Qs = sm;                    // stride 128
    float* Ks = Qs + 64*128;           // stride 129
    float* Vs = Ks + 64*129;           // stride 129
    float* Ps = Vs + 64*129;           // stride 65

    const int qt = blockIdx.x;
    const int bh = blockIdx.y;
    const int b  = bh >> 4;
    const int h  = bh & 15;
    const float* Qb = Q + (size_t)bh * TT * DD;
    const float* Kb = K + (size_t)bh * TT * DD;
    const float* Vb = V + (size_t)bh * TT * DD;

    const int tid = threadIdx.x;
    const int tx  = tid & 15;
    const int ty  = tid >> 4;

    // load Q tile (contiguous float4 copy)
    {
        const float4* Qg = (const float4*)(Qb + (size_t)qt * 64 * DD);
        float4* Q4 = (float4*)Qs;
#pragma unroll
        for (int i = 0; i < 8; i++) Q4[i*256 + tid] = Qg[i*256 + tid];
    }

    float m_i[4], l_i[4], o[4][8];
#pragma unroll
    for (int i = 0; i < 4; i++) {
        m_i[i] = -1e30f; l_i[i] = 0.f;
#pragma unroll
        for (int jj = 0; jj < 8; jj++) o[i][jj] = 0.f;
    }

    for (int kt = 0; kt <= qt; kt++) {
        __syncthreads();   // protect smem from previous iteration readers
        // load K,V tiles with padded scalar stores
#pragma unroll
        for (int i = 0; i < 8; i++) {
            const int lin = i*1024 + tid*4;
            const int r = lin >> 7, c = lin & 127;
            float4 kv = *(const float4*)(Kb + (size_t)kt*64*DD + lin);
            float4 vv = *(const float4*)(Vb + (size_t)kt*64*DD + lin);
            float* kd = Ks + r*129 + c;
            kd[0] = kv.x; kd[1] = kv.y; kd[2] = kv.z; kd[3] = kv.w;
            float* vd = Vs + r*129 + c;
            vd[0] = vv.x; vd[1] = vv.y; vd[2] = vv.z; vd[3] = vv.w;
        }
        __syncthreads();

        // S = Q K^T  (rows ty*4+i, cols j*16+tx)
        float s[4][4];
#pragma unroll
        for (int i = 0; i < 4; i++)
#pragma unroll
            for (int j = 0; j < 4; j++) s[i][j] = 0.f;

#pragma unroll 8
        for (int kk = 0; kk < 128; kk++) {
            float qf[4], kf[4];
#pragma unroll
            for (int i = 0; i < 4; i++) qf[i] = Qs[(ty*4 + i)*128 + kk];
#pragma unroll
            for (int j = 0; j < 4; j++) kf[j] = Ks[(j*16 + tx)*129 + kk];
#pragma unroll
            for (int i = 0; i < 4; i++)
#pragma unroll
                for (int j = 0; j < 4; j++) s[i][j] += qf[i] * kf[j];
        }

        if (kt == qt) {   // causal mask inside diagonal tile
#pragma unroll
            for (int i = 0; i < 4; i++)
#pragma unroll
                for (int j = 0; j < 4; j++)
                    if ((j*16 + tx) > (ty*4 + i)) s[i][j] = -1e30f;
        }

        // online softmax
#pragma unroll
        for (int i = 0; i < 4; i++) {
            float mt = fmaxf(fmaxf(s[i][0], s[i][1]), fmaxf(s[i][2], s[i][3]));
#pragma unroll
            for (int off = 8; off; off >>= 1)
                mt = fmaxf(mt, __shfl_xor_sync(0xffffffffu, mt, off, 16));
            const float mn   = fmaxf(m_i[i], mt);
            const float corr = __expf(m_i[i] - mn);
            m_i[i] = mn;
            float rs = 0.f;
#pragma unroll
            for (int j = 0; j < 4; j++) { s[i][j] = __expf(s[i][j] - mn); rs += s[i][j]; }
#pragma unroll
            for (int off = 8; off; off >>= 1)
                rs += __shfl_xor_sync(0xffffffffu, rs, off, 16);
            l_i[i] = l_i[i]*corr + rs;
#pragma unroll
            for (int jj = 0; jj < 8; jj++) o[i][jj] *= corr;
#pragma unroll
            for (int j = 0; j < 4; j++) Ps[(ty*4 + i)*65 + j*16 + tx] = s[i][j];
        }
        __syncthreads();

        // O += P V   (O cols jj*16+tx)
#pragma unroll 4
        for (int ss = 0; ss < 64; ss++) {
            float pv[4];
#pragma unroll
            for (int i = 0; i < 4; i++) pv[i] = Ps[(ty*4 + i)*65 + ss];
#pragma unroll
            for (int jj = 0; jj < 8; jj++) {
                const float vf = Vs[ss*129 + jj*16 + tx];
#pragma unroll
                for (int i = 0; i < 4; i++) o[i][jj] += pv[i] * vf;
            }
        }
    }

    // write out: Y is [B,T,C] with C = H*D
#pragma unroll
    for (int i = 0; i < 4; i++) {
        const float inv = 1.0f / l_i[i];
        const int tq = qt*64 + ty*4 + i;
        float* yr = Y + ((size_t)(b*TT + tq))*CC + h*DD;
#pragma unroll
        for (int jj = 0; jj < 8; jj++) yr[jj*16 + tx] = o[i][jj] * inv;
    }
}

// ---------------------------------------------------------------------------
// Fused LayerNorm(z)*g+b + residual.  One block (256 thr) per row of 2048.
// ---------------------------------------------------------------------------
__global__ __launch_bounds__(256) void ln_add_kernel(
    const float* __restrict__ z, const float* __restrict__ res,
    const float* __restrict__ gam, const float* __restrict__ bet,
    float* __restrict__ out)
{
    __shared__ float red[256];
    const int row = blockIdx.x;
    const int tid = threadIdx.x;
    const float* zr = z + (size_t)row * CC;

    float v[8];
#pragma unroll
    for (int i = 0; i < 2; i++) {
        float4 t4 = *(const float4*)(zr + i*1024 + tid*4);
        v[i*4+0] = t4.x; v[i*4+1] = t4.y; v[i*4+2] = t4.z; v[i*4+3] = t4.w;
    }

    float s = 0.f;
#pragma unroll
    for (int i = 0; i < 8; i++) s += v[i];
    red[tid] = s; __syncthreads();
#pragma unroll
    for (int off = 128; off; off >>= 1) {
        if (tid < off) red[tid] += red[tid + off];
        __syncthreads();
    }
    const float mean = red[0] * (1.0f / 2048.0f);
    __syncthreads();

    float vs = 0.f;
#pragma unroll
    for (int i = 0; i < 8; i++) { const float d = v[i] - mean; vs += d * d; }
    red[tid] = vs; __syncthreads();
#pragma unroll
    for (int off = 128; off; off >>= 1) {
        if (tid < off) red[tid] += red[tid + off];
        __syncthreads();
    }
    const float rstd = rsqrtf(red[0] * (1.0f / 2048.0f) + 1e-6f);

    const float* rr = res + (size_t)row * CC;
    float* orow = out + (size_t)row * CC;
#pragma unroll
    for (int i = 0; i < 2; i++) {
        const int c0 = i*1024 + tid*4;
        float4 g4 = *(const float4*)(gam + c0);
        float4 b4 = *(const float4*)(bet + c0);
        float4 r4 = *(const float4*)(rr + c0);
        float4 ov;
        ov.x = (v[i*4+0] - mean)*rstd*g4.x + b4.x + r4.x;
        ov.y = (v[i*4+1] - mean)*rstd*g4.y + b4.y + r4.y;
        ov.z = (v[i*4+2] - mean)*rstd*g4.z + b4.z + r4.z;
        ov.w = (v[i*4+3] - mean)*rstd*g4.w + b4.w + r4.w;
        *(float4*)(orow + c0) = ov;
    }
}

// ---------------------------------------------------------------------------
extern "C" void kernel_launch(void* const* d_in, const int* in_sizes, int n_in,
                              void* d_out, int out_size)
{
    const float* x    = (const float*)d_in[0];
    const float* mask = (const float*)d_in[1];
    const float* Wq   = (const float*)d_in[2];
    const float* bq   = (const float*)d_in[3];
    const float* Wk   = (const float*)d_in[4];
    const float* bk   = (const float*)d_in[5];
    const float* Wv   = (const float*)d_in[6];
    const float* bv   = (const float*)d_in[7];
    const float* Wp   = (const float*)d_in[8];
    const float* bp   = (const float*)d_in[9];
    const float* Wfc  = (const float*)d_in[10];
    const float* bfc  = (const float*)d_in[11];
    const float* ln_g = (const float*)d_in[12];
    const float* ln_b = (const float*)d_in[13];

    float *q, *k, *v, *y, *t0, *t1;
    cudaGetSymbolAddress((void**)&q,  g_q);
    cudaGetSymbolAddress((void**)&k,  g_k);
    cudaGetSymbolAddress((void**)&v,  g_v);
    cudaGetSymbolAddress((void**)&y,  g_y);
    cudaGetSymbolAddress((void**)&t0, g_t0);
    cudaGetSymbolAddress((void**)&t1, g_t1);

    cudaFuncSetAttribute(flash_kernel,
                         cudaFuncAttributeMaxDynamicSharedMemorySize, FLASH_SMEM);

    const dim3 gg(CC/128, MM/128);  // (16, 32)

    // QKV projections (scatter to [B,H,T,D]; Q pre-scaled by 1/sqrt(d))
    gemm_nt_kernel<<<gg, 256>>>(x, Wq, bq, nullptr, q, CC, CC, QSCALE, 0);
    gemm_nt_kernel<<<gg, 256>>>(x, Wk, bk, nullptr, k, CC, CC, 1.0f,   0);
    gemm_nt_kernel<<<gg, 256>>>(x, Wv, bv, nullptr, v, CC, CC, 1.0f,   0);

    // causal flash attention -> y [B,T,C]
    flash_kernel<<<dim3(TT/64, BB*HH), 256, FLASH_SMEM>>>(q, k, v, y);

    // output projection (+bias, *mask) -> t0
    gemm_nt_kernel<<<gg, 256>>>(y, Wp, bp, mask, t0, CC, CC, 1.0f, 2);

    // x1 = LN(t0) + x -> t1
    ln_add_kernel<<<MM, 256>>>(t0, x, ln_g, ln_b, t1);

    // fc = x1 @ Wfc^T + bfc -> t0
    gemm_nt_kernel<<<gg, 256>>>(t1, Wfc, bfc, nullptr, t0, CC, CC, 1.0f, 1);

    // out = LN(t0) + x1
    ln_add_kernel<<<MM, 256>>>(t0, t1, ln_g, ln_b, (float*)d_out);
}

// round 6
// speedup vs baseline: 1.6251x; 1.6251x over previous
#include <cuda_runtime.h>
#include <cuda_bf16.h>
#include <math.h>
#include <cstdint>

// Problem constants (fixed shapes)
#define BB 2
#define TT 2048
#define CC 2048
#define HH 16
#define DD 128
#define MM (BB*TT)          // 4096 rows
#define KK 2048
#define QSCALE 0.08838834764831845f  // 1/sqrt(128)

// ---------------- scratch (device globals; no allocation allowed) ----------
__device__ float g_q [BB*HH*TT*DD];  // [B,H,T,D] fp32
__device__ float g_k [BB*HH*TT*DD];
__device__ float g_v [BB*HH*TT*DD];
__device__ float g_y [MM*CC];        // attention output, [B,T,C]
__device__ float g_t0[MM*CC];        // proj out / fc out
__device__ float g_t1[MM*CC];        // x1

// split-bf16 operands
__device__ __nv_bfloat16 g_xh[MM*CC],  g_xl[MM*CC];    // x split
__device__ __nv_bfloat16 g_ah[MM*CC],  g_al[MM*CC];    // reused: y split, then t1 split
__device__ __nv_bfloat16 g_wh[5*CC*CC], g_wl[5*CC*CC]; // Wq,Wk,Wv,Wp,Wfc splits

// ============================ helpers ======================================
__device__ __forceinline__ uint32_t smem_u32(const void* p) {
    uint32_t a;
    asm("{ .reg .u64 t; cvta.to.shared.u64 t, %1; cvt.u32.u64 %0, t; }" : "=r"(a) : "l"(p));
    return a;
}

#define CP_ASYNC_16(dst_u32, src_ptr) \
    asm volatile("cp.async.cg.shared.global [%0], [%1], 16;" :: "r"(dst_u32), "l"(src_ptr))
#define CP_ASYNC_COMMIT() asm volatile("cp.async.commit_group;" ::: "memory")
#define CP_ASYNC_WAIT1()  asm volatile("cp.async.wait_group 1;" ::: "memory")

__device__ __forceinline__ void mma16816(float* d, const uint32_t* a,
                                         uint32_t b0, uint32_t b1) {
    asm volatile(
        "mma.sync.aligned.m16n8k16.row.col.f32.bf16.bf16.f32 "
        "{%0,%1,%2,%3}, {%4,%5,%6,%7}, {%8,%9}, {%0,%1,%2,%3};"
        : "+f"(d[0]), "+f"(d[1]), "+f"(d[2]), "+f"(d[3])
        : "r"(a[0]), "r"(a[1]), "r"(a[2]), "r"(a[3]), "r"(b0), "r"(b1));
}

// ---------------------------------------------------------------------------
// Split-bf16 NT GEMM on mma.sync: D[m,n] = sum_k A[m,k]*B[n,k], fp32 accum.
// D = AhBh + AhBl + AlBh (AlBl dropped, err ~2^-16).
// CTA 128x128, 8 warps (4x2), warp tile 32x64, BK=32, cp.async double buffer.
// Smem row stride 40 halves (80B): fragment LDS phases are conflict-free.
// epi 0: scatter to [B,H,T,D] * scale; 1: plain; 2: * mask[m]
// ---------------------------------------------------------------------------
#define BKH 32
#define NST (KK/BKH)                 // 64
#define SRB 80                       // smem row stride bytes (40 halves)
#define TILE_TERM_B (128*SRB)        // 10240
#define STAGE_B (4*TILE_TERM_B)      // 40960: Ah,Al,Bh,Bl
#define GEMM_SMEM (2*STAGE_B)        // 81920

__global__ __launch_bounds__(256) void gemm_mma_kernel(
    const __nv_bfloat16* __restrict__ Ah, const __nv_bfloat16* __restrict__ Al,
    const __nv_bfloat16* __restrict__ Bh, const __nv_bfloat16* __restrict__ Bl,
    const float* __restrict__ bias, const float* __restrict__ mask,
    float* __restrict__ out, float scale, int epi)
{
    extern __shared__ char sm_[];
    const uint32_t sb = smem_u32(sm_);
    const int tid    = threadIdx.x;
    const int wid    = tid >> 5;
    const int lane   = tid & 31;
    const int warp_m = wid & 3;
    const int warp_n = wid >> 2;
    const int g      = lane >> 2;   // group id (0..7)
    const int t      = lane & 3;    // thread-in-group
    const int m0 = blockIdx.y * 128;
    const int n0 = blockIdx.x * 128;

    const __nv_bfloat16* srcs[4] = { Ah + (size_t)m0*KK, Al + (size_t)m0*KK,
                                     Bh + (size_t)n0*KK, Bl + (size_t)n0*KK };

    float acc[2][8][4];
#pragma unroll
    for (int mt = 0; mt < 2; mt++)
#pragma unroll
        for (int nt = 0; nt < 8; nt++)
#pragma unroll
            for (int r = 0; r < 4; r++) acc[mt][nt][r] = 0.f;

    // ---- async stage loader: stage index s loads k0 = s*32 into buffer s&1
    const int cid0 = tid;          // chunk ids: tid, tid+256
    // chunk: row = cid>>2 (0..127), c = cid&3 (16B chunk within 64B row)
    auto LOAD_STAGE = [&](int s) {
        const int k0 = s * BKH;
        const uint32_t base = sb + (uint32_t)(s & 1) * STAGE_B;
#pragma unroll
        for (int tl = 0; tl < 4; tl++) {
            const __nv_bfloat16* src = srcs[tl];
#pragma unroll
            for (int i = 0; i < 2; i++) {
                const int cid = cid0 + i * 256;
                const int row = cid >> 2, c = cid & 3;
                const uint32_t dst = base + (uint32_t)tl * TILE_TERM_B
                                   + (uint32_t)row * SRB + (uint32_t)c * 16;
                CP_ASYNC_16(dst, src + (size_t)row * KK + k0 + c * 8);
            }
        }
        CP_ASYNC_COMMIT();
    };

    LOAD_STAGE(0);
    LOAD_STAGE(1);

    for (int s = 0; s < NST; s++) {
        CP_ASYNC_WAIT1();
        __syncthreads();

        const uint32_t base = sb + (uint32_t)(s & 1) * STAGE_B;
        const uint32_t pAh = base;
        const uint32_t pAl = base + TILE_TERM_B;
        const uint32_t pBh = base + 2*TILE_TERM_B;
        const uint32_t pBl = base + 3*TILE_TERM_B;

#pragma unroll
        for (int ks = 0; ks < 2; ks++) {
            const int kc = ks * 16;             // k offset within stage
            const int kb = (kc + 2*t) * 2;      // byte offset of k pair
            uint32_t aH[2][4], aL[2][4];
#pragma unroll
            for (int mt = 0; mt < 2; mt++) {
                const int r = warp_m*32 + mt*16 + g;
                uint32_t a0, a1, a2, a3;
                asm volatile("ld.shared.b32 %0, [%1];" : "=r"(a0) : "r"(pAh + r*SRB + kb));
                asm volatile("ld.shared.b32 %0, [%1];" : "=r"(a1) : "r"(pAh + (r+8)*SRB + kb));
                asm volatile("ld.shared.b32 %0, [%1];" : "=r"(a2) : "r"(pAh + r*SRB + kb + 16));
                asm volatile("ld.shared.b32 %0, [%1];" : "=r"(a3) : "r"(pAh + (r+8)*SRB + kb + 16));
                aH[mt][0]=a0; aH[mt][1]=a1; aH[mt][2]=a2; aH[mt][3]=a3;
                asm volatile("ld.shared.b32 %0, [%1];" : "=r"(a0) : "r"(pAl + r*SRB + kb));
                asm volatile("ld.shared.b32 %0, [%1];" : "=r"(a1) : "r"(pAl + (r+8)*SRB + kb));
                asm volatile("ld.shared.b32 %0, [%1];" : "=r"(a2) : "r"(pAl + r*SRB + kb + 16));
                asm volatile("ld.shared.b32 %0, [%1];" : "=r"(a3) : "r"(pAl + (r+8)*SRB + kb + 16));
                aL[mt][0]=a0; aL[mt][1]=a1; aL[mt][2]=a2; aL[mt][3]=a3;
            }
#pragma unroll
            for (int nt = 0; nt < 8; nt++) {
                const int n = warp_n*64 + nt*8 + g;
                uint32_t bh0, bh1, bl0, bl1;
                asm volatile("ld.shared.b32 %0, [%1];" : "=r"(bh0) : "r"(pBh + n*SRB + kb));
                asm volatile("ld.shared.b32 %0, [%1];" : "=r"(bh1) : "r"(pBh + n*SRB + kb + 16));
                asm volatile("ld.shared.b32 %0, [%1];" : "=r"(bl0) : "r"(pBl + n*SRB + kb));
                asm volatile("ld.shared.b32 %0, [%1];" : "=r"(bl1) : "r"(pBl + n*SRB + kb + 16));
#pragma unroll
                for (int mt = 0; mt < 2; mt++) {
                    mma16816(acc[mt][nt], aH[mt], bh0, bh1);
                    mma16816(acc[mt][nt], aH[mt], bl0, bl1);
                    mma16816(acc[mt][nt], aL[mt], bh0, bh1);
                }
            }
        }
        __syncthreads();
        if (s + 2 < NST) LOAD_STAGE(s + 2);
        else             CP_ASYNC_COMMIT();     // keep group count consistent
    }

    // ---- epilogue: d0,d1 -> (row g, col 2t,2t+1); d2,d3 -> (row g+8, same)
#pragma unroll
    for (int mt = 0; mt < 2; mt++) {
#pragma unroll
        for (int nt = 0; nt < 8; nt++) {
            const float* d = acc[mt][nt];
            const int r0 = m0 + warp_m*32 + mt*16 + g;
            const int r1 = r0 + 8;
            const int n  = n0 + warp_n*64 + nt*8 + 2*t;
            const float2 b2 = *(const float2*)(bias + n);
            float v00 = d[0] + b2.x, v01 = d[1] + b2.y;
            float v10 = d[2] + b2.x, v11 = d[3] + b2.y;
            if (epi == 0) {
                const int h  = n >> 7;
                const int dd = n & (DD - 1);
                const int b0i = r0 >> 11, t0i = r0 & (TT-1);
                const int b1i = r1 >> 11, t1i = r1 & (TT-1);
                *(float2*)(out + (((size_t)(b0i*HH + h))*TT + t0i)*DD + dd)
                    = make_float2(v00*scale, v01*scale);
                *(float2*)(out + (((size_t)(b1i*HH + h))*TT + t1i)*DD + dd)
                    = make_float2(v10*scale, v11*scale);
            } else if (epi == 1) {
                *(float2*)(out + (size_t)r0*CC + n) = make_float2(v00, v01);
                *(float2*)(out + (size_t)r1*CC + n) = make_float2(v10, v11);
            } else {
                const float mk0 = mask[r0], mk1 = mask[r1];
                *(float2*)(out + (size_t)r0*CC + n) = make_float2(v00*mk0, v01*mk0);
                *(float2*)(out + (size_t)r1*CC + n) = make_float2(v10*mk1, v11*mk1);
            }
        }
    }
}

// ---------------------------------------------------------------------------
// split fp32 -> bf16 hi + bf16 lo (residual)
// ---------------------------------------------------------------------------
__global__ __launch_bounds__(256) void split_kernel(
    const float* __restrict__ in, __nv_bfloat16* __restrict__ hi,
    __nv_bfloat16* __restrict__ lo)
{
    const int i = blockIdx.x * 256 + threadIdx.x;
    float4 v = ((const float4*)in)[i];
    float f[4] = {v.x, v.y, v.z, v.w};
    union U { __nv_bfloat16 b[4]; uint2 u; } H, L;
#pragma unroll
    for (int j = 0; j < 4; j++) {
        H.b[j] = __float2bfloat16(f[j]);
        L.b[j] = __float2bfloat16(f[j] - __bfloat162float(H.b[j]));
    }
    ((uint2*)hi)[i] = H.u;
    ((uint2*)lo)[i] = L.u;
}

// ---------------------------------------------------------------------------
// Causal flash attention, fp32 (unchanged — passing since R2).
// ---------------------------------------------------------------------------
#define FLASH_SMEM ((64*128 + 64*129 + 64*129 + 64*65) * 4)   // 115456 B

__global__ __launch_bounds__(256) void flash_kernel(
    const float* __restrict__ Q, const float* __restrict__ K,
    const float* __restrict__ V, float* __restrict__ Y)
{
    extern __shared__ float sm[];
    float* Qs = sm;
    float* Ks = Qs + 64*128;
    float* Vs = Ks + 64*129;
    float* Ps = Vs + 64*129;

    const int qt = blockIdx.x;
    const int bh = blockIdx.y;
    const int b  = bh >> 4;
    const int h  = bh & 15;
    const float* Qb = Q + (size_t)bh * TT * DD;
    const float* Kb = K + (size_t)bh * TT * DD;
    const float* Vb = V + (size_t)bh * TT * DD;

    const int tid = threadIdx.x;
    const int tx  = tid & 15;
    const int ty  = tid >> 4;

    {
        const float4* Qg = (const float4*)(Qb + (size_t)qt * 64 * DD);
        float4* Q4 = (float4*)Qs;
#pragma unroll
        for (int i = 0; i < 8; i++) Q4[i*256 + tid] = Qg[i*256 + tid];
    }

    float m_i[4], l_i[4], o[4][8];
#pragma unroll
    for (int i = 0; i < 4; i++) {
        m_i[i] = -1e30f; l_i[i] = 0.f;
#pragma unroll
        for (int jj = 0; jj < 8; jj++) o[i][jj] = 0.f;
    }

    for (int kt = 0; kt <= qt; kt++) {
        __syncthreads();
#pragma unroll
        for (int i = 0; i < 8; i++) {
            const int lin = i*1024 + tid*4;
            const int r = lin >> 7, c = lin & 127;
            float4 kv = *(const float4*)(Kb + (size_t)kt*64*DD + lin);
            float4 vv = *(const float4*)(Vb + (size_t)kt*64*DD + lin);
            float* kd = Ks + r*129 + c;
            kd[0] = kv.x; kd[1] = kv.y; kd[2] = kv.z; kd[3] = kv.w;
            float* vd = Vs + r*129 + c;
            vd[0] = vv.x; vd[1] = vv.y; vd[2] = vv.z; vd[3] = vv.w;
        }
        __syncthreads();

        float s[4][4];
#pragma unroll
        for (int i = 0; i < 4; i++)
#pragma unroll
            for (int j = 0; j < 4; j++) s[i][j] = 0.f;

#pragma unroll 8
        for (int kk = 0; kk < 128; kk++) {
            float qf[4], kf[4];
#pragma unroll
            for (int i = 0; i < 4; i++) qf[i] = Qs[(ty*4 + i)*128 + kk];
#pragma unroll
            for (int j = 0; j < 4; j++) kf[j] = Ks[(j*16 + tx)*129 + kk];
#pragma unroll
            for (int i = 0; i < 4; i++)
#pragma unroll
                for (int j = 0; j < 4; j++) s[i][j] += qf[i] * kf[j];
        }

        if (kt == qt) {
#pragma unroll
            for (int i = 0; i < 4; i++)
#pragma unroll
                for (int j = 0; j < 4; j++)
                    if ((j*16 + tx) > (ty*4 + i)) s[i][j] = -1e30f;
        }

#pragma unroll
        for (int i = 0; i < 4; i++) {
            float mt = fmaxf(fmaxf(s[i][0], s[i][1]), fmaxf(s[i][2], s[i][3]));
#pragma unroll
            for (int off = 8; off; off >>= 1)
                mt = fmaxf(mt, __shfl_xor_sync(0xffffffffu, mt, off, 16));
            const float mn   = fmaxf(m_i[i], mt);
            const float corr = __expf(m_i[i] - mn);
            m_i[i] = mn;
            float rs = 0.f;
#pragma unroll
            for (int j = 0; j < 4; j++) { s[i][j] = __expf(s[i][j] - mn); rs += s[i][j]; }
#pragma unroll
            for (int off = 8; off; off >>= 1)
                rs += __shfl_xor_sync(0xffffffffu, rs, off, 16);
            l_i[i] = l_i[i]*corr + rs;
#pragma unroll
            for (int jj = 0; jj < 8; jj++) o[i][jj] *= corr;
#pragma unroll
            for (int j = 0; j < 4; j++) Ps[(ty*4 + i)*65 + j*16 + tx] = s[i][j];
        }
        __syncthreads();

#pragma unroll 4
        for (int ss = 0; ss < 64; ss++) {
            float pv[4];
#pragma unroll
            for (int i = 0; i < 4; i++) pv[i] = Ps[(ty*4 + i)*65 + ss];
#pragma unroll
            for (int jj = 0; jj < 8; jj++) {
                const float vf = Vs[ss*129 + jj*16 + tx];
#pragma unroll
                for (int i = 0; i < 4; i++) o[i][jj] += pv[i] * vf;
            }
        }
    }

#pragma unroll
    for (int i = 0; i < 4; i++) {
        const float inv = 1.0f / l_i[i];
        const int tq = qt*64 + ty*4 + i;
        float* yr = Y + ((size_t)(b*TT + tq))*CC + h*DD;
#pragma unroll
        for (int jj = 0; jj < 8; jj++) yr[jj*16 + tx] = o[i][jj] * inv;
    }
}

// ---------------------------------------------------------------------------
// Fused LayerNorm(z)*g+b + residual (unchanged — passing since R2).
// ---------------------------------------------------------------------------
__global__ __launch_bounds__(256) void ln_add_kernel(
    const float* __restrict__ z, const float* __restrict__ res,
    const float* __restrict__ gam, const float* __restrict__ bet,
    float* __restrict__ out)
{
    __shared__ float red[256];
    const int row = blockIdx.x;
    const int tid = threadIdx.x;
    const float* zr = z + (size_t)row * CC;

    float v[8];
#pragma unroll
    for (int i = 0; i < 2; i++) {
        float4 t4 = *(const float4*)(zr + i*1024 + tid*4);
        v[i*4+0] = t4.x; v[i*4+1] = t4.y; v[i*4+2] = t4.z; v[i*4+3] = t4.w;
    }

    float s = 0.f;
#pragma unroll
    for (int i = 0; i < 8; i++) s += v[i];
    red[tid] = s; __syncthreads();
#pragma unroll
    for (int off = 128; off; off >>= 1) {
        if (tid < off) red[tid] += red[tid + off];
        __syncthreads();
    }
    const float mean = red[0] * (1.0f / 2048.0f);
    __syncthreads();

    float vs = 0.f;
#pragma unroll
    for (int i = 0; i < 8; i++) { const float d = v[i] - mean; vs += d * d; }
    red[tid] = vs; __syncthreads();
#pragma unroll
    for (int off = 128; off; off >>= 1) {
        if (tid < off) red[tid] += red[tid + off];
        __syncthreads();
    }
    const float rstd = rsqrtf(red[0] * (1.0f / 2048.0f) + 1e-6f);

    const float* rr = res + (size_t)row * CC;
    float* orow = out + (size_t)row * CC;
#pragma unroll
    for (int i = 0; i < 2; i++) {
        const int c0 = i*1024 + tid*4;
        float4 g4 = *(const float4*)(gam + c0);
        float4 b4 = *(const float4*)(bet + c0);
        float4 r4 = *(const float4*)(rr + c0);
        float4 ov;
        ov.x = (v[i*4+0] - mean)*rstd*g4.x + b4.x + r4.x;
        ov.y = (v[i*4+1] - mean)*rstd*g4.y + b4.y + r4.y;
        ov.z = (v[i*4+2] - mean)*rstd*g4.z + b4.z + r4.z;
        ov.w = (v[i*4+3] - mean)*rstd*g4.w + b4.w + r4.w;
        *(float4*)(orow + c0) = ov;
    }
}

// ---------------------------------------------------------------------------
extern "C" void kernel_launch(void* const* d_in, const int* in_sizes, int n_in,
                              void* d_out, int out_size)
{
    const float* x    = (const float*)d_in[0];
    const float* mask = (const float*)d_in[1];
    const float* W[5] = { (const float*)d_in[2],  (const float*)d_in[4],
                          (const float*)d_in[6],  (const float*)d_in[8],
                          (const float*)d_in[10] };                 // Wq,Wk,Wv,Wp,Wfc
    const float* bq   = (const float*)d_in[3];
    const float* bk   = (const float*)d_in[5];
    const float* bv   = (const float*)d_in[7];
    const float* bp   = (const float*)d_in[9];
    const float* bfc  = (const float*)d_in[11];
    const float* ln_g = (const float*)d_in[12];
    const float* ln_b = (const float*)d_in[13];

    float *q, *k, *v, *y, *t0, *t1;
    __nv_bfloat16 *xh, *xl, *ah, *al, *wh, *wl;
    cudaGetSymbolAddress((void**)&q,  g_q);
    cudaGetSymbolAddress((void**)&k,  g_k);
    cudaGetSymbolAddress((void**)&v,  g_v);
    cudaGetSymbolAddress((void**)&y,  g_y);
    cudaGetSymbolAddress((void**)&t0, g_t0);
    cudaGetSymbolAddress((void**)&t1, g_t1);
    cudaGetSymbolAddress((void**)&xh, g_xh);
    cudaGetSymbolAddress((void**)&xl, g_xl);
    cudaGetSymbolAddress((void**)&ah, g_ah);
    cudaGetSymbolAddress((void**)&al, g_al);
    cudaGetSymbolAddress((void**)&wh, g_wh);
    cudaGetSymbolAddress((void**)&wl, g_wl);

    cudaFuncSetAttribute(flash_kernel,
                         cudaFuncAttributeMaxDynamicSharedMemorySize, FLASH_SMEM);
    cudaFuncSetAttribute(gemm_mma_kernel,
                         cudaFuncAttributeMaxDynamicSharedMemorySize, GEMM_SMEM);

    const dim3 gg(CC/128, MM/128);         // (16, 32)
    const int ACT4 = MM*CC/4;              // 2M float4
    const int WT4  = CC*CC/4;              // 1M float4

    // split inputs/weights to bf16 hi/lo
    split_kernel<<<ACT4/256, 256>>>(x, xh, xl);
    for (int i = 0; i < 5; i++)
        split_kernel<<<WT4/256, 256>>>(W[i], wh + (size_t)i*CC*CC, wl + (size_t)i*CC*CC);

    // QKV projections (scatter to [B,H,T,D]; Q pre-scaled by 1/sqrt(d))
    gemm_mma_kernel<<<gg, 256, GEMM_SMEM>>>(xh, xl, wh + 0*(size_t)CC*CC, wl + 0*(size_t)CC*CC,
                                            bq, nullptr, q, QSCALE, 0);
    gemm_mma_kernel<<<gg, 256, GEMM_SMEM>>>(xh, xl, wh + 1*(size_t)CC*CC, wl + 1*(size_t)CC*CC,
                                            bk, nullptr, k, 1.0f, 0);
    gemm_mma_kernel<<<gg, 256, GEMM_SMEM>>>(xh, xl, wh + 2*(size_t)CC*CC, wl + 2*(size_t)CC*CC,
                                            bv, nullptr, v, 1.0f, 0);

    // causal flash attention -> y [B,T,C]
    flash_kernel<<<dim3(TT/64, BB*HH), 256, FLASH_SMEM>>>(q, k, v, y);

    // output projection (+bias, *mask) -> t0
    split_kernel<<<ACT4/256, 256>>>(y, ah, al);
    gemm_mma_kernel<<<gg, 256, GEMM_SMEM>>>(ah, al, wh + 3*(size_t)CC*CC, wl + 3*(size_t)CC*CC,
                                            bp, mask, t0, 1.0f, 2);

    // x1 = LN(t0) + x -> t1
    ln_add_kernel<<<MM, 256>>>(t0, x, ln_g, ln_b, t1);

    // fc = x1 @ Wfc^T + bfc -> t0
    split_kernel<<<ACT4/256, 256>>>(t1, ah, al);
    gemm_mma_kernel<<<gg, 256, GEMM_SMEM>>>(ah, al, wh + 4*(size_t)CC*CC, wl + 4*(size_t)CC*CC,
                                            bfc, nullptr, t0, 1.0f, 1);

    // out = LN(t0) + x1
    ln_add_kernel<<<MM, 256>>>(t0, t1, ln_g, ln_b, (float*)d_out);
}

// round 8
// speedup vs baseline: 2.3317x; 1.4348x over previous
#include <cuda_runtime.h>
#include <cuda_bf16.h>
#include <math.h>
#include <cstdint>

// Problem constants (fixed shapes)
#define BB 2
#define TT 2048
#define CC 2048
#define HH 16
#define DD 128
#define MM (BB*TT)          // 4096 rows
#define KK 2048
#define QSCALE 0.08838834764831845f  // 1/sqrt(128)

// ---------------- scratch (device globals; no allocation allowed) ----------
__device__ __nv_bfloat16 g_qh[BB*HH*TT*DD], g_ql[BB*HH*TT*DD];  // [B,H,T,D]
__device__ __nv_bfloat16 g_kh[BB*HH*TT*DD], g_kl[BB*HH*TT*DD];  // [B,H,T,D]
__device__ __nv_bfloat16 g_vh[BB*HH*TT*DD], g_vl[BB*HH*TT*DD];  // [B,H,D,T] (transposed)
__device__ float g_y [MM*CC];        // attention output, [B,T,C]
__device__ float g_t0[MM*CC];        // proj out / fc out
__device__ float g_t1[MM*CC];        // x1

// split-bf16 operands for GEMMs
__device__ __nv_bfloat16 g_xh[MM*CC],  g_xl[MM*CC];    // x split
__device__ __nv_bfloat16 g_ah[MM*CC],  g_al[MM*CC];    // y split, then t1 split
__device__ __nv_bfloat16 g_wh[5*CC*CC], g_wl[5*CC*CC]; // Wq,Wk,Wv,Wp,Wfc splits

// ============================ helpers ======================================
__device__ __forceinline__ uint32_t smem_u32(const void* p) {
    uint32_t a;
    asm("{ .reg .u64 t; cvta.to.shared.u64 t, %1; cvt.u32.u64 %0, t; }" : "=r"(a) : "l"(p));
    return a;
}

#define CP_ASYNC_16(dst_u32, src_ptr) \
    asm volatile("cp.async.cg.shared.global [%0], [%1], 16;" :: "r"(dst_u32), "l"(src_ptr))
#define CP_ASYNC_COMMIT() asm volatile("cp.async.commit_group;" ::: "memory")
#define CP_ASYNC_WAIT1()  asm volatile("cp.async.wait_group 1;" ::: "memory")

__device__ __forceinline__ void mma16816(float* d, const uint32_t* a,
                                         uint32_t b0, uint32_t b1) {
    asm volatile(
        "mma.sync.aligned.m16n8k16.row.col.f32.bf16.bf16.f32 "
        "{%0,%1,%2,%3}, {%4,%5,%6,%7}, {%8,%9}, {%0,%1,%2,%3};"
        : "+f"(d[0]), "+f"(d[1]), "+f"(d[2]), "+f"(d[3])
        : "r"(a[0]), "r"(a[1]), "r"(a[2]), "r"(a[3]), "r"(b0), "r"(b1));
}

__device__ __forceinline__ uint32_t lds32(uint32_t addr) {
    uint32_t v;
    asm volatile("ld.shared.b32 %0, [%1];" : "=r"(v) : "r"(addr));
    return v;
}

__device__ __forceinline__ uint32_t pack_bf2(float lo, float hi) {
    __nv_bfloat162 r = __floats2bfloat162_rn(lo, hi);   // x=lo (low 16b), y=hi
    return *(uint32_t*)&r;
}
__device__ __forceinline__ float2 unpack_bf2(uint32_t u) {
    __nv_bfloat162 h = *(__nv_bfloat162*)&u;
    return make_float2(__bfloat162float(h.x), __bfloat162float(h.y));
}

// ---------------------------------------------------------------------------
// Split-bf16 NT GEMM (R6-validated core).  epilogues:
//  0: split-bf16 out -> (outh,outl) [B,H,T,D] with *scale     (Q,K)
//  3: split-bf16 out -> (outh,outl) [B,H,D,T] transposed      (V)
//  1: fp32 out[m*CC+n]                                        (FC)
//  2: fp32 out[m*CC+n] * mask[m]                              (proj)
// ---------------------------------------------------------------------------
#define BKH 32
#define NST (KK/BKH)                 // 64
#define SRB 80                       // smem row stride bytes (40 halves)
#define TILE_TERM_B (128*SRB)        // 10240
#define STAGE_B (4*TILE_TERM_B)      // 40960
#define GEMM_SMEM (2*STAGE_B)        // 81920

__global__ __launch_bounds__(256) void gemm_mma_kernel(
    const __nv_bfloat16* __restrict__ Ah, const __nv_bfloat16* __restrict__ Al,
    const __nv_bfloat16* __restrict__ Bh, const __nv_bfloat16* __restrict__ Bl,
    const float* __restrict__ bias, const float* __restrict__ mask,
    float* __restrict__ out, __nv_bfloat16* __restrict__ outh,
    __nv_bfloat16* __restrict__ outl, float scale, int epi)
{
    extern __shared__ char sm_[];
    const uint32_t sb = smem_u32(sm_);
    const int tid    = threadIdx.x;
    const int wid    = tid >> 5;
    const int lane   = tid & 31;
    const int warp_m = wid & 3;
    const int warp_n = wid >> 2;
    const int g      = lane >> 2;
    const int t      = lane & 3;
    const int m0 = blockIdx.y * 128;
    const int n0 = blockIdx.x * 128;

    const __nv_bfloat16* srcs[4] = { Ah + (size_t)m0*KK, Al + (size_t)m0*KK,
                                     Bh + (size_t)n0*KK, Bl + (size_t)n0*KK };

    float acc[2][8][4];
#pragma unroll
    for (int mt = 0; mt < 2; mt++)
#pragma unroll
        for (int nt = 0; nt < 8; nt++)
#pragma unroll
            for (int r = 0; r < 4; r++) acc[mt][nt][r] = 0.f;

    const int cid0 = tid;
    auto LOAD_STAGE = [&](int s) {
        const int k0 = s * BKH;
        const uint32_t base = sb + (uint32_t)(s & 1) * STAGE_B;
#pragma unroll
        for (int tl = 0; tl < 4; tl++) {
            const __nv_bfloat16* src = srcs[tl];
#pragma unroll
            for (int i = 0; i < 2; i++) {
                const int cid = cid0 + i * 256;
                const int row = cid >> 2, c = cid & 3;
                const uint32_t dst = base + (uint32_t)tl * TILE_TERM_B
                                   + (uint32_t)row * SRB + (uint32_t)c * 16;
                CP_ASYNC_16(dst, src + (size_t)row * KK + k0 + c * 8);
            }
        }
        CP_ASYNC_COMMIT();
    };

    LOAD_STAGE(0);
    LOAD_STAGE(1);

    for (int s = 0; s < NST; s++) {
        CP_ASYNC_WAIT1();
        __syncthreads();

        const uint32_t base = sb + (uint32_t)(s & 1) * STAGE_B;
        const uint32_t pAh = base;
        const uint32_t pAl = base + TILE_TERM_B;
        const uint32_t pBh = base + 2*TILE_TERM_B;
        const uint32_t pBl = base + 3*TILE_TERM_B;

#pragma unroll
        for (int ks = 0; ks < 2; ks++) {
            const int kb = (ks * 16 + 2*t) * 2;
            uint32_t aH[2][4], aL[2][4];
#pragma unroll
            for (int mt = 0; mt < 2; mt++) {
                const int r = warp_m*32 + mt*16 + g;
                aH[mt][0] = lds32(pAh + r*SRB + kb);
                aH[mt][1] = lds32(pAh + (r+8)*SRB + kb);
                aH[mt][2] = lds32(pAh + r*SRB + kb + 16);
                aH[mt][3] = lds32(pAh + (r+8)*SRB + kb + 16);
                aL[mt][0] = lds32(pAl + r*SRB + kb);
                aL[mt][1] = lds32(pAl + (r+8)*SRB + kb);
                aL[mt][2] = lds32(pAl + r*SRB + kb + 16);
                aL[mt][3] = lds32(pAl + (r+8)*SRB + kb + 16);
            }
#pragma unroll
            for (int nt = 0; nt < 8; nt++) {
                const int n = warp_n*64 + nt*8 + g;
                uint32_t bh0 = lds32(pBh + n*SRB + kb);
                uint32_t bh1 = lds32(pBh + n*SRB + kb + 16);
                uint32_t bl0 = lds32(pBl + n*SRB + kb);
                uint32_t bl1 = lds32(pBl + n*SRB + kb + 16);
#pragma unroll
                for (int mt = 0; mt < 2; mt++) {
                    mma16816(acc[mt][nt], aH[mt], bh0, bh1);
                    mma16816(acc[mt][nt], aH[mt], bl0, bl1);
                    mma16816(acc[mt][nt], aL[mt], bh0, bh1);
                }
            }
        }
        __syncthreads();
        if (s + 2 < NST) LOAD_STAGE(s + 2);
        else             CP_ASYNC_COMMIT();
    }

    const int hh = n0 >> 7;             // head index (one head per n-tile)
#pragma unroll
    for (int mt = 0; mt < 2; mt++) {
#pragma unroll
        for (int nt = 0; nt < 8; nt++) {
            const float* d = acc[mt][nt];
            const int r0 = m0 + warp_m*32 + mt*16 + g;
            const int r1 = r0 + 8;
            const int n  = n0 + warp_n*64 + nt*8 + 2*t;
            const float2 b2 = *(const float2*)(bias + n);
            float v00 = d[0] + b2.x, v01 = d[1] + b2.y;
            float v10 = d[2] + b2.x, v11 = d[3] + b2.y;
            if (epi == 0 || epi == 3) {
                v00 *= scale; v01 *= scale; v10 *= scale; v11 *= scale;
                const int dd  = n & (DD - 1);
                const int b0i = r0 >> 11, t0i = r0 & (TT-1);
                const int b1i = r1 >> 11, t1i = r1 & (TT-1);
                __nv_bfloat16 h00 = __float2bfloat16(v00);
                __nv_bfloat16 h01 = __float2bfloat16(v01);
                __nv_bfloat16 h10 = __float2bfloat16(v10);
                __nv_bfloat16 h11 = __float2bfloat16(v11);
                __nv_bfloat16 l00 = __float2bfloat16(v00 - __bfloat162float(h00));
                __nv_bfloat16 l01 = __float2bfloat16(v01 - __bfloat162float(h01));
                __nv_bfloat16 l10 = __float2bfloat16(v10 - __bfloat162float(h10));
                __nv_bfloat16 l11 = __float2bfloat16(v11 - __bfloat162float(h11));
                if (epi == 0) {   // [B,H,T,D]
                    const size_t i0 = (((size_t)(b0i*HH + hh))*TT + t0i)*DD + dd;
                    const size_t i1 = (((size_t)(b1i*HH + hh))*TT + t1i)*DD + dd;
                    __nv_bfloat162 H0; H0.x = h00; H0.y = h01;
                    __nv_bfloat162 H1; H1.x = h10; H1.y = h11;
                    __nv_bfloat162 L0; L0.x = l00; L0.y = l01;
                    __nv_bfloat162 L1; L1.x = l10; L1.y = l11;
                    *(__nv_bfloat162*)(outh + i0) = H0;
                    *(__nv_bfloat162*)(outh + i1) = H1;
                    *(__nv_bfloat162*)(outl + i0) = L0;
                    *(__nv_bfloat162*)(outl + i1) = L1;
                } else {          // [B,H,D,T] transposed
                    const size_t c0 = (((size_t)(b0i*HH + hh))*DD + dd)*TT + t0i;
                    const size_t c1 = (((size_t)(b1i*HH + hh))*DD + dd)*TT + t1i;
                    outh[c0] = h00; outh[c0 + TT] = h01;
                    outh[c1] = h10; outh[c1 + TT] = h11;
                    outl[c0] = l00; outl[c0 + TT] = l01;
                    outl[c1] = l10; outl[c1 + TT] = l11;
                }
            } else if (epi == 1) {
                *(float2*)(out + (size_t)r0*CC + n) = make_float2(v00, v01);
                *(float2*)(out + (size_t)r1*CC + n) = make_float2(v10, v11);
            } else {
                const float mk0 = mask[r0], mk1 = mask[r1];
                *(float2*)(out + (size_t)r0*CC + n) = make_float2(v00*mk0, v01*mk0);
                *(float2*)(out + (size_t)r1*CC + n) = make_float2(v10*mk1, v11*mk1);
            }
        }
    }
}

// ---------------------------------------------------------------------------
// split fp32 -> bf16 hi + bf16 lo (residual)
// ---------------------------------------------------------------------------
__global__ __launch_bounds__(256) void split_kernel(
    const float* __restrict__ in, __nv_bfloat16* __restrict__ hi,
    __nv_bfloat16* __restrict__ lo)
{
    const int i = blockIdx.x * 256 + threadIdx.x;
    float4 v = ((const float4*)in)[i];
    float f[4] = {v.x, v.y, v.z, v.w};
    union U { __nv_bfloat16 b[4]; uint2 u; } H, L;
#pragma unroll
    for (int j = 0; j < 4; j++) {
        H.b[j] = __float2bfloat16(f[j]);
        L.b[j] = __float2bfloat16(f[j] - __bfloat162float(H.b[j]));
    }
    ((uint2*)hi)[i] = H.u;
    ((uint2*)lo)[i] = L.u;
}

// ---------------------------------------------------------------------------
// Causal flash attention on mma.sync, split-bf16 (S and PV both 3-term).
// Br=128, Bc=64. 8 warps; warp w owns rows 16w..16w+15.
// Q,K layout [B,H,T,D] bf16 hi/lo; V layout [B,H,D,T] bf16 hi/lo (transposed).
// K/V double-buffered via cp.async. P fragments built in registers from S.
// ---------------------------------------------------------------------------
#define FQS 272                      // Q/K smem row stride bytes (128 bf16 + pad)
#define FVS 144                      // V^T smem row stride bytes (64 bf16 + pad)
#define FQ_TILE (128*FQS)            // 34816
#define FK_TILE (64*FQS)             // 17408
#define FV_TILE (128*FVS)            // 18432
#define FKV_STAGE (2*FK_TILE + 2*FV_TILE)   // 71680
#define FLASH_SMEM (2*FQ_TILE + 2*FKV_STAGE) // 212992

__global__ __launch_bounds__(256) void flash_mma_kernel(
    const __nv_bfloat16* __restrict__ qh, const __nv_bfloat16* __restrict__ ql,
    const __nv_bfloat16* __restrict__ kh, const __nv_bfloat16* __restrict__ kl,
    const __nv_bfloat16* __restrict__ vh, const __nv_bfloat16* __restrict__ vl,
    float* __restrict__ Y)
{
    extern __shared__ char sm_[];
    const uint32_t sb = smem_u32(sm_);
    const int tid  = threadIdx.x;
    const int wid  = tid >> 5;
    const int lane = tid & 31;
    const int g    = lane >> 2;
    const int t    = lane & 3;
    const int qt   = blockIdx.x;
    const int bh   = blockIdx.y;
    const int b    = bh >> 4;
    const int h    = bh & 15;

    const __nv_bfloat16* Qh = qh + (size_t)bh*TT*DD + (size_t)qt*128*DD;
    const __nv_bfloat16* Ql = ql + (size_t)bh*TT*DD + (size_t)qt*128*DD;
    const __nv_bfloat16* Kh = kh + (size_t)bh*TT*DD;
    const __nv_bfloat16* Kl = kl + (size_t)bh*TT*DD;
    const __nv_bfloat16* Vh = vh + (size_t)bh*DD*TT;   // [d][t]
    const __nv_bfloat16* Vl = vl + (size_t)bh*DD*TT;

    // Q tiles: 2 x 128 rows x 16 chunks(16B) = 4096 chunks / 256 thr
#pragma unroll
    for (int i = 0; i < 16; i++) {
        const int cid = i*256 + tid;
        const int tile = cid >> 11, rem = cid & 2047;
        const int row = rem >> 4, ch = rem & 15;
        const uint32_t dst = sb + (uint32_t)tile*FQ_TILE + (uint32_t)row*FQS + (uint32_t)ch*16;
        const __nv_bfloat16* src = (tile ? Ql : Qh) + (size_t)row*DD + ch*8;
        CP_ASYNC_16(dst, src);
    }
    auto LOAD_STAGE = [&](int s) {
        const uint32_t base = sb + 2*FQ_TILE + (uint32_t)(s & 1)*FKV_STAGE;
#pragma unroll
        for (int i = 0; i < 8; i++) {      // K: 2 tiles x 64 rows x 16 chunks
            const int cid = i*256 + tid;
            const int tile = cid >> 10, rem = cid & 1023;
            const int row = rem >> 4, ch = rem & 15;
            const uint32_t dst = base + (uint32_t)tile*FK_TILE + (uint32_t)row*FQS + (uint32_t)ch*16;
            const __nv_bfloat16* src = (tile ? Kl : Kh) + (size_t)(s*64 + row)*DD + ch*8;
            CP_ASYNC_16(dst, src);
        }
#pragma unroll
        for (int i = 0; i < 8; i++) {      // V: 2 tiles x 128 rows x 8 chunks
            const int cid = i*256 + tid;
            const int tile = cid >> 10, rem = cid & 1023;
            const int row = rem >> 3, ch = rem & 7;
            const uint32_t dst = base + 2*FK_TILE + (uint32_t)tile*FV_TILE
                               + (uint32_t)row*FVS + (uint32_t)ch*16;
            const __nv_bfloat16* src = (tile ? Vl : Vh) + (size_t)row*TT + s*64 + ch*8;
            CP_ASYNC_16(dst, src);
        }
        CP_ASYNC_COMMIT();
    };

    LOAD_STAGE(0);   // Q cps join stage-0's group
    LOAD_STAGE(1);

    const int NT = 2*qt + 2;
    float mI[2] = {-1e30f, -1e30f};
    float lI[2] = {0.f, 0.f};
    float o[16][4];
#pragma unroll
    for (int nt = 0; nt < 16; nt++)
#pragma unroll
        for (int e = 0; e < 4; e++) o[nt][e] = 0.f;

    const int row0g = qt*128 + wid*16 + g;   // global row of thread's first row
    const int row1g = row0g + 8;

    for (int kt = 0; kt < NT; kt++) {
        CP_ASYNC_WAIT1();
        __syncthreads();
        const uint32_t base = sb + 2*FQ_TILE + (uint32_t)(kt & 1)*FKV_STAGE;
        const uint32_t pKh = base;
        const uint32_t pKl = base + FK_TILE;
        const uint32_t pVh = base + 2*FK_TILE;
        const uint32_t pVl = base + 2*FK_TILE + FV_TILE;

        const bool active = (kt*64 <= qt*128 + wid*16 + 15);
        if (active) {
            // ---- S = Q K^T (split, 3 terms), fp32 frags
            float s[8][4];
#pragma unroll
            for (int nt = 0; nt < 8; nt++)
#pragma unroll
                for (int e = 0; e < 4; e++) s[nt][e] = 0.f;

#pragma unroll
            for (int k8 = 0; k8 < 8; k8++) {
                const int kb = k8*32 + 4*t;
                const int rA = wid*16 + g;
                uint32_t aH[4], aL[4];
                aH[0] = lds32(sb + rA*FQS + kb);
                aH[1] = lds32(sb + (rA+8)*FQS + kb);
                aH[2] = lds32(sb + rA*FQS + kb + 16);
                aH[3] = lds32(sb + (rA+8)*FQS + kb + 16);
                aL[0] = lds32(sb + FQ_TILE + rA*FQS + kb);
                aL[1] = lds32(sb + FQ_TILE + (rA+8)*FQS + kb);
                aL[2] = lds32(sb + FQ_TILE + rA*FQS + kb + 16);
                aL[3] = lds32(sb + FQ_TILE + (rA+8)*FQS + kb + 16);
#pragma unroll
                for (int nt = 0; nt < 8; nt++) {
                    const int rB = nt*8 + g;
                    uint32_t kh0 = lds32(pKh + rB*FQS + kb);
                    uint32_t kh1 = lds32(pKh + rB*FQS + kb + 16);
                    uint32_t kl0 = lds32(pKl + rB*FQS + kb);
                    uint32_t kl1 = lds32(pKl + rB*FQS + kb + 16);
                    mma16816(s[nt], aH, kh0, kh1);
                    mma16816(s[nt], aH, kl0, kl1);
                    mma16816(s[nt], aL, kh0, kh1);
                }
            }

            // ---- causal mask (only near diagonal)
            if (kt >= 2*qt) {
#pragma unroll
                for (int nt = 0; nt < 8; nt++) {
                    const int c0 = kt*64 + nt*8 + 2*t;
                    const int c1 = c0 + 1;
                    if (c0 > row0g) s[nt][0] = -1e30f;
                    if (c1 > row0g) s[nt][1] = -1e30f;
                    if (c0 > row1g) s[nt][2] = -1e30f;
                    if (c1 > row1g) s[nt][3] = -1e30f;
                }
            }

            // ---- online softmax (rows g and g+8)
            float mt0 = -1e30f, mt1 = -1e30f;
#pragma unroll
            for (int nt = 0; nt < 8; nt++) {
                mt0 = fmaxf(mt0, fmaxf(s[nt][0], s[nt][1]));
                mt1 = fmaxf(mt1, fmaxf(s[nt][2], s[nt][3]));
            }
            mt0 = fmaxf(mt0, __shfl_xor_sync(0xffffffffu, mt0, 1));
            mt0 = fmaxf(mt0, __shfl_xor_sync(0xffffffffu, mt0, 2));
            mt1 = fmaxf(mt1, __shfl_xor_sync(0xffffffffu, mt1, 1));
            mt1 = fmaxf(mt1, __shfl_xor_sync(0xffffffffu, mt1, 2));
            const float mn0 = fmaxf(mI[0], mt0);
            const float mn1 = fmaxf(mI[1], mt1);
            const float corr0 = __expf(mI[0] - mn0);
            const float corr1 = __expf(mI[1] - mn1);
            mI[0] = mn0; mI[1] = mn1;

            float rs0 = 0.f, rs1 = 0.f;
#pragma unroll
            for (int nt = 0; nt < 8; nt++) {
                s[nt][0] = __expf(s[nt][0] - mn0); rs0 += s[nt][0];
                s[nt][1] = __expf(s[nt][1] - mn0); rs0 += s[nt][1];
                s[nt][2] = __expf(s[nt][2] - mn1); rs1 += s[nt][2];
                s[nt][3] = __expf(s[nt][3] - mn1); rs1 += s[nt][3];
            }
            rs0 += __shfl_xor_sync(0xffffffffu, rs0, 1);
            rs0 += __shfl_xor_sync(0xffffffffu, rs0, 2);
            rs1 += __shfl_xor_sync(0xffffffffu, rs1, 1);
            rs1 += __shfl_xor_sync(0xffffffffu, rs1, 2);
            lI[0] = lI[0]*corr0 + rs0;
            lI[1] = lI[1]*corr1 + rs1;

#pragma unroll
            for (int nt = 0; nt < 16; nt++) {
                o[nt][0] *= corr0; o[nt][1] *= corr0;
                o[nt][2] *= corr1; o[nt][3] *= corr1;
            }

            // ---- pack P frags (A-layout) from S frags: hi + lo
            uint32_t ph[4][4], pl[4][4];
#pragma unroll
            for (int k4 = 0; k4 < 4; k4++) {
                const int e0 = 2*k4, e1 = 2*k4 + 1;
                ph[k4][0] = pack_bf2(s[e0][0], s[e0][1]);
                ph[k4][1] = pack_bf2(s[e0][2], s[e0][3]);
                ph[k4][2] = pack_bf2(s[e1][0], s[e1][1]);
                ph[k4][3] = pack_bf2(s[e1][2], s[e1][3]);
                float2 u0 = unpack_bf2(ph[k4][0]);
                float2 u1 = unpack_bf2(ph[k4][1]);
                float2 u2 = unpack_bf2(ph[k4][2]);
                float2 u3 = unpack_bf2(ph[k4][3]);
                pl[k4][0] = pack_bf2(s[e0][0]-u0.x, s[e0][1]-u0.y);
                pl[k4][1] = pack_bf2(s[e0][2]-u1.x, s[e0][3]-u1.y);
                pl[k4][2] = pack_bf2(s[e1][0]-u2.x, s[e1][1]-u2.y);
                pl[k4][3] = pack_bf2(s[e1][2]-u3.x, s[e1][3]-u3.y);
            }

            // ---- O += P V (split, 3 terms).  B operand: V^T smem [d][s]
#pragma unroll
            for (int k4 = 0; k4 < 4; k4++) {
                const int kb2 = k4*32 + 4*t;
#pragma unroll
                for (int nt = 0; nt < 16; nt++) {
                    const int rB = nt*8 + g;
                    uint32_t vh0 = lds32(pVh + rB*FVS + kb2);
                    uint32_t vh1 = lds32(pVh + rB*FVS + kb2 + 16);
                    uint32_t vl0 = lds32(pVl + rB*FVS + kb2);
                    uint32_t vl1 = lds32(pVl + rB*FVS + kb2 + 16);
                    mma16816(o[nt], ph[k4], vh0, vh1);
                    mma16816(o[nt], ph[k4], vl0, vl1);
                    mma16816(o[nt], pl[k4], vh0, vh1);
                }
            }
        }
        __syncthreads();
        if (kt + 2 < NT) LOAD_STAGE(kt + 2);
        else             CP_ASYNC_COMMIT();
    }

    // ---- epilogue: Y[B,T,C]
    const float inv0 = 1.0f / lI[0];
    const float inv1 = 1.0f / lI[1];
    float* y0 = Y + ((size_t)(b*TT + row0g))*CC + h*DD;
    float* y1 = Y + ((size_t)(b*TT + row1g))*CC + h*DD;
#pragma unroll
    for (int nt = 0; nt < 16; nt++) {
        const int col = nt*8 + 2*t;
        *(float2*)(y0 + col) = make_float2(o[nt][0]*inv0, o[nt][1]*inv0);
        *(float2*)(y1 + col) = make_float2(o[nt][2]*inv1, o[nt][3]*inv1);
    }
}

// ---------------------------------------------------------------------------
// Fused LayerNorm(z)*g+b + residual (unchanged — passing since R2).
// ---------------------------------------------------------------------------
__global__ __launch_bounds__(256) void ln_add_kernel(
    const float* __restrict__ z, const float* __restrict__ res,
    const float* __restrict__ gam, const float* __restrict__ bet,
    float* __restrict__ out)
{
    __shared__ float red[256];
    const int row = blockIdx.x;
    const int tid = threadIdx.x;
    const float* zr = z + (size_t)row * CC;

    float v[8];
#pragma unroll
    for (int i = 0; i < 2; i++) {
        float4 t4 = *(const float4*)(zr + i*1024 + tid*4);
        v[i*4+0] = t4.x; v[i*4+1] = t4.y; v[i*4+2] = t4.z; v[i*4+3] = t4.w;
    }

    float s = 0.f;
#pragma unroll
    for (int i = 0; i < 8; i++) s += v[i];
    red[tid] = s; __syncthreads();
#pragma unroll
    for (int off = 128; off; off >>= 1) {
        if (tid < off) red[tid] += red[tid + off];
        __syncthreads();
    }
    const float mean = red[0] * (1.0f / 2048.0f);
    __syncthreads();

    float vs = 0.f;
#pragma unroll
    for (int i = 0; i < 8; i++) { const float d = v[i] - mean; vs += d * d; }
    red[tid] = vs; __syncthreads();
#pragma unroll
    for (int off = 128; off; off >>= 1) {
        if (tid < off) red[tid] += red[tid + off];
        __syncthreads();
    }
    const float rstd = rsqrtf(red[0] * (1.0f / 2048.0f) + 1e-6f);

    const float* rr = res + (size_t)row * CC;
    float* orow = out + (size_t)row * CC;
#pragma unroll
    for (int i = 0; i < 2; i++) {
        const int c0 = i*1024 + tid*4;
        float4 g4 = *(const float4*)(gam + c0);
        float4 b4 = *(const float4*)(bet + c0);
        float4 r4 = *(const float4*)(rr + c0);
        float4 ov;
        ov.x = (v[i*4+0] - mean)*rstd*g4.x + b4.x + r4.x;
        ov.y = (v[i*4+1] - mean)*rstd*g4.y + b4.y + r4.y;
        ov.z = (v[i*4+2] - mean)*rstd*g4.z + b4.z + r4.z;
        ov.w = (v[i*4+3] - mean)*rstd*g4.w + b4.w + r4.w;
        *(float4*)(orow + c0) = ov;
    }
}

// ---------------------------------------------------------------------------
extern "C" void kernel_launch(void* const* d_in, const int* in_sizes, int n_in,
                              void* d_out, int out_size)
{
    const float* x    = (const float*)d_in[0];
    const float* mask = (const float*)d_in[1];
    const float* W[5] = { (const float*)d_in[2],  (const float*)d_in[4],
                          (const float*)d_in[6],  (const float*)d_in[8],
                          (const float*)d_in[10] };                 // Wq,Wk,Wv,Wp,Wfc
    const float* bq   = (const float*)d_in[3];
    const float* bk   = (const float*)d_in[5];
    const float* bv   = (const float*)d_in[7];
    const float* bp   = (const float*)d_in[9];
    const float* bfc  = (const float*)d_in[11];
    const float* ln_g = (const float*)d_in[12];
    const float* ln_b = (const float*)d_in[13];

    float *y, *t0, *t1;
    __nv_bfloat16 *qh, *ql, *kh, *kl, *vh, *vl, *xh, *xl, *ah, *al, *wh, *wl;
    cudaGetSymbolAddress((void**)&qh, g_qh);
    cudaGetSymbolAddress((void**)&ql, g_ql);
    cudaGetSymbolAddress((void**)&kh, g_kh);
    cudaGetSymbolAddress((void**)&kl, g_kl);
    cudaGetSymbolAddress((void**)&vh, g_vh);
    cudaGetSymbolAddress((void**)&vl, g_vl);
    cudaGetSymbolAddress((void**)&y,  g_y);
    cudaGetSymbolAddress((void**)&t0, g_t0);
    cudaGetSymbolAddress((void**)&t1, g_t1);
    cudaGetSymbolAddress((void**)&xh, g_xh);
    cudaGetSymbolAddress((void**)&xl, g_xl);
    cudaGetSymbolAddress((void**)&ah, g_ah);
    cudaGetSymbolAddress((void**)&al, g_al);
    cudaGetSymbolAddress((void**)&wh, g_wh);
    cudaGetSymbolAddress((void**)&wl, g_wl);

    cudaFuncSetAttribute(gemm_mma_kernel,
                         cudaFuncAttributeMaxDynamicSharedMemorySize, GEMM_SMEM);
    cudaFuncSetAttribute(flash_mma_kernel,
                         cudaFuncAttributeMaxDynamicSharedMemorySize, FLASH_SMEM);

    const dim3 gg(CC/128, MM/128);         // (16, 32)
    const int ACT4 = MM*CC/4;
    const int WT4  = CC*CC/4;

    // split input/weights to bf16 hi/lo
    split_kernel<<<ACT4/256, 256>>>(x, xh, xl);
    for (int i = 0; i < 5; i++)
        split_kernel<<<WT4/256, 256>>>(W[i], wh + (size_t)i*CC*CC, wl + (size_t)i*CC*CC);

    // QKV projections -> split bf16; Q scaled; V transposed [B,H,D,T]
    gemm_mma_kernel<<<gg, 256, GEMM_SMEM>>>(xh, xl, wh + 0*(size_t)CC*CC, wl + 0*(size_t)CC*CC,
                                            bq, nullptr, nullptr, qh, ql, QSCALE, 0);
    gemm_mma_kernel<<<gg, 256, GEMM_SMEM>>>(xh, xl, wh + 1*(size_t)CC*CC, wl + 1*(size_t)CC*CC,
                                            bk, nullptr, nullptr, kh, kl, 1.0f, 0);
    gemm_mma_kernel<<<gg, 256, GEMM_SMEM>>>(xh, xl, wh + 2*(size_t)CC*CC, wl + 2*(size_t)CC*CC,
                                            bv, nullptr, nullptr, vh, vl, 1.0f, 3);

    // causal flash attention (tensorized) -> y [B,T,C]
    flash_mma_kernel<<<dim3(TT/128, BB*HH), 256, FLASH_SMEM>>>(qh, ql, kh, kl, vh, vl, y);

    // output projection (+bias, *mask) -> t0
    split_kernel<<<ACT4/256, 256>>>(y, ah, al);
    gemm_mma_kernel<<<gg, 256, GEMM_SMEM>>>(ah, al, wh + 3*(size_t)CC*CC, wl + 3*(size_t)CC*CC,
                                            bp, mask, t0, nullptr, nullptr, 1.0f, 2);

    // x1 = LN(t0) + x -> t1
    ln_add_kernel<<<MM, 256>>>(t0, x, ln_g, ln_b, t1);

    // fc = x1 @ Wfc^T + bfc -> t0
    split_kernel<<<ACT4/256, 256>>>(t1, ah, al);
    gemm_mma_kernel<<<gg, 256, GEMM_SMEM>>>(ah, al, wh + 4*(size_t)CC*CC, wl + 4*(size_t)CC*CC,
                                            bfc, nullptr, t0, nullptr, nullptr, 1.0f, 1);

    // out = LN(t0) + x1
    ln_add_kernel<<<MM, 256>>>(t0, t1, ln_g, ln_b, (float*)d_out);
}

// round 11
// speedup vs baseline: 2.3387x; 1.0030x over previous
#include <cuda_runtime.h>
#include <cuda_bf16.h>
#include <math.h>
#include <cstdint>

// Problem constants (fixed shapes)
#define BB 2
#define TT 2048
#define CC 2048
#define HH 16
#define DD 128
#define MM (BB*TT)          // 4096 rows
#define KK 2048
#define QSCALE 0.08838834764831845f  // 1/sqrt(128)

// ---------------- scratch (device globals; no allocation allowed) ----------
__device__ __nv_bfloat16 g_qh[BB*HH*TT*DD], g_ql[BB*HH*TT*DD];  // [B,H,T,D]
__device__ __nv_bfloat16 g_kh[BB*HH*TT*DD], g_kl[BB*HH*TT*DD];  // [B,H,T,D]
__device__ __nv_bfloat16 g_vh[BB*HH*TT*DD], g_vl[BB*HH*TT*DD];  // [B,H,D,T] (transposed)
__device__ float g_t0[MM*CC];        // proj out / fc out
__device__ float g_t1[MM*CC];        // x1

// split-bf16 operands for GEMMs
__device__ __nv_bfloat16 g_xh[MM*CC],  g_xl[MM*CC];    // x split
__device__ __nv_bfloat16 g_ah[MM*CC],  g_al[MM*CC];    // flash out split, then t1 split
__device__ __nv_bfloat16 g_wh[5*CC*CC], g_wl[5*CC*CC]; // Wq,Wk,Wv,Wp,Wfc splits

// ============================ helpers ======================================
__device__ __forceinline__ uint32_t smem_u32(const void* p) {
    uint32_t a;
    asm("{ .reg .u64 t; cvta.to.shared.u64 t, %1; cvt.u32.u64 %0, t; }" : "=r"(a) : "l"(p));
    return a;
}

#define CP_ASYNC_16(dst_u32, src_ptr) \
    asm volatile("cp.async.cg.shared.global [%0], [%1], 16;" :: "r"(dst_u32), "l"(src_ptr))
#define CP_ASYNC_COMMIT() asm volatile("cp.async.commit_group;" ::: "memory")
#define CP_ASYNC_WAIT1()  asm volatile("cp.async.wait_group 1;" ::: "memory")

__device__ __forceinline__ void mma16816(float* d, const uint32_t* a,
                                         uint32_t b0, uint32_t b1) {
    asm volatile(
        "mma.sync.aligned.m16n8k16.row.col.f32.bf16.bf16.f32 "
        "{%0,%1,%2,%3}, {%4,%5,%6,%7}, {%8,%9}, {%0,%1,%2,%3};"
        : "+f"(d[0]), "+f"(d[1]), "+f"(d[2]), "+f"(d[3])
        : "r"(a[0]), "r"(a[1]), "r"(a[2]), "r"(a[3]), "r"(b0), "r"(b1));
}

__device__ __forceinline__ uint32_t lds32(uint32_t addr) {
    uint32_t v;
    asm volatile("ld.shared.b32 %0, [%1];" : "=r"(v) : "r"(addr));
    return v;
}

__device__ __forceinline__ uint32_t pack_bf2(float lo, float hi) {
    __nv_bfloat162 r = __floats2bfloat162_rn(lo, hi);   // x=lo (low 16b), y=hi
    return *(uint32_t*)&r;
}
__device__ __forceinline__ float2 unpack_bf2(uint32_t u) {
    __nv_bfloat162 h = *(__nv_bfloat162*)&u;
    return make_float2(__bfloat162float(h.x), __bfloat162float(h.y));
}

// ---------------------------------------------------------------------------
// Split-bf16 NT GEMM (R8-validated core: 8 warps, 32x64 warp tiles).
// epilogues:
//  0: split-bf16 out -> (outh,outl) [B,H,T,D] with *scale     (Q,K)
//  3: split-bf16 out -> (outh,outl) [B,H,D,T] transposed      (V)
//  1: fp32 out[m*CC+n]                                        (FC)
//  2: fp32 out[m*CC+n] * mask[m]                              (proj)
// ---------------------------------------------------------------------------
#define BKH 32
#define NST (KK/BKH)                 // 64
#define SRB 80                       // smem row stride bytes (40 halves)
#define TILE_TERM_B (128*SRB)        // 10240
#define STAGE_B (4*TILE_TERM_B)      // 40960
#define GEMM_SMEM (2*STAGE_B)        // 81920

__global__ __launch_bounds__(256) void gemm_mma_kernel(
    const __nv_bfloat16* __restrict__ Ah, const __nv_bfloat16* __restrict__ Al,
    const __nv_bfloat16* __restrict__ Bh, const __nv_bfloat16* __restrict__ Bl,
    const float* __restrict__ bias, const float* __restrict__ mask,
    float* __restrict__ out, __nv_bfloat16* __restrict__ outh,
    __nv_bfloat16* __restrict__ outl, float scale, int epi)
{
    extern __shared__ char sm_[];
    const uint32_t sb = smem_u32(sm_);
    const int tid    = threadIdx.x;
    const int wid    = tid >> 5;
    const int lane   = tid & 31;
    const int warp_m = wid & 3;
    const int warp_n = wid >> 2;
    const int g      = lane >> 2;
    const int t      = lane & 3;
    const int m0 = blockIdx.y * 128;
    const int n0 = blockIdx.x * 128;

    const __nv_bfloat16* srcs[4] = { Ah + (size_t)m0*KK, Al + (size_t)m0*KK,
                                     Bh + (size_t)n0*KK, Bl + (size_t)n0*KK };

    float acc[2][8][4];
#pragma unroll
    for (int mt = 0; mt < 2; mt++)
#pragma unroll
        for (int nt = 0; nt < 8; nt++)
#pragma unroll
            for (int r = 0; r < 4; r++) acc[mt][nt][r] = 0.f;

    const int cid0 = tid;
    auto LOAD_STAGE = [&](int s) {
        const int k0 = s * BKH;
        const uint32_t base = sb + (uint32_t)(s & 1) * STAGE_B;
#pragma unroll
        for (int tl = 0; tl < 4; tl++) {
            const __nv_bfloat16* src = srcs[tl];
#pragma unroll
            for (int i = 0; i < 2; i++) {
                const int cid = cid0 + i * 256;
                const int row = cid >> 2, c = cid & 3;
                const uint32_t dst = base + (uint32_t)tl * TILE_TERM_B
                                   + (uint32_t)row * SRB + (uint32_t)c * 16;
                CP_ASYNC_16(dst, src + (size_t)row * KK + k0 + c * 8);
            }
        }
        CP_ASYNC_COMMIT();
    };

    LOAD_STAGE(0);
    LOAD_STAGE(1);

    for (int s = 0; s < NST; s++) {
        CP_ASYNC_WAIT1();
        __syncthreads();

        const uint32_t base = sb + (uint32_t)(s & 1) * STAGE_B;
        const uint32_t pAh = base;
        const uint32_t pAl = base + TILE_TERM_B;
        const uint32_t pBh = base + 2*TILE_TERM_B;
        const uint32_t pBl = base + 3*TILE_TERM_B;

#pragma unroll
        for (int ks = 0; ks < 2; ks++) {
            const int kb = (ks * 16 + 2*t) * 2;
            uint32_t aH[2][4], aL[2][4];
#pragma unroll
            for (int mt = 0; mt < 2; mt++) {
                const int r = warp_m*32 + mt*16 + g;
                aH[mt][0] = lds32(pAh + r*SRB + kb);
                aH[mt][1] = lds32(pAh + (r+8)*SRB + kb);
                aH[mt][2] = lds32(pAh + r*SRB + kb + 16);
                aH[mt][3] = lds32(pAh + (r+8)*SRB + kb + 16);
                aL[mt][0] = lds32(pAl + r*SRB + kb);
                aL[mt][1] = lds32(pAl + (r+8)*SRB + kb);
                aL[mt][2] = lds32(pAl + r*SRB + kb + 16);
                aL[mt][3] = lds32(pAl + (r+8)*SRB + kb + 16);
            }
#pragma unroll
            for (int nt = 0; nt < 8; nt++) {
                const int n = warp_n*64 + nt*8 + g;
                uint32_t bh0 = lds32(pBh + n*SRB + kb);
                uint32_t bh1 = lds32(pBh + n*SRB + kb + 16);
                uint32_t bl0 = lds32(pBl + n*SRB + kb);
                uint32_t bl1 = lds32(pBl + n*SRB + kb + 16);
#pragma unroll
                for (int mt = 0; mt < 2; mt++) {
                    mma16816(acc[mt][nt], aH[mt], bh0, bh1);
                    mma16816(acc[mt][nt], aH[mt], bl0, bl1);
                    mma16816(acc[mt][nt], aL[mt], bh0, bh1);
                }
            }
        }
        __syncthreads();
        if (s + 2 < NST) LOAD_STAGE(s + 2);
        else             CP_ASYNC_COMMIT();
    }

#pragma unroll
    for (int mt = 0; mt < 2; mt++) {
#pragma unroll
        for (int nt = 0; nt < 8; nt++) {
            const float* d = acc[mt][nt];
            const int r0 = m0 + warp_m*32 + mt*16 + g;
            const int r1 = r0 + 8;
            const int n  = n0 + warp_n*64 + nt*8 + 2*t;
            const float2 b2 = *(const float2*)(bias + n);
            float v00 = d[0] + b2.x, v01 = d[1] + b2.y;
            float v10 = d[2] + b2.x, v11 = d[3] + b2.y;
            if (epi == 0 || epi == 3) {
                v00 *= scale; v01 *= scale; v10 *= scale; v11 *= scale;
                const int hh  = n >> 7;
                const int dd  = n & (DD - 1);
                const int b0i = r0 >> 11, t0i = r0 & (TT-1);
                const int b1i = r1 >> 11, t1i = r1 & (TT-1);
                __nv_bfloat16 h00 = __float2bfloat16(v00);
                __nv_bfloat16 h01 = __float2bfloat16(v01);
                __nv_bfloat16 h10 = __float2bfloat16(v10);
                __nv_bfloat16 h11 = __float2bfloat16(v11);
                __nv_bfloat16 l00 = __float2bfloat16(v00 - __bfloat162float(h00));
                __nv_bfloat16 l01 = __float2bfloat16(v01 - __bfloat162float(h01));
                __nv_bfloat16 l10 = __float2bfloat16(v10 - __bfloat162float(h10));
                __nv_bfloat16 l11 = __float2bfloat16(v11 - __bfloat162float(h11));
                if (epi == 0) {   // [B,H,T,D]
                    const size_t i0 = (((size_t)(b0i*HH + hh))*TT + t0i)*DD + dd;
                    const size_t i1 = (((size_t)(b1i*HH + hh))*TT + t1i)*DD + dd;
                    __nv_bfloat162 H0; H0.x = h00; H0.y = h01;
                    __nv_bfloat162 H1; H1.x = h10; H1.y = h11;
                    __nv_bfloat162 L0; L0.x = l00; L0.y = l01;
                    __nv_bfloat162 L1; L1.x = l10; L1.y = l11;
                    *(__nv_bfloat162*)(outh + i0) = H0;
                    *(__nv_bfloat162*)(outh + i1) = H1;
                    *(__nv_bfloat162*)(outl + i0) = L0;
                    *(__nv_bfloat162*)(outl + i1) = L1;
                } else {          // [B,H,D,T] transposed
                    const size_t c0 = (((size_t)(b0i*HH + hh))*DD + dd)*TT + t0i;
                    const size_t c1 = (((size_t)(b1i*HH + hh))*DD + dd)*TT + t1i;
                    outh[c0] = h00; outh[c0 + TT] = h01;
                    outh[c1] = h10; outh[c1 + TT] = h11;
                    outl[c0] = l00; outl[c0 + TT] = l01;
                    outl[c1] = l10; outl[c1 + TT] = l11;
                }
            } else if (epi == 1) {
                *(float2*)(out + (size_t)r0*CC + n) = make_float2(v00, v01);
                *(float2*)(out + (size_t)r1*CC + n) = make_float2(v10, v11);
            } else {
                const float mk0 = mask[r0], mk1 = mask[r1];
                *(float2*)(out + (size_t)r0*CC + n) = make_float2(v00*mk0, v01*mk0);
                *(float2*)(out + (size_t)r1*CC + n) = make_float2(v10*mk1, v11*mk1);
            }
        }
    }
}

// ---------------------------------------------------------------------------
// split fp32 -> bf16 hi + bf16 lo (residual)
// ---------------------------------------------------------------------------
__global__ __launch_bounds__(256) void split_kernel(
    const float* __restrict__ in, __nv_bfloat16* __restrict__ hi,
    __nv_bfloat16* __restrict__ lo)
{
    const int i = blockIdx.x * 256 + threadIdx.x;
    float4 v = ((const float4*)in)[i];
    float f[4] = {v.x, v.y, v.z, v.w};
    union U { __nv_bfloat16 b[4]; uint2 u; } H, L;
#pragma unroll
    for (int j = 0; j < 4; j++) {
        H.b[j] = __float2bfloat16(f[j]);
        L.b[j] = __float2bfloat16(f[j] - __bfloat162float(H.b[j]));
    }
    ((uint2*)hi)[i] = H.u;
    ((uint2*)lo)[i] = L.u;
}

// ---------------------------------------------------------------------------
// Causal flash attention on mma.sync, split-bf16 (S and PV both 3-term).
// Br=128, Bc=64. 8 warps; warp w owns rows 16w..16w+15.
// Output written directly as split bf16 (ah/al) for the proj GEMM.
// ---------------------------------------------------------------------------
#define FQS 272                      // Q/K smem row stride bytes (128 bf16 + pad)
#define FVS 144                      // V^T smem row stride bytes (64 bf16 + pad)
#define FQ_TILE (128*FQS)            // 34816
#define FK_TILE (64*FQS)             // 17408
#define FV_TILE (128*FVS)            // 18432
#define FKV_STAGE (2*FK_TILE + 2*FV_TILE)   // 71680
#define FLASH_SMEM (2*FQ_TILE + 2*FKV_STAGE) // 212992

__global__ __launch_bounds__(256) void flash_mma_kernel(
    const __nv_bfloat16* __restrict__ qh, const __nv_bfloat16* __restrict__ ql,
    const __nv_bfloat16* __restrict__ kh, const __nv_bfloat16* __restrict__ kl,
    const __nv_bfloat16* __restrict__ vh, const __nv_bfloat16* __restrict__ vl,
    __nv_bfloat16* __restrict__ AH, __nv_bfloat16* __restrict__ AL)
{
    extern __shared__ char sm_[];
    const uint32_t sb = smem_u32(sm_);
    const int tid  = threadIdx.x;
    const int wid  = tid >> 5;
    const int lane = tid & 31;
    const int g    = lane >> 2;
    const int t    = lane & 3;
    const int qt   = blockIdx.x;
    const int bh   = blockIdx.y;
    const int b    = bh >> 4;
    const int h    = bh & 15;

    const __nv_bfloat16* Qh = qh + (size_t)bh*TT*DD + (size_t)qt*128*DD;
    const __nv_bfloat16* Ql = ql + (size_t)bh*TT*DD + (size_t)qt*128*DD;
    const __nv_bfloat16* Kh = kh + (size_t)bh*TT*DD;
    const __nv_bfloat16* Kl = kl + (size_t)bh*TT*DD;
    const __nv_bfloat16* Vh = vh + (size_t)bh*DD*TT;   // [d][t]
    const __nv_bfloat16* Vl = vl + (size_t)bh*DD*TT;

    // Q tiles: 2 x 128 rows x 16 chunks(16B) = 4096 chunks / 256 thr
#pragma unroll
    for (int i = 0; i < 16; i++) {
        const int cid = i*256 + tid;
        const int tile = cid >> 11, rem = cid & 2047;
        const int row = rem >> 4, ch = rem & 15;
        const uint32_t dst = sb + (uint32_t)tile*FQ_TILE + (uint32_t)row*FQS + (uint32_t)ch*16;
        const __nv_bfloat16* src = (tile ? Ql : Qh) + (size_t)row*DD + ch*8;
        CP_ASYNC_16(dst, src);
    }
    auto LOAD_STAGE = [&](int s) {
        const uint32_t base = sb + 2*FQ_TILE + (uint32_t)(s & 1)*FKV_STAGE;
#pragma unroll
        for (int i = 0; i < 8; i++) {      // K: 2 tiles x 64 rows x 16 chunks
            const int cid = i*256 + tid;
            const int tile = cid >> 10, rem = cid & 1023;
            const int row = rem >> 4, ch = rem & 15;
            const uint32_t dst = base + (uint32_t)tile*FK_TILE + (uint32_t)row*FQS + (uint32_t)ch*16;
            const __nv_bfloat16* src = (tile ? Kl : Kh) + (size_t)(s*64 + row)*DD + ch*8;
            CP_ASYNC_16(dst, src);
        }
#pragma unroll
        for (int i = 0; i < 8; i++) {      // V: 2 tiles x 128 rows x 8 chunks
            const int cid = i*256 + tid;
            const int tile = cid >> 10, rem = cid & 1023;
            const int row = rem >> 3, ch = rem & 7;
            const uint32_t dst = base + 2*FK_TILE + (uint32_t)tile*FV_TILE
                               + (uint32_t)row*FVS + (uint32_t)ch*16;
            const __nv_bfloat16* src = (tile ? Vl : Vh) + (size_t)row*TT + s*64 + ch*8;
            CP_ASYNC_16(dst, src);
        }
        CP_ASYNC_COMMIT();
    };

    LOAD_STAGE(0);   // Q cps join stage-0's group
    LOAD_STAGE(1);

    const int NT = 2*qt + 2;
    float mI[2] = {-1e30f, -1e30f};
    float lI[2] = {0.f, 0.f};
    float o[16][4];
#pragma unroll
    for (int nt = 0; nt < 16; nt++)
#pragma unroll
        for (int e = 0; e < 4; e++) o[nt][e] = 0.f;

    const int row0g = qt*128 + wid*16 + g;   // global row of thread's first row
    const int row1g = row0g + 8;

    for (int kt = 0; kt < NT; kt++) {
        CP_ASYNC_WAIT1();
        __syncthreads();
        const uint32_t base = sb + 2*FQ_TILE + (uint32_t)(kt & 1)*FKV_STAGE;
        const uint32_t pKh = base;
        const uint32_t pKl = base + FK_TILE;
        const uint32_t pVh = base + 2*FK_TILE;
        const uint32_t pVl = base + 2*FK_TILE + FV_TILE;

        const bool active = (kt*64 <= qt*128 + wid*16 + 15);
        if (active) {
            // ---- S = Q K^T (split, 3 terms), fp32 frags
            float s[8][4];
#pragma unroll
            for (int nt = 0; nt < 8; nt++)
#pragma unroll
                for (int e = 0; e < 4; e++) s[nt][e] = 0.f;

#pragma unroll
            for (int k8 = 0; k8 < 8; k8++) {
                const int kb = k8*32 + 4*t;
                const int rA = wid*16 + g;
                uint32_t aH[4], aL[4];
                aH[0] = lds32(sb + rA*FQS + kb);
                aH[1] = lds32(sb + (rA+8)*FQS + kb);
                aH[2] = lds32(sb + rA*FQS + kb + 16);
                aH[3] = lds32(sb + (rA+8)*FQS + kb + 16);
                aL[0] = lds32(sb + FQ_TILE + rA*FQS + kb);
                aL[1] = lds32(sb + FQ_TILE + (rA+8)*FQS + kb);
                aL[2] = lds32(sb + FQ_TILE + rA*FQS + kb + 16);
                aL[3] = lds32(sb + FQ_TILE + (rA+8)*FQS + kb + 16);
#pragma unroll
                for (int nt = 0; nt < 8; nt++) {
                    const int rB = nt*8 + g;
                    uint32_t kh0 = lds32(pKh + rB*FQS + kb);
                    uint32_t kh1 = lds32(pKh + rB*FQS + kb + 16);
                    uint32_t kl0 = lds32(pKl + rB*FQS + kb);
                    uint32_t kl1 = lds32(pKl + rB*FQS + kb + 16);
                    mma16816(s[nt], aH, kh0, kh1);
                    mma16816(s[nt], aH, kl0, kl1);
                    mma16816(s[nt], aL, kh0, kh1);
                }
            }

            // ---- causal mask (only near diagonal)
            if (kt >= 2*qt) {
#pragma unroll
                for (int nt = 0; nt < 8; nt++) {
                    const int c0 = kt*64 + nt*8 + 2*t;
                    const int c1 = c0 + 1;
                    if (c0 > row0g) s[nt][0] = -1e30f;
                    if (c1 > row0g) s[nt][1] = -1e30f;
                    if (c0 > row1g) s[nt][2] = -1e30f;
                    if (c1 > row1g) s[nt][3] = -1e30f;
                }
            }

            // ---- online softmax (rows g and g+8)
            float mt0 = -1e30f, mt1 = -1e30f;
#pragma unroll
            for (int nt = 0; nt < 8; nt++) {
                mt0 = fmaxf(mt0, fmaxf(s[nt][0], s[nt][1]));
                mt1 = fmaxf(mt1, fmaxf(s[nt][2], s[nt][3]));
            }
            mt0 = fmaxf(mt0, __shfl_xor_sync(0xffffffffu, mt0, 1));
            mt0 = fmaxf(mt0, __shfl_xor_sync(0xffffffffu, mt0, 2));
            mt1 = fmaxf(mt1, __shfl_xor_sync(0xffffffffu, mt1, 1));
            mt1 = fmaxf(mt1, __shfl_xor_sync(0xffffffffu, mt1, 2));
            const float mn0 = fmaxf(mI[0], mt0);
            const float mn1 = fmaxf(mI[1], mt1);
            const float corr0 = __expf(mI[0] - mn0);
            const float corr1 = __expf(mI[1] - mn1);
            mI[0] = mn0; mI[1] = mn1;

            float rs0 = 0.f, rs1 = 0.f;
#pragma unroll
            for (int nt = 0; nt < 8; nt++) {
                s[nt][0] = __expf(s[nt][0] - mn0); rs0 += s[nt][0];
                s[nt][1] = __expf(s[nt][1] - mn0); rs0 += s[nt][1];
                s[nt][2] = __expf(s[nt][2] - mn1); rs1 += s[nt][2];
                s[nt][3] = __expf(s[nt][3] - mn1); rs1 += s[nt][3];
            }
            rs0 += __shfl_xor_sync(0xffffffffu, rs0, 1);
            rs0 += __shfl_xor_sync(0xffffffffu, rs0, 2);
            rs1 += __shfl_xor_sync(0xffffffffu, rs1, 1);
            rs1 += __shfl_xor_sync(0xffffffffu, rs1, 2);
            lI[0] = lI[0]*corr0 + rs0;
            lI[1] = lI[1]*corr1 + rs1;

#pragma unroll
            for (int nt = 0; nt < 16; nt++) {
                o[nt][0] *= corr0; o[nt][1] *= corr0;
                o[nt][2] *= corr1; o[nt][3] *= corr1;
            }

            // ---- pack P frags (A-layout) from S frags: hi + lo
            uint32_t ph[4][4], pl[4][4];
#pragma unroll
            for (int k4 = 0; k4 < 4; k4++) {
                const int e0 = 2*k4, e1 = 2*k4 + 1;
                ph[k4][0] = pack_bf2(s[e0][0], s[e0][1]);
                ph[k4][1] = pack_bf2(s[e0][2], s[e0][3]);
                ph[k4][2] = pack_bf2(s[e1][0], s[e1][1]);
                ph[k4][3] = pack_bf2(s[e1][2], s[e1][3]);
                float2 u0 = unpack_bf2(ph[k4][0]);
                float2 u1 = unpack_bf2(ph[k4][1]);
                float2 u2 = unpack_bf2(ph[k4][2]);
                float2 u3 = unpack_bf2(ph[k4][3]);
                pl[k4][0] = pack_bf2(s[e0][0]-u0.x, s[e0][1]-u0.y);
                pl[k4][1] = pack_bf2(s[e0][2]-u1.x, s[e0][3]-u1.y);
                pl[k4][2] = pack_bf2(s[e1][0]-u2.x, s[e1][1]-u2.y);
                pl[k4][3] = pack_bf2(s[e1][2]-u3.x, s[e1][3]-u3.y);
            }

            // ---- O += P V (split, 3 terms).  B operand: V^T smem [d][s]
#pragma unroll
            for (int k4 = 0; k4 < 4; k4++) {
                const int kb2 = k4*32 + 4*t;
#pragma unroll
                for (int nt = 0; nt < 16; nt++) {
                    const int rB = nt*8 + g;
                    uint32_t vh0 = lds32(pVh + rB*FVS + kb2);
                    uint32_t vh1 = lds32(pVh + rB*FVS + kb2 + 16);
                    uint32_t vl0 = lds32(pVl + rB*FVS + kb2);
                    uint32_t vl1 = lds32(pVl + rB*FVS + kb2 + 16);
                    mma16816(o[nt], ph[k4], vh0, vh1);
                    mma16816(o[nt], ph[k4], vl0, vl1);
                    mma16816(o[nt], pl[k4], vh0, vh1);
                }
            }
        }
        __syncthreads();
        if (kt + 2 < NT) LOAD_STAGE(kt + 2);
        else             CP_ASYNC_COMMIT();
    }

    // ---- epilogue: write split bf16 directly (feeds proj GEMM)
    const float inv0 = 1.0f / lI[0];
    const float inv1 = 1.0f / lI[1];
    __nv_bfloat16* ah0 = AH + ((size_t)(b*TT + row0g))*CC + h*DD;
    __nv_bfloat16* ah1 = AH + ((size_t)(b*TT + row1g))*CC + h*DD;
    __nv_bfloat16* al0 = AL + ((size_t)(b*TT + row0g))*CC + h*DD;
    __nv_bfloat16* al1 = AL + ((size_t)(b*TT + row1g))*CC + h*DD;
#pragma unroll
    for (int nt = 0; nt < 16; nt++) {
        const int col = nt*8 + 2*t;
        float v00 = o[nt][0]*inv0, v01 = o[nt][1]*inv0;
        float v10 = o[nt][2]*inv1, v11 = o[nt][3]*inv1;
        uint32_t H0 = pack_bf2(v00, v01);
        uint32_t H1 = pack_bf2(v10, v11);
        float2 u0 = unpack_bf2(H0);
        float2 u1 = unpack_bf2(H1);
        uint32_t L0 = pack_bf2(v00 - u0.x, v01 - u0.y);
        uint32_t L1 = pack_bf2(v10 - u1.x, v11 - u1.y);
        *(uint32_t*)(ah0 + col) = H0;
        *(uint32_t*)(ah1 + col) = H1;
        *(uint32_t*)(al0 + col) = L0;
        *(uint32_t*)(al1 + col) = L1;
    }
}

// ---------------------------------------------------------------------------
// Fused LayerNorm(z)*g+b + residual.  SPLIT=1 also emits bf16 hi/lo of out.
// ---------------------------------------------------------------------------
template <int SPLIT>
__global__ __launch_bounds__(256) void ln_add_kernel(
    const float* __restrict__ z, const float* __restrict__ res,
    const float* __restrict__ gam, const float* __restrict__ bet,
    float* __restrict__ out, __nv_bfloat16* __restrict__ hi,
    __nv_bfloat16* __restrict__ lo)
{
    __shared__ float red[256];
    const int row = blockIdx.x;
    const int tid = threadIdx.x;
    const float* zr = z + (size_t)row * CC;

    float v[8];
#pragma unroll
    for (int i = 0; i < 2; i++) {
        float4 t4 = *(const float4*)(zr + i*1024 + tid*4);
        v[i*4+0] = t4.x; v[i*4+1] = t4.y; v[i*4+2] = t4.z; v[i*4+3] = t4.w;
    }

    float s = 0.f;
#pragma unroll
    for (int i = 0; i < 8; i++) s += v[i];
    red[tid] = s; __syncthreads();
#pragma unroll
    for (int off = 128; off; off >>= 1) {
        if (tid < off) red[tid] += red[tid + off];
        __syncthreads();
    }
    const float mean = red[0] * (1.0f / 2048.0f);
    __syncthreads();

    float vs = 0.f;
#pragma unroll
    for (int i = 0; i < 8; i++) { const float d = v[i] - mean; vs += d * d; }
    red[tid] = vs; __syncthreads();
#pragma unroll
    for (int off = 128; off; off >>= 1) {
        if (tid < off) red[tid] += red[tid + off];
        __syncthreads();
    }
    const float rstd = rsqrtf(red[0] * (1.0f / 2048.0f) + 1e-6f);

    const float* rr = res + (size_t)row * CC;
    float* orow = out + (size_t)row * CC;
#pragma unroll
    for (int i = 0; i < 2; i++) {
        const int c0 = i*1024 + tid*4;
        float4 g4 = *(const float4*)(gam + c0);
        float4 b4 = *(const float4*)(bet + c0);
        float4 r4 = *(const float4*)(rr + c0);
        float4 ov;
        ov.x = (v[i*4+0] - mean)*rstd*g4.x + b4.x + r4.x;
        ov.y = (v[i*4+1] - mean)*rstd*g4.y + b4.y + r4.y;
        ov.z = (v[i*4+2] - mean)*rstd*g4.z + b4.z + r4.z;
        ov.w = (v[i*4+3] - mean)*rstd*g4.w + b4.w + r4.w;
        *(float4*)(orow + c0) = ov;
        if (SPLIT) {
            float f[4] = {ov.x, ov.y, ov.z, ov.w};
            union U { __nv_bfloat16 b[4]; uint2 u; } H, L;
#pragma unroll
            for (int j = 0; j < 4; j++) {
                H.b[j] = __float2bfloat16(f[j]);
                L.b[j] = __float2bfloat16(f[j] - __bfloat162float(H.b[j]));
            }
            *(uint2*)(hi + (size_t)row*CC + c0) = H.u;
            *(uint2*)(lo + (size_t)row*CC + c0) = L.u;
        }
    }
}

// ---------------------------------------------------------------------------
extern "C" void kernel_launch(void* const* d_in, const int* in_sizes, int n_in,
                              void* d_out, int out_size)
{
    const float* x    = (const float*)d_in[0];
    const float* mask = (const float*)d_in[1];
    const float* W[5] = { (const float*)d_in[2],  (const float*)d_in[4],
                          (const float*)d_in[6],  (const float*)d_in[8],
                          (const float*)d_in[10] };                 // Wq,Wk,Wv,Wp,Wfc
    const float* bq   = (const float*)d_in[3];
    const float* bk   = (const float*)d_in[5];
    const float* bv   = (const float*)d_in[7];
    const float* bp   = (const float*)d_in[9];
    const float* bfc  = (const float*)d_in[11];
    const float* ln_g = (const float*)d_in[12];
    const float* ln_b = (const float*)d_in[13];

    float *t0, *t1;
    __nv_bfloat16 *qh, *ql, *kh, *kl, *vh, *vl, *xh, *xl, *ah, *al, *wh, *wl;
    cudaGetSymbolAddress((void**)&qh, g_qh);
    cudaGetSymbolAddress((void**)&ql, g_ql);
    cudaGetSymbolAddress((void**)&kh, g_kh);
    cudaGetSymbolAddress((void**)&kl, g_kl);
    cudaGetSymbolAddress((void**)&vh, g_vh);
    cudaGetSymbolAddress((void**)&vl, g_vl);
    cudaGetSymbolAddress((void**)&t0, g_t0);
    cudaGetSymbolAddress((void**)&t1, g_t1);
    cudaGetSymbolAddress((void**)&xh, g_xh);
    cudaGetSymbolAddress((void**)&xl, g_xl);
    cudaGetSymbolAddress((void**)&ah, g_ah);
    cudaGetSymbolAddress((void**)&al, g_al);
    cudaGetSymbolAddress((void**)&wh, g_wh);
    cudaGetSymbolAddress((void**)&wl, g_wl);

    cudaFuncSetAttribute(gemm_mma_kernel,
                         cudaFuncAttributeMaxDynamicSharedMemorySize, GEMM_SMEM);
    cudaFuncSetAttribute(flash_mma_kernel,
                         cudaFuncAttributeMaxDynamicSharedMemorySize, FLASH_SMEM);

    const dim3 gg(CC/128, MM/128);         // (16, 32)
    const int ACT4 = MM*CC/4;
    const int WT4  = CC*CC/4;

    // split input/weights to bf16 hi/lo
    split_kernel<<<ACT4/256, 256>>>(x, xh, xl);
    for (int i = 0; i < 5; i++)
        split_kernel<<<WT4/256, 256>>>(W[i], wh + (size_t)i*CC*CC, wl + (size_t)i*CC*CC);

    // QKV projections -> split bf16; Q scaled; V transposed [B,H,D,T]
    gemm_mma_kernel<<<gg, 256, GEMM_SMEM>>>(xh, xl, wh + 0*(size_t)CC*CC, wl + 0*(size_t)CC*CC,
                                            bq, nullptr, nullptr, qh, ql, QSCALE, 0);
    gemm_mma_kernel<<<gg, 256, GEMM_SMEM>>>(xh, xl, wh + 1*(size_t)CC*CC, wl + 1*(size_t)CC*CC,
                                            bk, nullptr, nullptr, kh, kl, 1.0f, 0);
    gemm_mma_kernel<<<gg, 256, GEMM_SMEM>>>(xh, xl, wh + 2*(size_t)CC*CC, wl + 2*(size_t)CC*CC,
                                            bv, nullptr, nullptr, vh, vl, 1.0f, 3);

    // causal flash attention (tensorized) -> ah/al split bf16 directly
    flash_mma_kernel<<<dim3(TT/128, BB*HH), 256, FLASH_SMEM>>>(qh, ql, kh, kl, vh, vl, ah, al);

    // output projection (+bias, *mask) -> t0
    gemm_mma_kernel<<<gg, 256, GEMM_SMEM>>>(ah, al, wh + 3*(size_t)CC*CC, wl + 3*(size_t)CC*CC,
                                            bp, mask, t0, nullptr, nullptr, 1.0f, 2);

    // x1 = LN(t0) + x -> t1 (+ split to ah/al for FC GEMM)
    ln_add_kernel<1><<<MM, 256>>>(t0, x, ln_g, ln_b, t1, ah, al);

    // fc = x1 @ Wfc^T + bfc -> t0
    gemm_mma_kernel<<<gg, 256, GEMM_SMEM>>>(ah, al, wh + 4*(size_t)CC*CC, wl + 4*(size_t)CC*CC,
                                            bfc, nullptr, t0, nullptr, nullptr, 1.0f, 1);

    // out = LN(t0) + x1
    ln_add_kernel<0><<<MM, 256>>>(t0, t1, ln_g, ln_b, (float*)d_out, nullptr, nullptr);
}

// round 12
// speedup vs baseline: 2.3629x; 1.0103x over previous
#include <cuda_runtime.h>
#include <cuda_bf16.h>
#include <math.h>
#include <cstdint>

// Problem constants (fixed shapes)
#define BB 2
#define TT 2048
#define CC 2048
#define HH 16
#define DD 128
#define MM (BB*TT)          // 4096 rows
#define KK 2048
#define QSCALE 0.08838834764831845f  // 1/sqrt(128)

// ---------------- scratch (device globals; no allocation allowed) ----------
__device__ __nv_bfloat16 g_qh[BB*HH*TT*DD], g_ql[BB*HH*TT*DD];  // [B,H,T,D]
__device__ __nv_bfloat16 g_kh[BB*HH*TT*DD], g_kl[BB*HH*TT*DD];  // [B,H,T,D]
__device__ __nv_bfloat16 g_vh[BB*HH*TT*DD], g_vl[BB*HH*TT*DD];  // [B,H,D,T] (transposed)
__device__ float g_t0[MM*CC];        // proj out / fc out
__device__ float g_t1[MM*CC];        // x1

// split-bf16 operands for GEMMs
__device__ __nv_bfloat16 g_xh[MM*CC],  g_xl[MM*CC];    // x split
__device__ __nv_bfloat16 g_ah[MM*CC],  g_al[MM*CC];    // flash out split, then t1 split
__device__ __nv_bfloat16 g_wh[5*CC*CC], g_wl[5*CC*CC]; // Wq,Wk,Wv,Wp,Wfc splits

// ============================ helpers ======================================
__device__ __forceinline__ uint32_t smem_u32(const void* p) {
    uint32_t a;
    asm("{ .reg .u64 t; cvta.to.shared.u64 t, %1; cvt.u32.u64 %0, t; }" : "=r"(a) : "l"(p));
    return a;
}

#define CP_ASYNC_16(dst_u32, src_ptr) \
    asm volatile("cp.async.cg.shared.global [%0], [%1], 16;" :: "r"(dst_u32), "l"(src_ptr))
#define CP_ASYNC_COMMIT() asm volatile("cp.async.commit_group;" ::: "memory")
#define CP_ASYNC_WAIT1()  asm volatile("cp.async.wait_group 1;" ::: "memory")

__device__ __forceinline__ void mma16816(float* d, const uint32_t* a,
                                         uint32_t b0, uint32_t b1) {
    asm volatile(
        "mma.sync.aligned.m16n8k16.row.col.f32.bf16.bf16.f32 "
        "{%0,%1,%2,%3}, {%4,%5,%6,%7}, {%8,%9}, {%0,%1,%2,%3};"
        : "+f"(d[0]), "+f"(d[1]), "+f"(d[2]), "+f"(d[3])
        : "r"(a[0]), "r"(a[1]), "r"(a[2]), "r"(a[3]), "r"(b0), "r"(b1));
}

__device__ __forceinline__ uint32_t lds32(uint32_t addr) {
    uint32_t v;
    asm volatile("ld.shared.b32 %0, [%1];" : "=r"(v) : "r"(addr));
    return v;
}

__device__ __forceinline__ uint32_t pack_bf2(float lo, float hi) {
    __nv_bfloat162 r = __floats2bfloat162_rn(lo, hi);   // x=lo (low 16b), y=hi
    return *(uint32_t*)&r;
}
__device__ __forceinline__ float2 unpack_bf2(uint32_t u) {
    __nv_bfloat162 h = *(__nv_bfloat162*)&u;
    return make_float2(__bfloat162float(h.x), __bfloat162float(h.y));
}

// ---------------------------------------------------------------------------
// Split-bf16 NT GEMM (R8/R11-validated core: 8 warps, 32x64 warp tiles).
// epilogues:
//  0: split-bf16 out -> (outh,outl) [B,H,T,D] with *scale     (Q,K)
//  3: split-bf16 out -> (outh,outl) [B,H,D,T] transposed      (V)
//  1: fp32 out[m*CC+n]                                        (FC)
//  2: fp32 out[m*CC+n] * mask[m]                               (proj)
// QKV=1 instantiation: blockIdx.z in {0,1,2} selects Wq/Wk/Wv, bias, epi.
// ---------------------------------------------------------------------------
#define BKH 32
#define NST (KK/BKH)                 // 64
#define SRB 80                       // smem row stride bytes (40 halves)
#define TILE_TERM_B (128*SRB)        // 10240
#define STAGE_B (4*TILE_TERM_B)      // 40960
#define GEMM_SMEM (2*STAGE_B)        // 81920

template <int QKV>
__global__ __launch_bounds__(256) void gemm_mma_kernel(
    const __nv_bfloat16* __restrict__ Ah, const __nv_bfloat16* __restrict__ Al,
    const __nv_bfloat16* __restrict__ Bh, const __nv_bfloat16* __restrict__ Bl,
    const float* __restrict__ bias0, const float* __restrict__ bias1,
    const float* __restrict__ bias2, const float* __restrict__ mask,
    float* __restrict__ out,
    __nv_bfloat16* __restrict__ oh0, __nv_bfloat16* __restrict__ ol0,
    __nv_bfloat16* __restrict__ oh1, __nv_bfloat16* __restrict__ ol1,
    __nv_bfloat16* __restrict__ oh2, __nv_bfloat16* __restrict__ ol2,
    float scale0, int epi0)
{
    extern __shared__ char sm_[];
    const uint32_t sb = smem_u32(sm_);
    const int tid    = threadIdx.x;
    const int wid    = tid >> 5;
    const int lane   = tid & 31;
    const int warp_m = wid & 3;
    const int warp_n = wid >> 2;
    const int g      = lane >> 2;
    const int t      = lane & 3;
    const int m0 = blockIdx.y * 128;
    const int n0 = blockIdx.x * 128;

    // per-z selection (uniform across CTA; QKV=0 collapses at compile time)
    const int z = QKV ? blockIdx.z : 0;
    const float* bias = (z == 0) ? bias0 : (z == 1) ? bias1 : bias2;
    __nv_bfloat16* outh = (z == 0) ? oh0 : (z == 1) ? oh1 : oh2;
    __nv_bfloat16* outl = (z == 0) ? ol0 : (z == 1) ? ol1 : ol2;
    const float scale = (QKV && z != 0) ? 1.0f : scale0;
    const int epi     = (QKV) ? ((z == 2) ? 3 : 0) : epi0;
    const size_t woff = QKV ? (size_t)z * CC * CC : 0;

    const __nv_bfloat16* srcs[4] = { Ah + (size_t)m0*KK, Al + (size_t)m0*KK,
                                     Bh + woff + (size_t)n0*KK,
                                     Bl + woff + (size_t)n0*KK };

    float acc[2][8][4];
#pragma unroll
    for (int mt = 0; mt < 2; mt++)
#pragma unroll
        for (int nt = 0; nt < 8; nt++)
#pragma unroll
            for (int r = 0; r < 4; r++) acc[mt][nt][r] = 0.f;

    const int cid0 = tid;
    auto LOAD_STAGE = [&](int s) {
        const int k0 = s * BKH;
        const uint32_t base = sb + (uint32_t)(s & 1) * STAGE_B;
#pragma unroll
        for (int tl = 0; tl < 4; tl++) {
            const __nv_bfloat16* src = srcs[tl];
#pragma unroll
            for (int i = 0; i < 2; i++) {
                const int cid = cid0 + i * 256;
                const int row = cid >> 2, c = cid & 3;
                const uint32_t dst = base + (uint32_t)tl * TILE_TERM_B
                                   + (uint32_t)row * SRB + (uint32_t)c * 16;
                CP_ASYNC_16(dst, src + (size_t)row * KK + k0 + c * 8);
            }
        }
        CP_ASYNC_COMMIT();
    };

    LOAD_STAGE(0);
    LOAD_STAGE(1);

    for (int s = 0; s < NST; s++) {
        CP_ASYNC_WAIT1();
        __syncthreads();

        const uint32_t base = sb + (uint32_t)(s & 1) * STAGE_B;
        const uint32_t pAh = base;
        const uint32_t pAl = base + TILE_TERM_B;
        const uint32_t pBh = base + 2*TILE_TERM_B;
        const uint32_t pBl = base + 3*TILE_TERM_B;

#pragma unroll
        for (int ks = 0; ks < 2; ks++) {
            const int kb = (ks * 16 + 2*t) * 2;
            uint32_t aH[2][4], aL[2][4];
#pragma unroll
            for (int mt = 0; mt < 2; mt++) {
                const int r = warp_m*32 + mt*16 + g;
                aH[mt][0] = lds32(pAh + r*SRB + kb);
                aH[mt][1] = lds32(pAh + (r+8)*SRB + kb);
                aH[mt][2] = lds32(pAh + r*SRB + kb + 16);
                aH[mt][3] = lds32(pAh + (r+8)*SRB + kb + 16);
                aL[mt][0] = lds32(pAl + r*SRB + kb);
                aL[mt][1] = lds32(pAl + (r+8)*SRB + kb);
                aL[mt][2] = lds32(pAl + r*SRB + kb + 16);
                aL[mt][3] = lds32(pAl + (r+8)*SRB + kb + 16);
            }
#pragma unroll
            for (int nt = 0; nt < 8; nt++) {
                const int n = warp_n*64 + nt*8 + g;
                uint32_t bh0 = lds32(pBh + n*SRB + kb);
                uint32_t bh1 = lds32(pBh + n*SRB + kb + 16);
                uint32_t bl0 = lds32(pBl + n*SRB + kb);
                uint32_t bl1 = lds32(pBl + n*SRB + kb + 16);
#pragma unroll
                for (int mt = 0; mt < 2; mt++) {
                    mma16816(acc[mt][nt], aH[mt], bh0, bh1);
                    mma16816(acc[mt][nt], aH[mt], bl0, bl1);
                    mma16816(acc[mt][nt], aL[mt], bh0, bh1);
                }
            }
        }
        __syncthreads();
        if (s + 2 < NST) LOAD_STAGE(s + 2);
        else             CP_ASYNC_COMMIT();
    }

#pragma unroll
    for (int mt = 0; mt < 2; mt++) {
#pragma unroll
        for (int nt = 0; nt < 8; nt++) {
            const float* d = acc[mt][nt];
            const int r0 = m0 + warp_m*32 + mt*16 + g;
            const int r1 = r0 + 8;
            const int n  = n0 + warp_n*64 + nt*8 + 2*t;
            const float2 b2 = *(const float2*)(bias + n);
            float v00 = d[0] + b2.x, v01 = d[1] + b2.y;
            float v10 = d[2] + b2.x, v11 = d[3] + b2.y;
            if (epi == 0 || epi == 3) {
                v00 *= scale; v01 *= scale; v10 *= scale; v11 *= scale;
                const int hh  = n >> 7;
                const int dd  = n & (DD - 1);
                const int b0i = r0 >> 11, t0i = r0 & (TT-1);
                const int b1i = r1 >> 11, t1i = r1 & (TT-1);
                __nv_bfloat16 h00 = __float2bfloat16(v00);
                __nv_bfloat16 h01 = __float2bfloat16(v01);
                __nv_bfloat16 h10 = __float2bfloat16(v10);
                __nv_bfloat16 h11 = __float2bfloat16(v11);
                __nv_bfloat16 l00 = __float2bfloat16(v00 - __bfloat162float(h00));
                __nv_bfloat16 l01 = __float2bfloat16(v01 - __bfloat162float(h01));
                __nv_bfloat16 l10 = __float2bfloat16(v10 - __bfloat162float(h10));
                __nv_bfloat16 l11 = __float2bfloat16(v11 - __bfloat162float(h11));
                if (epi == 0) {   // [B,H,T,D]
                    const size_t i0 = (((size_t)(b0i*HH + hh))*TT + t0i)*DD + dd;
                    const size_t i1 = (((size_t)(b1i*HH + hh))*TT + t1i)*DD + dd;
                    __nv_bfloat162 H0; H0.x = h00; H0.y = h01;
                    __nv_bfloat162 H1; H1.x = h10; H1.y = h11;
                    __nv_bfloat162 L0; L0.x = l00; L0.y = l01;
                    __nv_bfloat162 L1; L1.x = l10; L1.y = l11;
                    *(__nv_bfloat162*)(outh + i0) = H0;
                    *(__nv_bfloat162*)(outh + i1) = H1;
                    *(__nv_bfloat162*)(outl + i0) = L0;
                    *(__nv_bfloat162*)(outl + i1) = L1;
                } else {          // [B,H,D,T] transposed
                    const size_t c0 = (((size_t)(b0i*HH + hh))*DD + dd)*TT + t0i;
                    const size_t c1 = (((size_t)(b1i*HH + hh))*DD + dd)*TT + t1i;
                    outh[c0] = h00; outh[c0 + TT] = h01;
                    outh[c1] = h10; outh[c1 + TT] = h11;
                    outl[c0] = l00; outl[c0 + TT] = l01;
                    outl[c1] = l10; outl[c1 + TT] = l11;
                }
            } else if (epi == 1) {
                *(float2*)(out + (size_t)r0*CC + n) = make_float2(v00, v01);
                *(float2*)(out + (size_t)r1*CC + n) = make_float2(v10, v11);
            } else {
                const float mk0 = mask[r0], mk1 = mask[r1];
                *(float2*)(out + (size_t)r0*CC + n) = make_float2(v00*mk0, v01*mk0);
                *(float2*)(out + (size_t)r1*CC + n) = make_float2(v10*mk1, v11*mk1);
            }
        }
    }
}

// ---------------------------------------------------------------------------
// Fused split: x (2 regions) + 5 weights (contiguous in g_wh/g_wl).
// 4096 blocks per 4M-element region; 7 regions = 28672 blocks.
// ---------------------------------------------------------------------------
__global__ __launch_bounds__(256) void split_all_kernel(
    const float* __restrict__ x,
    const float* __restrict__ w0, const float* __restrict__ w1,
    const float* __restrict__ w2, const float* __restrict__ w3,
    const float* __restrict__ w4,
    __nv_bfloat16* __restrict__ xh, __nv_bfloat16* __restrict__ xl,
    __nv_bfloat16* __restrict__ wh, __nv_bfloat16* __restrict__ wl)
{
    const int region = blockIdx.x >> 12;            // 4096 blocks per region
    const int bi     = blockIdx.x & 4095;
    const int i      = bi * 256 + threadIdx.x;      // float4 index within region

    const float* src;
    __nv_bfloat16 *hi, *lo;
    if (region < 2) {
        src = x + (size_t)region * (CC*CC);         // 4M floats per region
        hi  = xh + (size_t)region * (CC*CC);
        lo  = xl + (size_t)region * (CC*CC);
    } else {
        const int w = region - 2;
        src = (w == 0) ? w0 : (w == 1) ? w1 : (w == 2) ? w2 : (w == 3) ? w3 : w4;
        hi  = wh + (size_t)w * (CC*CC);
        lo  = wl + (size_t)w * (CC*CC);
    }

    float4 v = ((const float4*)src)[i];
    float f[4] = {v.x, v.y, v.z, v.w};
    union U { __nv_bfloat16 b[4]; uint2 u; } H, L;
#pragma unroll
    for (int j = 0; j < 4; j++) {
        H.b[j] = __float2bfloat16(f[j]);
        L.b[j] = __float2bfloat16(f[j] - __bfloat162float(H.b[j]));
    }
    ((uint2*)hi)[i] = H.u;
    ((uint2*)lo)[i] = L.u;
}

// ---------------------------------------------------------------------------
// Causal flash attention on mma.sync, split-bf16 (unchanged, R8/R11-validated).
// ---------------------------------------------------------------------------
#define FQS 272                      // Q/K smem row stride bytes (128 bf16 + pad)
#define FVS 144                      // V^T smem row stride bytes (64 bf16 + pad)
#define FQ_TILE (128*FQS)            // 34816
#define FK_TILE (64*FQS)             // 17408
#define FV_TILE (128*FVS)            // 18432
#define FKV_STAGE (2*FK_TILE + 2*FV_TILE)   // 71680
#define FLASH_SMEM (2*FQ_TILE + 2*FKV_STAGE) // 212992

__global__ __launch_bounds__(256) void flash_mma_kernel(
    const __nv_bfloat16* __restrict__ qh, const __nv_bfloat16* __restrict__ ql,
    const __nv_bfloat16* __restrict__ kh, const __nv_bfloat16* __restrict__ kl,
    const __nv_bfloat16* __restrict__ vh, const __nv_bfloat16* __restrict__ vl,
    __nv_bfloat16* __restrict__ AH, __nv_bfloat16* __restrict__ AL)
{
    extern __shared__ char sm_[];
    const uint32_t sb = smem_u32(sm_);
    const int tid  = threadIdx.x;
    const int wid  = tid >> 5;
    const int lane = tid & 31;
    const int g    = lane >> 2;
    const int t    = lane & 3;
    const int qt   = blockIdx.x;
    const int bh   = blockIdx.y;
    const int b    = bh >> 4;
    const int h    = bh & 15;

    const __nv_bfloat16* Qh = qh + (size_t)bh*TT*DD + (size_t)qt*128*DD;
    const __nv_bfloat16* Ql = ql + (size_t)bh*TT*DD + (size_t)qt*128*DD;
    const __nv_bfloat16* Kh = kh + (size_t)bh*TT*DD;
    const __nv_bfloat16* Kl = kl + (size_t)bh*TT*DD;
    const __nv_bfloat16* Vh = vh + (size_t)bh*DD*TT;   // [d][t]
    const __nv_bfloat16* Vl = vl + (size_t)bh*DD*TT;

    // Q tiles: 2 x 128 rows x 16 chunks(16B) = 4096 chunks / 256 thr
#pragma unroll
    for (int i = 0; i < 16; i++) {
        const int cid = i*256 + tid;
        const int tile = cid >> 11, rem = cid & 2047;
        const int row = rem >> 4, ch = rem & 15;
        const uint32_t dst = sb + (uint32_t)tile*FQ_TILE + (uint32_t)row*FQS + (uint32_t)ch*16;
        const __nv_bfloat16* src = (tile ? Ql : Qh) + (size_t)row*DD + ch*8;
        CP_ASYNC_16(dst, src);
    }
    auto LOAD_STAGE = [&](int s) {
        const uint32_t base = sb + 2*FQ_TILE + (uint32_t)(s & 1)*FKV_STAGE;
#pragma unroll
        for (int i = 0; i < 8; i++) {      // K: 2 tiles x 64 rows x 16 chunks
            const int cid = i*256 + tid;
            const int tile = cid >> 10, rem = cid & 1023;
            const int row = rem >> 4, ch = rem & 15;
            const uint32_t dst = base + (uint32_t)tile*FK_TILE + (uint32_t)row*FQS + (uint32_t)ch*16;
            const __nv_bfloat16* src = (tile ? Kl : Kh) + (size_t)(s*64 + row)*DD + ch*8;
            CP_ASYNC_16(dst, src);
        }
#pragma unroll
        for (int i = 0; i < 8; i++) {      // V: 2 tiles x 128 rows x 8 chunks
            const int cid = i*256 + tid;
            const int tile = cid >> 10, rem = cid & 1023;
            const int row = rem >> 3, ch = rem & 7;
            const uint32_t dst = base + 2*FK_TILE + (uint32_t)tile*FV_TILE
                               + (uint32_t)row*FVS + (uint32_t)ch*16;
            const __nv_bfloat16* src = (tile ? Vl : Vh) + (size_t)row*TT + s*64 + ch*8;
            CP_ASYNC_16(dst, src);
        }
        CP_ASYNC_COMMIT();
    };

    LOAD_STAGE(0);   // Q cps join stage-0's group
    LOAD_STAGE(1);

    const int NT = 2*qt + 2;
    float mI[2] = {-1e30f, -1e30f};
    float lI[2] = {0.f, 0.f};
    float o[16][4];
#pragma unroll
    for (int nt = 0; nt < 16; nt++)
#pragma unroll
        for (int e = 0; e < 4; e++) o[nt][e] = 0.f;

    const int row0g = qt*128 + wid*16 + g;   // global row of thread's first row
    const int row1g = row0g + 8;

    for (int kt = 0; kt < NT; kt++) {
        CP_ASYNC_WAIT1();
        __syncthreads();
        const uint32_t base = sb + 2*FQ_TILE + (uint32_t)(kt & 1)*FKV_STAGE;
        const uint32_t pKh = base;
        const uint32_t pKl = base + FK_TILE;
        const uint32_t pVh = base + 2*FK_TILE;
        const uint32_t pVl = base + 2*FK_TILE + FV_TILE;

        const bool active = (kt*64 <= qt*128 + wid*16 + 15);
        if (active) {
            // ---- S = Q K^T (split, 3 terms), fp32 frags
            float s[8][4];
#pragma unroll
            for (int nt = 0; nt < 8; nt++)
#pragma unroll
                for (int e = 0; e < 4; e++) s[nt][e] = 0.f;

#pragma unroll
            for (int k8 = 0; k8 < 8; k8++) {
                const int kb = k8*32 + 4*t;
                const int rA = wid*16 + g;
                uint32_t aH[4], aL[4];
                aH[0] = lds32(sb + rA*FQS + kb);
                aH[1] = lds32(sb + (rA+8)*FQS + kb);
                aH[2] = lds32(sb + rA*FQS + kb + 16);
                aH[3] = lds32(sb + (rA+8)*FQS + kb + 16);
                aL[0] = lds32(sb + FQ_TILE + rA*FQS + kb);
                aL[1] = lds32(sb + FQ_TILE + (rA+8)*FQS + kb);
                aL[2] = lds32(sb + FQ_TILE + rA*FQS + kb + 16);
                aL[3] = lds32(sb + FQ_TILE + (rA+8)*FQS + kb + 16);
#pragma unroll
                for (int nt = 0; nt < 8; nt++) {
                    const int rB = nt*8 + g;
                    uint32_t kh0 = lds32(pKh + rB*FQS + kb);
                    uint32_t kh1 = lds32(pKh + rB*FQS + kb + 16);
                    uint32_t kl0 = lds32(pKl + rB*FQS + kb);
                    uint32_t kl1 = lds32(pKl + rB*FQS + kb + 16);
                    mma16816(s[nt], aH, kh0, kh1);
                    mma16816(s[nt], aH, kl0, kl1);
                    mma16816(s[nt], aL, kh0, kh1);
                }
            }

            // ---- causal mask (only near diagonal)
            if (kt >= 2*qt) {
#pragma unroll
                for (int nt = 0; nt < 8; nt++) {
                    const int c0 = kt*64 + nt*8 + 2*t;
                    const int c1 = c0 + 1;
                    if (c0 > row0g) s[nt][0] = -1e30f;
                    if (c1 > row0g) s[nt][1] = -1e30f;
                    if (c0 > row1g) s[nt][2] = -1e30f;
                    if (c1 > row1g) s[nt][3] = -1e30f;
                }
            }

            // ---- online softmax (rows g and g+8)
            float mt0 = -1e30f, mt1 = -1e30f;
#pragma unroll
            for (int nt = 0; nt < 8; nt++) {
                mt0 = fmaxf(mt0, fmaxf(s[nt][0], s[nt][1]));
                mt1 = fmaxf(mt1, fmaxf(s[nt][2], s[nt][3]));
            }
            mt0 = fmaxf(mt0, __shfl_xor_sync(0xffffffffu, mt0, 1));
            mt0 = fmaxf(mt0, __shfl_xor_sync(0xffffffffu, mt0, 2));
            mt1 = fmaxf(mt1, __shfl_xor_sync(0xffffffffu, mt1, 1));
            mt1 = fmaxf(mt1, __shfl_xor_sync(0xffffffffu, mt1, 2));
            const float mn0 = fmaxf(mI[0], mt0);
            const float mn1 = fmaxf(mI[1], mt1);
            const float corr0 = __expf(mI[0] - mn0);
            const float corr1 = __expf(mI[1] - mn1);
            mI[0] = mn0; mI[1] = mn1;

            float rs0 = 0.f, rs1 = 0.f;
#pragma unroll
            for (int nt = 0; nt < 8; nt++) {
                s[nt][0] = __expf(s[nt][0] - mn0); rs0 += s[nt][0];
                s[nt][1] = __expf(s[nt][1] - mn0); rs0 += s[nt][1];
                s[nt][2] = __expf(s[nt][2] - mn1); rs1 += s[nt][2];
                s[nt][3] = __expf(s[nt][3] - mn1); rs1 += s[nt][3];
            }
            rs0 += __shfl_xor_sync(0xffffffffu, rs0, 1);
            rs0 += __shfl_xor_sync(0xffffffffu, rs0, 2);
            rs1 += __shfl_xor_sync(0xffffffffu, rs1, 1);
            rs1 += __shfl_xor_sync(0xffffffffu, rs1, 2);
            lI[0] = lI[0]*corr0 + rs0;
            lI[1] = lI[1]*corr1 + rs1;

#pragma unroll
            for (int nt = 0; nt < 16; nt++) {
                o[nt][0] *= corr0; o[nt][1] *= corr0;
                o[nt][2] *= corr1; o[nt][3] *= corr1;
            }

            // ---- pack P frags (A-layout) from S frags: hi + lo
            uint32_t ph[4][4], pl[4][4];
#pragma unroll
            for (int k4 = 0; k4 < 4; k4++) {
                const int e0 = 2*k4, e1 = 2*k4 + 1;
                ph[k4][0] = pack_bf2(s[e0][0], s[e0][1]);
                ph[k4][1] = pack_bf2(s[e0][2], s[e0][3]);
                ph[k4][2] = pack_bf2(s[e1][0], s[e1][1]);
                ph[k4][3] = pack_bf2(s[e1][2], s[e1][3]);
                float2 u0 = unpack_bf2(ph[k4][0]);
                float2 u1 = unpack_bf2(ph[k4][1]);
                float2 u2 = unpack_bf2(ph[k4][2]);
                float2 u3 = unpack_bf2(ph[k4][3]);
                pl[k4][0] = pack_bf2(s[e0][0]-u0.x, s[e0][1]-u0.y);
                pl[k4][1] = pack_bf2(s[e0][2]-u1.x, s[e0][3]-u1.y);
                pl[k4][2] = pack_bf2(s[e1][0]-u2.x, s[e1][1]-u2.y);
                pl[k4][3] = pack_bf2(s[e1][2]-u3.x, s[e1][3]-u3.y);
            }

            // ---- O += P V (split, 3 terms).  B operand: V^T smem [d][s]
#pragma unroll
            for (int k4 = 0; k4 < 4; k4++) {
                const int kb2 = k4*32 + 4*t;
#pragma unroll
                for (int nt = 0; nt < 16; nt++) {
                    const int rB = nt*8 + g;
                    uint32_t vh0 = lds32(pVh + rB*FVS + kb2);
                    uint32_t vh1 = lds32(pVh + rB*FVS + kb2 + 16);
                    uint32_t vl0 = lds32(pVl + rB*FVS + kb2);
                    uint32_t vl1 = lds32(pVl + rB*FVS + kb2 + 16);
                    mma16816(o[nt], ph[k4], vh0, vh1);
                    mma16816(o[nt], ph[k4], vl0, vl1);
                    mma16816(o[nt], pl[k4], vh0, vh1);
                }
            }
        }
        __syncthreads();
        if (kt + 2 < NT) LOAD_STAGE(kt + 2);
        else             CP_ASYNC_COMMIT();
    }

    // ---- epilogue: write split bf16 directly (feeds proj GEMM)
    const float inv0 = 1.0f / lI[0];
    const float inv1 = 1.0f / lI[1];
    __nv_bfloat16* ah0 = AH + ((size_t)(b*TT + row0g))*CC + h*DD;
    __nv_bfloat16* ah1 = AH + ((size_t)(b*TT + row1g))*CC + h*DD;
    __nv_bfloat16* al0 = AL + ((size_t)(b*TT + row0g))*CC + h*DD;
    __nv_bfloat16* al1 = AL + ((size_t)(b*TT + row1g))*CC + h*DD;
#pragma unroll
    for (int nt = 0; nt < 16; nt++) {
        const int col = nt*8 + 2*t;
        float v00 = o[nt][0]*inv0, v01 = o[nt][1]*inv0;
        float v10 = o[nt][2]*inv1, v11 = o[nt][3]*inv1;
        uint32_t H0 = pack_bf2(v00, v01);
        uint32_t H1 = pack_bf2(v10, v11);
        float2 u0 = unpack_bf2(H0);
        float2 u1 = unpack_bf2(H1);
        uint32_t L0 = pack_bf2(v00 - u0.x, v01 - u0.y);
        uint32_t L1 = pack_bf2(v10 - u1.x, v11 - u1.y);
        *(uint32_t*)(ah0 + col) = H0;
        *(uint32_t*)(ah1 + col) = H1;
        *(uint32_t*)(al0 + col) = L0;
        *(uint32_t*)(al1 + col) = L1;
    }
}

// ---------------------------------------------------------------------------
// Fused LayerNorm(z)*g+b + residual.  SPLIT=1 also emits bf16 hi/lo of out.
// ---------------------------------------------------------------------------
template <int SPLIT>
__global__ __launch_bounds__(256) void ln_add_kernel(
    const float* __restrict__ z, const float* __restrict__ res,
    const float* __restrict__ gam, const float* __restrict__ bet,
    float* __restrict__ out, __nv_bfloat16* __restrict__ hi,
    __nv_bfloat16* __restrict__ lo)
{
    __shared__ float red[256];
    const int row = blockIdx.x;
    const int tid = threadIdx.x;
    const float* zr = z + (size_t)row * CC;

    float v[8];
#pragma unroll
    for (int i = 0; i < 2; i++) {
        float4 t4 = *(const float4*)(zr + i*1024 + tid*4);
        v[i*4+0] = t4.x; v[i*4+1] = t4.y; v[i*4+2] = t4.z; v[i*4+3] = t4.w;
    }

    float s = 0.f;
#pragma unroll
    for (int i = 0; i < 8; i++) s += v[i];
    red[tid] = s; __syncthreads();
#pragma unroll
    for (int off = 128; off; off >>= 1) {
        if (tid < off) red[tid] += red[tid + off];
        __syncthreads();
    }
    const float mean = red[0] * (1.0f / 2048.0f);
    __syncthreads();

    float vs = 0.f;
#pragma unroll
    for (int i = 0; i < 8; i++) { const float d = v[i] - mean; vs += d * d; }
    red[tid] = vs; __syncthreads();
#pragma unroll
    for (int off = 128; off; off >>= 1) {
        if (tid < off) red[tid] += red[tid + off];
        __syncthreads();
    }
    const float rstd = rsqrtf(red[0] * (1.0f / 2048.0f) + 1e-6f);

    const float* rr = res + (size_t)row * CC;
    float* orow = out + (size_t)row * CC;
#pragma unroll
    for (int i = 0; i < 2; i++) {
        const int c0 = i*1024 + tid*4;
        float4 g4 = *(const float4*)(gam + c0);
        float4 b4 = *(const float4*)(bet + c0);
        float4 r4 = *(const float4*)(rr + c0);
        float4 ov;
        ov.x = (v[i*4+0] - mean)*rstd*g4.x + b4.x + r4.x;
        ov.y = (v[i*4+1] - mean)*rstd*g4.y + b4.y + r4.y;
        ov.z = (v[i*4+2] - mean)*rstd*g4.z + b4.z + r4.z;
        ov.w = (v[i*4+3] - mean)*rstd*g4.w + b4.w + r4.w;
        *(float4*)(orow + c0) = ov;
        if (SPLIT) {
            float f[4] = {ov.x, ov.y, ov.z, ov.w};
            union U { __nv_bfloat16 b[4]; uint2 u; } H, L;
#pragma unroll
            for (int j = 0; j < 4; j++) {
                H.b[j] = __float2bfloat16(f[j]);
                L.b[j] = __float2bfloat16(f[j] - __bfloat162float(H.b[j]));
            }
            *(uint2*)(hi + (size_t)row*CC + c0) = H.u;
            *(uint2*)(lo + (size_t)row*CC + c0) = L.u;
        }
    }
}

// ---------------------------------------------------------------------------
extern "C" void kernel_launch(void* const* d_in, const int* in_sizes, int n_in,
                              void* d_out, int out_size)
{
    const float* x    = (const float*)d_in[0];
    const float* mask = (const float*)d_in[1];
    const float* Wq   = (const float*)d_in[2];
    const float* bq   = (const float*)d_in[3];
    const float* Wk   = (const float*)d_in[4];
    const float* bk   = (const float*)d_in[5];
    const float* Wv   = (const float*)d_in[6];
    const float* bv   = (const float*)d_in[7];
    const float* Wp   = (const float*)d_in[8];
    const float* bp   = (const float*)d_in[9];
    const float* Wfc  = (const float*)d_in[10];
    const float* bfc  = (const float*)d_in[11];
    const float* ln_g = (const float*)d_in[12];
    const float* ln_b = (const float*)d_in[13];

    float *t0, *t1;
    __nv_bfloat16 *qh, *ql, *kh, *kl, *vh, *vl, *xh, *xl, *ah, *al, *wh, *wl;
    cudaGetSymbolAddress((void**)&qh, g_qh);
    cudaGetSymbolAddress((void**)&ql, g_ql);
    cudaGetSymbolAddress((void**)&kh, g_kh);
    cudaGetSymbolAddress((void**)&kl, g_kl);
    cudaGetSymbolAddress((void**)&vh, g_vh);
    cudaGetSymbolAddress((void**)&vl, g_vl);
    cudaGetSymbolAddress((void**)&t0, g_t0);
    cudaGetSymbolAddress((void**)&t1, g_t1);
    cudaGetSymbolAddress((void**)&xh, g_xh);
    cudaGetSymbolAddress((void**)&xl, g_xl);
    cudaGetSymbolAddress((void**)&ah, g_ah);
    cudaGetSymbolAddress((void**)&al, g_al);
    cudaGetSymbolAddress((void**)&wh, g_wh);
    cudaGetSymbolAddress((void**)&wl, g_wl);

    cudaFuncSetAttribute(gemm_mma_kernel<1>,
                         cudaFuncAttributeMaxDynamicSharedMemorySize, GEMM_SMEM);
    cudaFuncSetAttribute(gemm_mma_kernel<0>,
                         cudaFuncAttributeMaxDynamicSharedMemorySize, GEMM_SMEM);
    cudaFuncSetAttribute(flash_mma_kernel,
                         cudaFuncAttributeMaxDynamicSharedMemorySize, FLASH_SMEM);

    const dim3 gg(CC/128, MM/128);          // (16, 32)
    const dim3 gqkv(CC/128, MM/128, 3);     // fused QKV

    // fused split: x (2 regions) + 5 weights (5 regions), 4096 blocks each
    split_all_kernel<<<7*4096, 256>>>(x, Wq, Wk, Wv, Wp, Wfc, xh, xl, wh, wl);

    // fused QKV projections -> split bf16; Q scaled; V transposed [B,H,D,T]
    gemm_mma_kernel<1><<<gqkv, 256, GEMM_SMEM>>>(
        xh, xl, wh, wl, bq, bk, bv, nullptr, nullptr,
        qh, ql, kh, kl, vh, vl, QSCALE, 0);

    // causal flash attention (tensorized) -> ah/al split bf16 directly
    flash_mma_kernel<<<dim3(TT/128, BB*HH), 256, FLASH_SMEM>>>(qh, ql, kh, kl, vh, vl, ah, al);

    // output projection (+bias, *mask) -> t0
    gemm_mma_kernel<0><<<gg, 256, GEMM_SMEM>>>(
        ah, al, wh + 3*(size_t)CC*CC, wl + 3*(size_t)CC*CC,
        bp, nullptr, nullptr, mask, t0,
        nullptr, nullptr, nullptr, nullptr, nullptr, nullptr, 1.0f, 2);

    // x1 = LN(t0) + x -> t1 (+ split to ah/al for FC GEMM)
    ln_add_kernel<1><<<MM, 256>>>(t0, x, ln_g, ln_b, t1, ah, al);

    // fc = x1 @ Wfc^T + bfc -> t0
    gemm_mma_kernel<0><<<gg, 256, GEMM_SMEM>>>(
        ah, al, wh + 4*(size_t)CC*CC, wl + 4*(size_t)CC*CC,
        bfc, nullptr, nullptr, nullptr, t0,
        nullptr, nullptr, nullptr, nullptr, nullptr, nullptr, 1.0f, 1);

    // out = LN(t0) + x1
    ln_add_kernel<0><<<MM, 256>>>(t0, t1, ln_g, ln_b, (float*)d_out, nullptr, nullptr);
}

// round 13
// speedup vs baseline: 2.3779x; 1.0064x over previous
#include <cuda_runtime.h>
#include <cuda_bf16.h>
#include <math.h>
#include <cstdint>

// Problem constants (fixed shapes)
#define BB 2
#define TT 2048
#define CC 2048
#define HH 16
#define DD 128
#define MM (BB*TT)          // 4096 rows
#define KK 2048
#define QSCALE 0.08838834764831845f  // 1/sqrt(128)

// ---------------- scratch (device globals; no allocation allowed) ----------
__device__ __nv_bfloat16 g_qh[BB*HH*TT*DD], g_ql[BB*HH*TT*DD];  // [B,H,T,D]
__device__ __nv_bfloat16 g_kh[BB*HH*TT*DD], g_kl[BB*HH*TT*DD];  // [B,H,T,D]
__device__ __nv_bfloat16 g_vh[BB*HH*TT*DD], g_vl[BB*HH*TT*DD];  // [B,H,D,T] (transposed)
__device__ float g_t0[MM*CC];        // proj out / fc out
__device__ float g_t1[MM*CC];        // x1

// split-bf16 operands for GEMMs
__device__ __nv_bfloat16 g_xh[MM*CC],  g_xl[MM*CC];    // x split
__device__ __nv_bfloat16 g_ah[MM*CC],  g_al[MM*CC];    // flash out split, then t1 split
__device__ __nv_bfloat16 g_wh[5*CC*CC], g_wl[5*CC*CC]; // Wq,Wk,Wv,Wp,Wfc splits

// ============================ helpers ======================================
__device__ __forceinline__ uint32_t smem_u32(const void* p) {
    uint32_t a;
    asm("{ .reg .u64 t; cvta.to.shared.u64 t, %1; cvt.u32.u64 %0, t; }" : "=r"(a) : "l"(p));
    return a;
}

#define CP_ASYNC_16(dst_u32, src_ptr) \
    asm volatile("cp.async.cg.shared.global [%0], [%1], 16;" :: "r"(dst_u32), "l"(src_ptr))
#define CP_ASYNC_COMMIT() asm volatile("cp.async.commit_group;" ::: "memory")
#define CP_ASYNC_WAIT1()  asm volatile("cp.async.wait_group 1;" ::: "memory")

__device__ __forceinline__ void mma16816(float* d, const uint32_t* a,
                                         uint32_t b0, uint32_t b1) {
    asm volatile(
        "mma.sync.aligned.m16n8k16.row.col.f32.bf16.bf16.f32 "
        "{%0,%1,%2,%3}, {%4,%5,%6,%7}, {%8,%9}, {%0,%1,%2,%3};"
        : "+f"(d[0]), "+f"(d[1]), "+f"(d[2]), "+f"(d[3])
        : "r"(a[0]), "r"(a[1]), "r"(a[2]), "r"(a[3]), "r"(b0), "r"(b1));
}

__device__ __forceinline__ uint32_t lds32(uint32_t addr) {
    uint32_t v;
    asm volatile("ld.shared.b32 %0, [%1];" : "=r"(v) : "r"(addr));
    return v;
}

__device__ __forceinline__ uint32_t pack_bf2(float lo, float hi) {
    __nv_bfloat162 r = __floats2bfloat162_rn(lo, hi);   // x=lo (low 16b), y=hi
    return *(uint32_t*)&r;
}
__device__ __forceinline__ float2 unpack_bf2(uint32_t u) {
    __nv_bfloat162 h = *(__nv_bfloat162*)&u;
    return make_float2(__bfloat162float(h.x), __bfloat162float(h.y));
}

// ---------------------------------------------------------------------------
// Split-bf16 NT GEMM. CTA tile 128x64, 8 warps (4x2), warp tile 32x32.
// acc = 32 regs/thread -> <=85 regs -> 3 CTAs/SM (24 warps, was 16).
// epilogues:
//  0: split-bf16 out -> (outh,outl) [B,H,T,D] with *scale     (Q,K)
//  3: split-bf16 out -> (outh,outl) [B,H,D,T] transposed      (V)
//  1: fp32 out[m*CC+n]                                        (FC)
//  2: fp32 out[m*CC+n] * mask[m]                               (proj)
// QKV=1 instantiation: blockIdx.z in {0,1,2} selects Wq/Wk/Wv, bias, epi.
// ---------------------------------------------------------------------------
#define BKH 32
#define NST (KK/BKH)                 // 64
#define SRB 80                       // smem row stride bytes (40 halves)
#define A_TERM_B (128*SRB)           // 10240
#define B_TERM_B (64*SRB)            // 5120
#define STAGE_B (2*A_TERM_B + 2*B_TERM_B)  // 30720
#define GEMM_SMEM (2*STAGE_B)        // 61440

template <int QKV>
__global__ __launch_bounds__(256, 3) void gemm_mma_kernel(
    const __nv_bfloat16* __restrict__ Ah, const __nv_bfloat16* __restrict__ Al,
    const __nv_bfloat16* __restrict__ Bh, const __nv_bfloat16* __restrict__ Bl,
    const float* __restrict__ bias0, const float* __restrict__ bias1,
    const float* __restrict__ bias2, const float* __restrict__ mask,
    float* __restrict__ out,
    __nv_bfloat16* __restrict__ oh0, __nv_bfloat16* __restrict__ ol0,
    __nv_bfloat16* __restrict__ oh1, __nv_bfloat16* __restrict__ ol1,
    __nv_bfloat16* __restrict__ oh2, __nv_bfloat16* __restrict__ ol2,
    float scale0, int epi0)
{
    extern __shared__ char sm_[];
    const uint32_t sb = smem_u32(sm_);
    const int tid    = threadIdx.x;
    const int wid    = tid >> 5;
    const int lane   = tid & 31;
    const int warp_m = wid & 3;        // 4 m-blocks of 32 rows
    const int warp_n = wid >> 2;       // 2 n-blocks of 32 cols
    const int g      = lane >> 2;
    const int t      = lane & 3;
    const int m0 = blockIdx.y * 128;
    const int n0 = blockIdx.x * 64;

    // per-z selection (uniform across CTA; QKV=0 collapses at compile time)
    const int z = QKV ? blockIdx.z : 0;
    const float* bias = (z == 0) ? bias0 : (z == 1) ? bias1 : bias2;
    __nv_bfloat16* outh = (z == 0) ? oh0 : (z == 1) ? oh1 : oh2;
    __nv_bfloat16* outl = (z == 0) ? ol0 : (z == 1) ? ol1 : ol2;
    const float scale = (QKV && z != 0) ? 1.0f : scale0;
    const int epi     = (QKV) ? ((z == 2) ? 3 : 0) : epi0;
    const size_t woff = QKV ? (size_t)z * CC * CC : 0;

    const __nv_bfloat16* srcs[4] = { Ah + (size_t)m0*KK, Al + (size_t)m0*KK,
                                     Bh + woff + (size_t)n0*KK,
                                     Bl + woff + (size_t)n0*KK };

    float acc[2][4][4];
#pragma unroll
    for (int mt = 0; mt < 2; mt++)
#pragma unroll
        for (int nt = 0; nt < 4; nt++)
#pragma unroll
            for (int r = 0; r < 4; r++) acc[mt][nt][r] = 0.f;

    // stage loader: A 1024 chunks (2 tiles x 128 rows x 4), B 512 chunks
    // (2 tiles x 64 rows x 4) -> 1536 chunks / 256 thr = 6 per thread.
    auto LOAD_STAGE = [&](int s) {
        const int k0 = s * BKH;
        const uint32_t base = sb + (uint32_t)(s & 1) * STAGE_B;
#pragma unroll
        for (int i = 0; i < 6; i++) {
            const int cid = i*256 + tid;
            const int c   = cid & 3;
            uint32_t dst;
            const __nv_bfloat16* srcp;
            if (i < 4) {                       // A chunks (cid < 1024)
                const int tl  = cid >> 9;
                const int row = (cid & 511) >> 2;
                dst  = base + (uint32_t)tl*A_TERM_B + (uint32_t)row*SRB + (uint32_t)c*16;
                srcp = srcs[tl] + (size_t)row*KK + k0 + c*8;
            } else {                           // B chunks
                const int cid2 = cid - 1024;
                const int tl   = cid2 >> 8;
                const int row  = (cid2 & 255) >> 2;
                dst  = base + 2*A_TERM_B + (uint32_t)tl*B_TERM_B + (uint32_t)row*SRB + (uint32_t)c*16;
                srcp = srcs[2 + tl] + (size_t)row*KK + k0 + c*8;
            }
            CP_ASYNC_16(dst, srcp);
        }
        CP_ASYNC_COMMIT();
    };

    LOAD_STAGE(0);
    LOAD_STAGE(1);

    for (int s = 0; s < NST; s++) {
        CP_ASYNC_WAIT1();
        __syncthreads();

        const uint32_t base = sb + (uint32_t)(s & 1) * STAGE_B;
        const uint32_t pAh = base;
        const uint32_t pAl = base + A_TERM_B;
        const uint32_t pBh = base + 2*A_TERM_B;
        const uint32_t pBl = base + 2*A_TERM_B + B_TERM_B;

#pragma unroll
        for (int ks = 0; ks < 2; ks++) {
            const int kb = (ks * 16 + 2*t) * 2;
            uint32_t aH[2][4], aL[2][4];
#pragma unroll
            for (int mt = 0; mt < 2; mt++) {
                const int r = warp_m*32 + mt*16 + g;
                aH[mt][0] = lds32(pAh + r*SRB + kb);
                aH[mt][1] = lds32(pAh + (r+8)*SRB + kb);
                aH[mt][2] = lds32(pAh + r*SRB + kb + 16);
                aH[mt][3] = lds32(pAh + (r+8)*SRB + kb + 16);
                aL[mt][0] = lds32(pAl + r*SRB + kb);
                aL[mt][1] = lds32(pAl + (r+8)*SRB + kb);
                aL[mt][2] = lds32(pAl + r*SRB + kb + 16);
                aL[mt][3] = lds32(pAl + (r+8)*SRB + kb + 16);
            }
#pragma unroll
            for (int nt = 0; nt < 4; nt++) {
                const int n = warp_n*32 + nt*8 + g;
                uint32_t bh0 = lds32(pBh + n*SRB + kb);
                uint32_t bh1 = lds32(pBh + n*SRB + kb + 16);
                uint32_t bl0 = lds32(pBl + n*SRB + kb);
                uint32_t bl1 = lds32(pBl + n*SRB + kb + 16);
#pragma unroll
                for (int mt = 0; mt < 2; mt++) {
                    mma16816(acc[mt][nt], aH[mt], bh0, bh1);
                    mma16816(acc[mt][nt], aH[mt], bl0, bl1);
                    mma16816(acc[mt][nt], aL[mt], bh0, bh1);
                }
            }
        }
        __syncthreads();
        if (s + 2 < NST) LOAD_STAGE(s + 2);
        else             CP_ASYNC_COMMIT();
    }

#pragma unroll
    for (int mt = 0; mt < 2; mt++) {
#pragma unroll
        for (int nt = 0; nt < 4; nt++) {
            const float* d = acc[mt][nt];
            const int r0 = m0 + warp_m*32 + mt*16 + g;
            const int r1 = r0 + 8;
            const int n  = n0 + warp_n*32 + nt*8 + 2*t;
            const float2 b2 = *(const float2*)(bias + n);
            float v00 = d[0] + b2.x, v01 = d[1] + b2.y;
            float v10 = d[2] + b2.x, v11 = d[3] + b2.y;
            if (epi == 0 || epi == 3) {
                v00 *= scale; v01 *= scale; v10 *= scale; v11 *= scale;
                const int hh  = n >> 7;
                const int dd  = n & (DD - 1);
                const int b0i = r0 >> 11, t0i = r0 & (TT-1);
                const int b1i = r1 >> 11, t1i = r1 & (TT-1);
                __nv_bfloat16 h00 = __float2bfloat16(v00);
                __nv_bfloat16 h01 = __float2bfloat16(v01);
                __nv_bfloat16 h10 = __float2bfloat16(v10);
                __nv_bfloat16 h11 = __float2bfloat16(v11);
                __nv_bfloat16 l00 = __float2bfloat16(v00 - __bfloat162float(h00));
                __nv_bfloat16 l01 = __float2bfloat16(v01 - __bfloat162float(h01));
                __nv_bfloat16 l10 = __float2bfloat16(v10 - __bfloat162float(h10));
                __nv_bfloat16 l11 = __float2bfloat16(v11 - __bfloat162float(h11));
                if (epi == 0) {   // [B,H,T,D]
                    const size_t i0 = (((size_t)(b0i*HH + hh))*TT + t0i)*DD + dd;
                    const size_t i1 = (((size_t)(b1i*HH + hh))*TT + t1i)*DD + dd;
                    __nv_bfloat162 H0; H0.x = h00; H0.y = h01;
                    __nv_bfloat162 H1; H1.x = h10; H1.y = h11;
                    __nv_bfloat162 L0; L0.x = l00; L0.y = l01;
                    __nv_bfloat162 L1; L1.x = l10; L1.y = l11;
                    *(__nv_bfloat162*)(outh + i0) = H0;
                    *(__nv_bfloat162*)(outh + i1) = H1;
                    *(__nv_bfloat162*)(outl + i0) = L0;
                    *(__nv_bfloat162*)(outl + i1) = L1;
                } else {          // [B,H,D,T] transposed
                    const size_t c0 = (((size_t)(b0i*HH + hh))*DD + dd)*TT + t0i;
                    const size_t c1 = (((size_t)(b1i*HH + hh))*DD + dd)*TT + t1i;
                    outh[c0] = h00; outh[c0 + TT] = h01;
                    outh[c1] = h10; outh[c1 + TT] = h11;
                    outl[c0] = l00; outl[c0 + TT] = l01;
                    outl[c1] = l10; outl[c1 + TT] = l11;
                }
            } else if (epi == 1) {
                *(float2*)(out + (size_t)r0*CC + n) = make_float2(v00, v01);
                *(float2*)(out + (size_t)r1*CC + n) = make_float2(v10, v11);
            } else {
                const float mk0 = mask[r0], mk1 = mask[r1];
                *(float2*)(out + (size_t)r0*CC + n) = make_float2(v00*mk0, v01*mk0);
                *(float2*)(out + (size_t)r1*CC + n) = make_float2(v10*mk1, v11*mk1);
            }
        }
    }
}

// ---------------------------------------------------------------------------
// Fused split: x (2 regions) + 5 weights (contiguous in g_wh/g_wl).
// ---------------------------------------------------------------------------
__global__ __launch_bounds__(256) void split_all_kernel(
    const float* __restrict__ x,
    const float* __restrict__ w0, const float* __restrict__ w1,
    const float* __restrict__ w2, const float* __restrict__ w3,
    const float* __restrict__ w4,
    __nv_bfloat16* __restrict__ xh, __nv_bfloat16* __restrict__ xl,
    __nv_bfloat16* __restrict__ wh, __nv_bfloat16* __restrict__ wl)
{
    const int region = blockIdx.x >> 12;            // 4096 blocks per region
    const int bi     = blockIdx.x & 4095;
    const int i      = bi * 256 + threadIdx.x;      // float4 index within region

    const float* src;
    __nv_bfloat16 *hi, *lo;
    if (region < 2) {
        src = x + (size_t)region * (CC*CC);
        hi  = xh + (size_t)region * (CC*CC);
        lo  = xl + (size_t)region * (CC*CC);
    } else {
        const int w = region - 2;
        src = (w == 0) ? w0 : (w == 1) ? w1 : (w == 2) ? w2 : (w == 3) ? w3 : w4;
        hi  = wh + (size_t)w * (CC*CC);
        lo  = wl + (size_t)w * (CC*CC);
    }

    float4 v = ((const float4*)src)[i];
    float f[4] = {v.x, v.y, v.z, v.w};
    union U { __nv_bfloat16 b[4]; uint2 u; } H, L;
#pragma unroll
    for (int j = 0; j < 4; j++) {
        H.b[j] = __float2bfloat16(f[j]);
        L.b[j] = __float2bfloat16(f[j] - __bfloat162float(H.b[j]));
    }
    ((uint2*)hi)[i] = H.u;
    ((uint2*)lo)[i] = L.u;
}

// ---------------------------------------------------------------------------
// Causal flash attention on mma.sync, split-bf16 (unchanged, validated).
// ---------------------------------------------------------------------------
#define FQS 272
#define FVS 144
#define FQ_TILE (128*FQS)
#define FK_TILE (64*FQS)
#define FV_TILE (128*FVS)
#define FKV_STAGE (2*FK_TILE + 2*FV_TILE)
#define FLASH_SMEM (2*FQ_TILE + 2*FKV_STAGE)

__global__ __launch_bounds__(256) void flash_mma_kernel(
    const __nv_bfloat16* __restrict__ qh, const __nv_bfloat16* __restrict__ ql,
    const __nv_bfloat16* __restrict__ kh, const __nv_bfloat16* __restrict__ kl,
    const __nv_bfloat16* __restrict__ vh, const __nv_bfloat16* __restrict__ vl,
    __nv_bfloat16* __restrict__ AH, __nv_bfloat16* __restrict__ AL)
{
    extern __shared__ char sm_[];
    const uint32_t sb = smem_u32(sm_);
    const int tid  = threadIdx.x;
    const int wid  = tid >> 5;
    const int lane = tid & 31;
    const int g    = lane >> 2;
    const int t    = lane & 3;
    const int qt   = blockIdx.x;
    const int bh   = blockIdx.y;
    const int b    = bh >> 4;
    const int h    = bh & 15;

    const __nv_bfloat16* Qh = qh + (size_t)bh*TT*DD + (size_t)qt*128*DD;
    const __nv_bfloat16* Ql = ql + (size_t)bh*TT*DD + (size_t)qt*128*DD;
    const __nv_bfloat16* Kh = kh + (size_t)bh*TT*DD;
    const __nv_bfloat16* Kl = kl + (size_t)bh*TT*DD;
    const __nv_bfloat16* Vh = vh + (size_t)bh*DD*TT;
    const __nv_bfloat16* Vl = vl + (size_t)bh*DD*TT;

#pragma unroll
    for (int i = 0; i < 16; i++) {
        const int cid = i*256 + tid;
        const int tile = cid >> 11, rem = cid & 2047;
        const int row = rem >> 4, ch = rem & 15;
        const uint32_t dst = sb + (uint32_t)tile*FQ_TILE + (uint32_t)row*FQS + (uint32_t)ch*16;
        const __nv_bfloat16* src = (tile ? Ql : Qh) + (size_t)row*DD + ch*8;
        CP_ASYNC_16(dst, src);
    }
    auto LOAD_STAGE = [&](int s) {
        const uint32_t base = sb + 2*FQ_TILE + (uint32_t)(s & 1)*FKV_STAGE;
#pragma unroll
        for (int i = 0; i < 8; i++) {
            const int cid = i*256 + tid;
            const int tile = cid >> 10, rem = cid & 1023;
            const int row = rem >> 4, ch = rem & 15;
            const uint32_t dst = base + (uint32_t)tile*FK_TILE + (uint32_t)row*FQS + (uint32_t)ch*16;
            const __nv_bfloat16* src = (tile ? Kl : Kh) + (size_t)(s*64 + row)*DD + ch*8;
            CP_ASYNC_16(dst, src);
        }
#pragma unroll
        for (int i = 0; i < 8; i++) {
            const int cid = i*256 + tid;
            const int tile = cid >> 10, rem = cid & 1023;
            const int row = rem >> 3, ch = rem & 7;
            const uint32_t dst = base + 2*FK_TILE + (uint32_t)tile*FV_TILE
                               + (uint32_t)row*FVS + (uint32_t)ch*16;
            const __nv_bfloat16* src = (tile ? Vl : Vh) + (size_t)row*TT + s*64 + ch*8;
            CP_ASYNC_16(dst, src);
        }
        CP_ASYNC_COMMIT();
    };

    LOAD_STAGE(0);
    LOAD_STAGE(1);

    const int NT = 2*qt + 2;
    float mI[2] = {-1e30f, -1e30f};
    float lI[2] = {0.f, 0.f};
    float o[16][4];
#pragma unroll
    for (int nt = 0; nt < 16; nt++)
#pragma unroll
        for (int e = 0; e < 4; e++) o[nt][e] = 0.f;

    const int row0g = qt*128 + wid*16 + g;
    const int row1g = row0g + 8;

    for (int kt = 0; kt < NT; kt++) {
        CP_ASYNC_WAIT1();
        __syncthreads();
        const uint32_t base = sb + 2*FQ_TILE + (uint32_t)(kt & 1)*FKV_STAGE;
        const uint32_t pKh = base;
        const uint32_t pKl = base + FK_TILE;
        const uint32_t pVh = base + 2*FK_TILE;
        const uint32_t pVl = base + 2*FK_TILE + FV_TILE;

        const bool active = (kt*64 <= qt*128 + wid*16 + 15);
        if (active) {
            float s[8][4];
#pragma unroll
            for (int nt = 0; nt < 8; nt++)
#pragma unroll
                for (int e = 0; e < 4; e++) s[nt][e] = 0.f;

#pragma unroll
            for (int k8 = 0; k8 < 8; k8++) {
                const int kb = k8*32 + 4*t;
                const int rA = wid*16 + g;
                uint32_t aH[4], aL[4];
                aH[0] = lds32(sb + rA*FQS + kb);
                aH[1] = lds32(sb + (rA+8)*FQS + kb);
                aH[2] = lds32(sb + rA*FQS + kb + 16);
                aH[3] = lds32(sb + (rA+8)*FQS + kb + 16);
                aL[0] = lds32(sb + FQ_TILE + rA*FQS + kb);
                aL[1] = lds32(sb + FQ_TILE + (rA+8)*FQS + kb);
                aL[2] = lds32(sb + FQ_TILE + rA*FQS + kb + 16);
                aL[3] = lds32(sb + FQ_TILE + (rA+8)*FQS + kb + 16);
#pragma unroll
                for (int nt = 0; nt < 8; nt++) {
                    const int rB = nt*8 + g;
                    uint32_t kh0 = lds32(pKh + rB*FQS + kb);
                    uint32_t kh1 = lds32(pKh + rB*FQS + kb + 16);
                    uint32_t kl0 = lds32(pKl + rB*FQS + kb);
                    uint32_t kl1 = lds32(pKl + rB*FQS + kb + 16);
                    mma16816(s[nt], aH, kh0, kh1);
                    mma16816(s[nt], aH, kl0, kl1);
                    mma16816(s[nt], aL, kh0, kh1);
                }
            }

            if (kt >= 2*qt) {
#pragma unroll
                for (int nt = 0; nt < 8; nt++) {
                    const int c0 = kt*64 + nt*8 + 2*t;
                    const int c1 = c0 + 1;
                    if (c0 > row0g) s[nt][0] = -1e30f;
                    if (c1 > row0g) s[nt][1] = -1e30f;
                    if (c0 > row1g) s[nt][2] = -1e30f;
                    if (c1 > row1g) s[nt][3] = -1e30f;
                }
            }

            float mt0 = -1e30f, mt1 = -1e30f;
#pragma unroll
            for (int nt = 0; nt < 8; nt++) {
                mt0 = fmaxf(mt0, fmaxf(s[nt][0], s[nt][1]));
                mt1 = fmaxf(mt1, fmaxf(s[nt][2], s[nt][3]));
            }
            mt0 = fmaxf(mt0, __shfl_xor_sync(0xffffffffu, mt0, 1));
            mt0 = fmaxf(mt0, __shfl_xor_sync(0xffffffffu, mt0, 2));
            mt1 = fmaxf(mt1, __shfl_xor_sync(0xffffffffu, mt1, 1));
            mt1 = fmaxf(mt1, __shfl_xor_sync(0xffffffffu, mt1, 2));
            const float mn0 = fmaxf(mI[0], mt0);
            const float mn1 = fmaxf(mI[1], mt1);
            const float corr0 = __expf(mI[0] - mn0);
            const float corr1 = __expf(mI[1] - mn1);
            mI[0] = mn0; mI[1] = mn1;

            float rs0 = 0.f, rs1 = 0.f;
#pragma unroll
            for (int nt = 0; nt < 8; nt++) {
                s[nt][0] = __expf(s[nt][0] - mn0); rs0 += s[nt][0];
                s[nt][1] = __expf(s[nt][1] - mn0); rs0 += s[nt][1];
                s[nt][2] = __expf(s[nt][2] - mn1); rs1 += s[nt][2];
                s[nt][3] = __expf(s[nt][3] - mn1); rs1 += s[nt][3];
            }
            rs0 += __shfl_xor_sync(0xffffffffu, rs0, 1);
            rs0 += __shfl_xor_sync(0xffffffffu, rs0, 2);
            rs1 += __shfl_xor_sync(0xffffffffu, rs1, 1);
            rs1 += __shfl_xor_sync(0xffffffffu, rs1, 2);
            lI[0] = lI[0]*corr0 + rs0;
            lI[1] = lI[1]*corr1 + rs1;

#pragma unroll
            for (int nt = 0; nt < 16; nt++) {
                o[nt][0] *= corr0; o[nt][1] *= corr0;
                o[nt][2] *= corr1; o[nt][3] *= corr1;
            }

            uint32_t ph[4][4], pl[4][4];
#pragma unroll
            for (int k4 = 0; k4 < 4; k4++) {
                const int e0 = 2*k4, e1 = 2*k4 + 1;
                ph[k4][0] = pack_bf2(s[e0][0], s[e0][1]);
                ph[k4][1] = pack_bf2(s[e0][2], s[e0][3]);
                ph[k4][2] = pack_bf2(s[e1][0], s[e1][1]);
                ph[k4][3] = pack_bf2(s[e1][2], s[e1][3]);
                float2 u0 = unpack_bf2(ph[k4][0]);
                float2 u1 = unpack_bf2(ph[k4][1]);
                float2 u2 = unpack_bf2(ph[k4][2]);
                float2 u3 = unpack_bf2(ph[k4][3]);
                pl[k4][0] = pack_bf2(s[e0][0]-u0.x, s[e0][1]-u0.y);
                pl[k4][1] = pack_bf2(s[e0][2]-u1.x, s[e0][3]-u1.y);
                pl[k4][2] = pack_bf2(s[e1][0]-u2.x, s[e1][1]-u2.y);
                pl[k4][3] = pack_bf2(s[e1][2]-u3.x, s[e1][3]-u3.y);
            }

#pragma unroll
            for (int k4 = 0; k4 < 4; k4++) {
                const int kb2 = k4*32 + 4*t;
#pragma unroll
                for (int nt = 0; nt < 16; nt++) {
                    const int rB = nt*8 + g;
                    uint32_t vh0 = lds32(pVh + rB*FVS + kb2);
                    uint32_t vh1 = lds32(pVh + rB*FVS + kb2 + 16);
                    uint32_t vl0 = lds32(pVl + rB*FVS + kb2);
                    uint32_t vl1 = lds32(pVl + rB*FVS + kb2 + 16);
                    mma16816(o[nt], ph[k4], vh0, vh1);
                    mma16816(o[nt], ph[k4], vl0, vl1);
                    mma16816(o[nt], pl[k4], vh0, vh1);
                }
            }
        }
        __syncthreads();
        if (kt + 2 < NT) LOAD_STAGE(kt + 2);
        else             CP_ASYNC_COMMIT();
    }

    const float inv0 = 1.0f / lI[0];
    const float inv1 = 1.0f / lI[1];
    __nv_bfloat16* ah0 = AH + ((size_t)(b*TT + row0g))*CC + h*DD;
    __nv_bfloat16* ah1 = AH + ((size_t)(b*TT + row1g))*CC + h*DD;
    __nv_bfloat16* al0 = AL + ((size_t)(b*TT + row0g))*CC + h*DD;
    __nv_bfloat16* al1 = AL + ((size_t)(b*TT + row1g))*CC + h*DD;
#pragma unroll
    for (int nt = 0; nt < 16; nt++) {
        const int col = nt*8 + 2*t;
        float v00 = o[nt][0]*inv0, v01 = o[nt][1]*inv0;
        float v10 = o[nt][2]*inv1, v11 = o[nt][3]*inv1;
        uint32_t H0 = pack_bf2(v00, v01);
        uint32_t H1 = pack_bf2(v10, v11);
        float2 u0 = unpack_bf2(H0);
        float2 u1 = unpack_bf2(H1);
        uint32_t L0 = pack_bf2(v00 - u0.x, v01 - u0.y);
        uint32_t L1 = pack_bf2(v10 - u1.x, v11 - u1.y);
        *(uint32_t*)(ah0 + col) = H0;
        *(uint32_t*)(ah1 + col) = H1;
        *(uint32_t*)(al0 + col) = L0;
        *(uint32_t*)(al1 + col) = L1;
    }
}

// ---------------------------------------------------------------------------
// Fused LayerNorm(z)*g+b + residual.  SPLIT=1 also emits bf16 hi/lo of out.
// ---------------------------------------------------------------------------
template <int SPLIT>
__global__ __launch_bounds__(256) void ln_add_kernel(
    const float* __restrict__ z, const float* __restrict__ res,
    const float* __restrict__ gam, const float* __restrict__ bet,
    float* __restrict__ out, __nv_bfloat16* __restrict__ hi,
    __nv_bfloat16* __restrict__ lo)
{
    __shared__ float red[256];
    const int row = blockIdx.x;
    const int tid = threadIdx.x;
    const float* zr = z + (size_t)row * CC;

    float v[8];
#pragma unroll
    for (int i = 0; i < 2; i++) {
        float4 t4 = *(const float4*)(zr + i*1024 + tid*4);
        v[i*4+0] = t4.x; v[i*4+1] = t4.y; v[i*4+2] = t4.z; v[i*4+3] = t4.w;
    }

    float s = 0.f;
#pragma unroll
    for (int i = 0; i < 8; i++) s += v[i];
    red[tid] = s; __syncthreads();
#pragma unroll
    for (int off = 128; off; off >>= 1) {
        if (tid < off) red[tid] += red[tid + off];
        __syncthreads();
    }
    const float mean = red[0] * (1.0f / 2048.0f);
    __syncthreads();

    float vs = 0.f;
#pragma unroll
    for (int i = 0; i < 8; i++) { const float d = v[i] - mean; vs += d * d; }
    red[tid] = vs; __syncthreads();
#pragma unroll
    for (int off = 128; off; off >>= 1) {
        if (tid < off) red[tid] += red[tid + off];
        __syncthreads();
    }
    const float rstd = rsqrtf(red[0] * (1.0f / 2048.0f) + 1e-6f);

    const float* rr = res + (size_t)row * CC;
    float* orow = out + (size_t)row * CC;
#pragma unroll
    for (int i = 0; i < 2; i++) {
        const int c0 = i*1024 + tid*4;
        float4 g4 = *(const float4*)(gam + c0);
        float4 b4 = *(const float4*)(bet + c0);
        float4 r4 = *(const float4*)(rr + c0);
        float4 ov;
        ov.x = (v[i*4+0] - mean)*rstd*g4.x + b4.x + r4.x;
        ov.y = (v[i*4+1] - mean)*rstd*g4.y + b4.y + r4.y;
        ov.z = (v[i*4+2] - mean)*rstd*g4.z + b4.z + r4.z;
        ov.w = (v[i*4+3] - mean)*rstd*g4.w + b4.w + r4.w;
        *(float4*)(orow + c0) = ov;
        if (SPLIT) {
            float f[4] = {ov.x, ov.y, ov.z, ov.w};
            union U { __nv_bfloat16 b[4]; uint2 u; } H, L;
#pragma unroll
            for (int j = 0; j < 4; j++) {
                H.b[j] = __float2bfloat16(f[j]);
                L.b[j] = __float2bfloat16(f[j] - __bfloat162float(H.b[j]));
            }
            *(uint2*)(hi + (size_t)row*CC + c0) = H.u;
            *(uint2*)(lo + (size_t)row*CC + c0) = L.u;
        }
    }
}

// ---------------------------------------------------------------------------
extern "C" void kernel_launch(void* const* d_in, const int* in_sizes, int n_in,
                              void* d_out, int out_size)
{
    const float* x    = (const float*)d_in[0];
    const float* mask = (const float*)d_in[1];
    const float* Wq   = (const float*)d_in[2];
    const float* bq   = (const float*)d_in[3];
    const float* Wk   = (const float*)d_in[4];
    const float* bk   = (const float*)d_in[5];
    const float* Wv   = (const float*)d_in[6];
    const float* bv   = (const float*)d_in[7];
    const float* Wp   = (const float*)d_in[8];
    const float* bp   = (const float*)d_in[9];
    const float* Wfc  = (const float*)d_in[10];
    const float* bfc  = (const float*)d_in[11];
    const float* ln_g = (const float*)d_in[12];
    const float* ln_b = (const float*)d_in[13];

    float *t0, *t1;
    __nv_bfloat16 *qh, *ql, *kh, *kl, *vh, *vl, *xh, *xl, *ah, *al, *wh, *wl;
    cudaGetSymbolAddress((void**)&qh, g_qh);
    cudaGetSymbolAddress((void**)&ql, g_ql);
    cudaGetSymbolAddress((void**)&kh, g_kh);
    cudaGetSymbolAddress((void**)&kl, g_kl);
    cudaGetSymbolAddress((void**)&vh, g_vh);
    cudaGetSymbolAddress((void**)&vl, g_vl);
    cudaGetSymbolAddress((void**)&t0, g_t0);
    cudaGetSymbolAddress((void**)&t1, g_t1);
    cudaGetSymbolAddress((void**)&xh, g_xh);
    cudaGetSymbolAddress((void**)&xl, g_xl);
    cudaGetSymbolAddress((void**)&ah, g_ah);
    cudaGetSymbolAddress((void**)&al, g_al);
    cudaGetSymbolAddress((void**)&wh, g_wh);
    cudaGetSymbolAddress((void**)&wl, g_wl);

    cudaFuncSetAttribute(gemm_mma_kernel<1>,
                         cudaFuncAttributeMaxDynamicSharedMemorySize, GEMM_SMEM);
    cudaFuncSetAttribute(gemm_mma_kernel<0>,
                         cudaFuncAttributeMaxDynamicSharedMemorySize, GEMM_SMEM);
    cudaFuncSetAttribute(flash_mma_kernel,
                         cudaFuncAttributeMaxDynamicSharedMemorySize, FLASH_SMEM);

    const dim3 gg(CC/64, MM/128);           // (32, 32)
    const dim3 gqkv(CC/64, MM/128, 3);      // fused QKV

    // fused split: x (2 regions) + 5 weights (5 regions)
    split_all_kernel<<<7*4096, 256>>>(x, Wq, Wk, Wv, Wp, Wfc, xh, xl, wh, wl);

    // fused QKV projections -> split bf16; Q scaled; V transposed [B,H,D,T]
    gemm_mma_kernel<1><<<gqkv, 256, GEMM_SMEM>>>(
        xh, xl, wh, wl, bq, bk, bv, nullptr, nullptr,
        qh, ql, kh, kl, vh, vl, QSCALE, 0);

    // causal flash attention (tensorized) -> ah/al split bf16 directly
    flash_mma_kernel<<<dim3(TT/128, BB*HH), 256, FLASH_SMEM>>>(qh, ql, kh, kl, vh, vl, ah, al);

    // output projection (+bias, *mask) -> t0
    gemm_mma_kernel<0><<<gg, 256, GEMM_SMEM>>>(
        ah, al, wh + 3*(size_t)CC*CC, wl + 3*(size_t)CC*CC,
        bp, nullptr, nullptr, mask, t0,
        nullptr, nullptr, nullptr, nullptr, nullptr, nullptr, 1.0f, 2);

    // x1 = LN(t0) + x -> t1 (+ split to ah/al for FC GEMM)
    ln_add_kernel<1><<<MM, 256>>>(t0, x, ln_g, ln_b, t1, ah, al);

    // fc = x1 @ Wfc^T + bfc -> t0
    gemm_mma_kernel<0><<<gg, 256, GEMM_SMEM>>>(
        ah, al, wh + 4*(size_t)CC*CC, wl + 4*(size_t)CC*CC,
        bfc, nullptr, nullptr, nullptr, t0,
        nullptr, nullptr, nullptr, nullptr, nullptr, nullptr, 1.0f, 1);

    // out = LN(t0) + x1
    ln_add_kernel<0><<<MM, 256>>>(t0, t1, ln_g, ln_b, (float*)d_out, nullptr, nullptr);
}

// round 16
// speedup vs baseline: 5.1509x; 2.1661x over previous
#include <cuda_runtime.h>
#include <cuda_fp16.h>
#include <math.h>
#include <cstdint>

// Problem constants (fixed shapes)
#define BB 2
#define TT 2048
#define CC 2048
#define HH 16
#define DD 128
#define MM (BB*TT)          // 4096 rows
#define KK 2048
#define QSCALE 0.08838834764831845f  // 1/sqrt(128)

// ---------------- scratch (device globals; no allocation allowed) ----------
__device__ __half g_q[BB*HH*TT*DD];   // [B,H,T,D]
__device__ __half g_k[BB*HH*TT*DD];   // [B,H,T,D]
__device__ __half g_v[BB*HH*TT*DD];   // [B,H,D,T] (transposed)
__device__ float  g_t0[MM*CC];        // proj out / fc out
__device__ float  g_t1[MM*CC];        // x1
__device__ __half g_x[MM*CC];         // x fp16
__device__ __half g_a[MM*CC];         // flash out fp16, then x1 fp16
__device__ __half g_w[5*CC*CC];       // Wq,Wk,Wv,Wp,Wfc fp16

// ============================ helpers ======================================
__device__ __forceinline__ uint32_t smem_u32(const void* p) {
    uint32_t a;
    asm("{ .reg .u64 t; cvta.to.shared.u64 t, %1; cvt.u32.u64 %0, t; }" : "=r"(a) : "l"(p));
    return a;
}

#define CP_ASYNC_16(dst_u32, src_ptr) \
    asm volatile("cp.async.cg.shared.global [%0], [%1], 16;" :: "r"(dst_u32), "l"(src_ptr))
#define CP_ASYNC_COMMIT() asm volatile("cp.async.commit_group;" ::: "memory")
#define CP_ASYNC_WAIT1()  asm volatile("cp.async.wait_group 1;" ::: "memory")

__device__ __forceinline__ void mma16816h(float* d, const uint32_t* a,
                                          uint32_t b0, uint32_t b1) {
    asm volatile(
        "mma.sync.aligned.m16n8k16.row.col.f32.f16.f16.f32 "
        "{%0,%1,%2,%3}, {%4,%5,%6,%7}, {%8,%9}, {%0,%1,%2,%3};"
        : "+f"(d[0]), "+f"(d[1]), "+f"(d[2]), "+f"(d[3])
        : "r"(a[0]), "r"(a[1]), "r"(a[2]), "r"(a[3]), "r"(b0), "r"(b1));
}

__device__ __forceinline__ uint32_t lds32(uint32_t addr) {
    uint32_t v;
    asm volatile("ld.shared.b32 %0, [%1];" : "=r"(v) : "r"(addr));
    return v;
}

__device__ __forceinline__ uint32_t pack_h2(float lo, float hi) {
    __half2 r = __floats2half2_rn(lo, hi);   // x=lo (low 16b), y=hi
    return *(uint32_t*)&r;
}

// ---------------------------------------------------------------------------
// fp16 NT GEMM. CTA tile 128x64, 8 warps (4x2), warp tile 32x32.
// 1 MMA per (mt,nt,ks). epilogues:
//  0: fp16 out -> outX [B,H,T,D] with *scale     (Q,K)
//  3: fp16 out -> outX [B,H,D,T] transposed      (V)
//  1: fp32 out[m*CC+n]                            (FC)
//  2: fp32 out[m*CC+n] * mask[m]                  (proj)
// QKV=1: blockIdx.z in {0,1,2} selects weight slab, bias, epi.
// ---------------------------------------------------------------------------
#define BKH 32
#define NST (KK/BKH)                 // 64
#define SRB 80                       // smem row stride bytes (64B payload + pad)
#define A_TERM_B (128*SRB)           // 10240
#define B_TERM_B (64*SRB)            // 5120
#define STAGE_B (A_TERM_B + B_TERM_B)  // 15360
#define GEMM_SMEM (2*STAGE_B)        // 30720

template <int QKV>
__global__ __launch_bounds__(256, 3) void gemm_mma_kernel(
    const __half* __restrict__ A, const __half* __restrict__ B,
    const float* __restrict__ bias0, const float* __restrict__ bias1,
    const float* __restrict__ bias2, const float* __restrict__ mask,
    float* __restrict__ out,
    __half* __restrict__ oh0, __half* __restrict__ oh1, __half* __restrict__ oh2,
    float scale0, int epi0)
{
    extern __shared__ char sm_[];
    const uint32_t sb = smem_u32(sm_);
    const int tid    = threadIdx.x;
    const int wid    = tid >> 5;
    const int lane   = tid & 31;
    const int warp_m = wid & 3;        // 4 m-blocks of 32 rows
    const int warp_n = wid >> 2;       // 2 n-blocks of 32 cols
    const int g      = lane >> 2;
    const int t      = lane & 3;
    const int m0 = blockIdx.y * 128;
    const int n0 = blockIdx.x * 64;

    const int z = QKV ? blockIdx.z : 0;
    const float* bias = (z == 0) ? bias0 : (z == 1) ? bias1 : bias2;
    __half* outh = (z == 0) ? oh0 : (z == 1) ? oh1 : oh2;
    const float scale = (QKV && z != 0) ? 1.0f : scale0;
    const int epi     = (QKV) ? ((z == 2) ? 3 : 0) : epi0;
    const size_t woff = QKV ? (size_t)z * CC * CC : 0;

    const __half* srcA = A + (size_t)m0*KK;
    const __half* srcB = B + woff + (size_t)n0*KK;

    float acc[2][4][4];
#pragma unroll
    for (int mt = 0; mt < 2; mt++)
#pragma unroll
        for (int nt = 0; nt < 4; nt++)
#pragma unroll
            for (int r = 0; r < 4; r++) acc[mt][nt][r] = 0.f;

    // stage loader: A 512 chunks (128 rows x 4), B 256 chunks -> 3 per thread
    auto LOAD_STAGE = [&](int s) {
        const int k0 = s * BKH;
        const uint32_t base = sb + (uint32_t)(s & 1) * STAGE_B;
#pragma unroll
        for (int i = 0; i < 3; i++) {
            const int cid = i*256 + tid;
            const int c   = cid & 3;
            uint32_t dst;
            const __half* srcp;
            if (cid < 512) {                   // A chunks
                const int row = cid >> 2;
                dst  = base + (uint32_t)row*SRB + (uint32_t)c*16;
                srcp = srcA + (size_t)row*KK + k0 + c*8;
            } else {                           // B chunks
                const int row = (cid - 512) >> 2;
                dst  = base + A_TERM_B + (uint32_t)row*SRB + (uint32_t)c*16;
                srcp = srcB + (size_t)row*KK + k0 + c*8;
            }
            CP_ASYNC_16(dst, srcp);
        }
        CP_ASYNC_COMMIT();
    };

    LOAD_STAGE(0);
    LOAD_STAGE(1);

    for (int s = 0; s < NST; s++) {
        CP_ASYNC_WAIT1();
        __syncthreads();

        const uint32_t base = sb + (uint32_t)(s & 1) * STAGE_B;
        const uint32_t pA = base;
        const uint32_t pB = base + A_TERM_B;

#pragma unroll
        for (int ks = 0; ks < 2; ks++) {
            const int kb = (ks * 16 + 2*t) * 2;
            uint32_t aF[2][4];
#pragma unroll
            for (int mt = 0; mt < 2; mt++) {
                const int r = warp_m*32 + mt*16 + g;
                aF[mt][0] = lds32(pA + r*SRB + kb);
                aF[mt][1] = lds32(pA + (r+8)*SRB + kb);
                aF[mt][2] = lds32(pA + r*SRB + kb + 16);
                aF[mt][3] = lds32(pA + (r+8)*SRB + kb + 16);
            }
#pragma unroll
            for (int nt = 0; nt < 4; nt++) {
                const int n = warp_n*32 + nt*8 + g;
                uint32_t b0 = lds32(pB + n*SRB + kb);
                uint32_t b1 = lds32(pB + n*SRB + kb + 16);
#pragma unroll
                for (int mt = 0; mt < 2; mt++)
                    mma16816h(acc[mt][nt], aF[mt], b0, b1);
            }
        }
        __syncthreads();
        if (s + 2 < NST) LOAD_STAGE(s + 2);
        else             CP_ASYNC_COMMIT();
    }

#pragma unroll
    for (int mt = 0; mt < 2; mt++) {
#pragma unroll
        for (int nt = 0; nt < 4; nt++) {
            const float* d = acc[mt][nt];
            const int r0 = m0 + warp_m*32 + mt*16 + g;
            const int r1 = r0 + 8;
            const int n  = n0 + warp_n*32 + nt*8 + 2*t;
            const float2 b2 = *(const float2*)(bias + n);
            float v00 = d[0] + b2.x, v01 = d[1] + b2.y;
            float v10 = d[2] + b2.x, v11 = d[3] + b2.y;
            if (epi == 0 || epi == 3) {
                v00 *= scale; v01 *= scale; v10 *= scale; v11 *= scale;
                const int hh  = n >> 7;
                const int dd  = n & (DD - 1);
                const int b0i = r0 >> 11, t0i = r0 & (TT-1);
                const int b1i = r1 >> 11, t1i = r1 & (TT-1);
                if (epi == 0) {   // [B,H,T,D]
                    const size_t i0 = (((size_t)(b0i*HH + hh))*TT + t0i)*DD + dd;
                    const size_t i1 = (((size_t)(b1i*HH + hh))*TT + t1i)*DD + dd;
                    *(__half2*)(outh + i0) = __floats2half2_rn(v00, v01);
                    *(__half2*)(outh + i1) = __floats2half2_rn(v10, v11);
                } else {          // [B,H,D,T] transposed
                    const size_t c0 = (((size_t)(b0i*HH + hh))*DD + dd)*TT + t0i;
                    const size_t c1 = (((size_t)(b1i*HH + hh))*DD + dd)*TT + t1i;
                    outh[c0] = __float2half_rn(v00); outh[c0 + TT] = __float2half_rn(v01);
                    outh[c1] = __float2half_rn(v10); outh[c1 + TT] = __float2half_rn(v11);
                }
            } else if (epi == 1) {
                *(float2*)(out + (size_t)r0*CC + n) = make_float2(v00, v01);
                *(float2*)(out + (size_t)r1*CC + n) = make_float2(v10, v11);
            } else {
                const float mk0 = mask[r0], mk1 = mask[r1];
                *(float2*)(out + (size_t)r0*CC + n) = make_float2(v00*mk0, v01*mk0);
                *(float2*)(out + (size_t)r1*CC + n) = make_float2(v10*mk1, v11*mk1);
            }
        }
    }
}

// ---------------------------------------------------------------------------
// Fused convert fp32 -> fp16: x (2 regions) + 5 weights (contiguous in g_w).
// ---------------------------------------------------------------------------
__global__ __launch_bounds__(256) void cvt_all_kernel(
    const float* __restrict__ x,
    const float* __restrict__ w0, const float* __restrict__ w1,
    const float* __restrict__ w2, const float* __restrict__ w3,
    const float* __restrict__ w4,
    __half* __restrict__ xo, __half* __restrict__ wo)
{
    const int region = blockIdx.x >> 12;            // 4096 blocks per region
    const int bi     = blockIdx.x & 4095;
    const int i      = bi * 256 + threadIdx.x;      // float4 index within region

    const float* src;
    __half* dst;
    if (region < 2) {
        src = x  + (size_t)region * (CC*CC);
        dst = xo + (size_t)region * (CC*CC);
    } else {
        const int w = region - 2;
        src = (w == 0) ? w0 : (w == 1) ? w1 : (w == 2) ? w2 : (w == 3) ? w3 : w4;
        dst = wo + (size_t)w * (CC*CC);
    }

    float4 v = ((const float4*)src)[i];
    union U { __half h[4]; uint2 u; } O;
    O.h[0] = __float2half_rn(v.x); O.h[1] = __float2half_rn(v.y);
    O.h[2] = __float2half_rn(v.z); O.h[3] = __float2half_rn(v.w);
    ((uint2*)dst)[i] = O.u;
}

// ---------------------------------------------------------------------------
// Causal flash attention on mma.sync, fp16 single. Br=128, Bc=64, 8 warps.
// Q resident; K/V double-buffered cp.async. P packed to fp16 in registers.
// ---------------------------------------------------------------------------
#define FQS 272                      // Q/K smem row stride bytes
#define FVS 144                      // V^T smem row stride bytes
#define FQ_TILE (128*FQS)            // 34816
#define FK_TILE (64*FQS)             // 17408
#define FV_TILE (128*FVS)            // 18432
#define FKV_STAGE (FK_TILE + FV_TILE)       // 35840
#define FLASH_SMEM (FQ_TILE + 2*FKV_STAGE)  // 106496

__global__ __launch_bounds__(256) void flash_mma_kernel(
    const __half* __restrict__ q, const __half* __restrict__ k,
    const __half* __restrict__ v, __half* __restrict__ AH)
{
    extern __shared__ char sm_[];
    const uint32_t sb = smem_u32(sm_);
    const int tid  = threadIdx.x;
    const int wid  = tid >> 5;
    const int lane = tid & 31;
    const int g    = lane >> 2;
    const int t    = lane & 3;
    const int qt   = blockIdx.x;
    const int bh   = blockIdx.y;
    const int b    = bh >> 4;
    const int h    = bh & 15;

    const __half* Q = q + (size_t)bh*TT*DD + (size_t)qt*128*DD;
    const __half* K = k + (size_t)bh*TT*DD;
    const __half* V = v + (size_t)bh*DD*TT;   // [d][t]

    // Q tile: 128 rows x 16 chunks = 2048 chunks / 256 thr = 8 each
#pragma unroll
    for (int i = 0; i < 8; i++) {
        const int cid = i*256 + tid;
        const int row = cid >> 4, ch = cid & 15;
        CP_ASYNC_16(sb + (uint32_t)row*FQS + (uint32_t)ch*16,
                    Q + (size_t)row*DD + ch*8);
    }
    auto LOAD_STAGE = [&](int s) {
        const uint32_t base = sb + FQ_TILE + (uint32_t)(s & 1)*FKV_STAGE;
#pragma unroll
        for (int i = 0; i < 4; i++) {      // K: 64 rows x 16 chunks
            const int cid = i*256 + tid;
            const int row = cid >> 4, ch = cid & 15;
            CP_ASYNC_16(base + (uint32_t)row*FQS + (uint32_t)ch*16,
                        K + (size_t)(s*64 + row)*DD + ch*8);
        }
#pragma unroll
        for (int i = 0; i < 4; i++) {      // V: 128 rows x 8 chunks
            const int cid = i*256 + tid;
            const int row = cid >> 3, ch = cid & 7;
            CP_ASYNC_16(base + FK_TILE + (uint32_t)row*FVS + (uint32_t)ch*16,
                        V + (size_t)row*TT + s*64 + ch*8);
        }
        CP_ASYNC_COMMIT();
    };

    LOAD_STAGE(0);   // Q cps join stage-0's group
    LOAD_STAGE(1);

    const int NT = 2*qt + 2;
    float mI[2] = {-1e30f, -1e30f};
    float lI[2] = {0.f, 0.f};
    float o[16][4];
#pragma unroll
    for (int nt = 0; nt < 16; nt++)
#pragma unroll
        for (int e = 0; e < 4; e++) o[nt][e] = 0.f;

    const int row0g = qt*128 + wid*16 + g;
    const int row1g = row0g + 8;

    for (int kt = 0; kt < NT; kt++) {
        CP_ASYNC_WAIT1();
        __syncthreads();
        const uint32_t base = sb + FQ_TILE + (uint32_t)(kt & 1)*FKV_STAGE;
        const uint32_t pK = base;
        const uint32_t pV = base + FK_TILE;

        const bool active = (kt*64 <= qt*128 + wid*16 + 15);
        if (active) {
            float s[8][4];
#pragma unroll
            for (int nt = 0; nt < 8; nt++)
#pragma unroll
                for (int e = 0; e < 4; e++) s[nt][e] = 0.f;

#pragma unroll
            for (int k8 = 0; k8 < 8; k8++) {
                const int kb = k8*32 + 4*t;
                const int rA = wid*16 + g;
                uint32_t aF[4];
                aF[0] = lds32(sb + rA*FQS + kb);
                aF[1] = lds32(sb + (rA+8)*FQS + kb);
                aF[2] = lds32(sb + rA*FQS + kb + 16);
                aF[3] = lds32(sb + (rA+8)*FQS + kb + 16);
#pragma unroll
                for (int nt = 0; nt < 8; nt++) {
                    const int rB = nt*8 + g;
                    uint32_t k0 = lds32(pK + rB*FQS + kb);
                    uint32_t k1 = lds32(pK + rB*FQS + kb + 16);
                    mma16816h(s[nt], aF, k0, k1);
                }
            }

            if (kt >= 2*qt) {
#pragma unroll
                for (int nt = 0; nt < 8; nt++) {
                    const int c0 = kt*64 + nt*8 + 2*t;
                    const int c1 = c0 + 1;
                    if (c0 > row0g) s[nt][0] = -1e30f;
                    if (c1 > row0g) s[nt][1] = -1e30f;
                    if (c0 > row1g) s[nt][2] = -1e30f;
                    if (c1 > row1g) s[nt][3] = -1e30f;
                }
            }

            float mt0 = -1e30f, mt1 = -1e30f;
#pragma unroll
            for (int nt = 0; nt < 8; nt++) {
                mt0 = fmaxf(mt0, fmaxf(s[nt][0], s[nt][1]));
                mt1 = fmaxf(mt1, fmaxf(s[nt][2], s[nt][3]));
            }
            mt0 = fmaxf(mt0, __shfl_xor_sync(0xffffffffu, mt0, 1));
            mt0 = fmaxf(mt0, __shfl_xor_sync(0xffffffffu, mt0, 2));
            mt1 = fmaxf(mt1, __shfl_xor_sync(0xffffffffu, mt1, 1));
            mt1 = fmaxf(mt1, __shfl_xor_sync(0xffffffffu, mt1, 2));
            const float mn0 = fmaxf(mI[0], mt0);
            const float mn1 = fmaxf(mI[1], mt1);
            const float corr0 = __expf(mI[0] - mn0);
            const float corr1 = __expf(mI[1] - mn1);
            mI[0] = mn0; mI[1] = mn1;

            float rs0 = 0.f, rs1 = 0.f;
#pragma unroll
            for (int nt = 0; nt < 8; nt++) {
                s[nt][0] = __expf(s[nt][0] - mn0); rs0 += s[nt][0];
                s[nt][1] = __expf(s[nt][1] - mn0); rs0 += s[nt][1];
                s[nt][2] = __expf(s[nt][2] - mn1); rs1 += s[nt][2];
                s[nt][3] = __expf(s[nt][3] - mn1); rs1 += s[nt][3];
            }
            rs0 += __shfl_xor_sync(0xffffffffu, rs0, 1);
            rs0 += __shfl_xor_sync(0xffffffffu, rs0, 2);
            rs1 += __shfl_xor_sync(0xffffffffu, rs1, 1);
            rs1 += __shfl_xor_sync(0xffffffffu, rs1, 2);
            lI[0] = lI[0]*corr0 + rs0;
            lI[1] = lI[1]*corr1 + rs1;

#pragma unroll
            for (int nt = 0; nt < 16; nt++) {
                o[nt][0] *= corr0; o[nt][1] *= corr0;
                o[nt][2] *= corr1; o[nt][3] *= corr1;
            }

            // pack P frags (A-layout) fp16
            uint32_t ph[4][4];
#pragma unroll
            for (int k4 = 0; k4 < 4; k4++) {
                const int e0 = 2*k4, e1 = 2*k4 + 1;
                ph[k4][0] = pack_h2(s[e0][0], s[e0][1]);
                ph[k4][1] = pack_h2(s[e0][2], s[e0][3]);
                ph[k4][2] = pack_h2(s[e1][0], s[e1][1]);
                ph[k4][3] = pack_h2(s[e1][2], s[e1][3]);
            }

            // O += P V.  B operand: V^T smem [d][s]
#pragma unroll
            for (int k4 = 0; k4 < 4; k4++) {
                const int kb2 = k4*32 + 4*t;
#pragma unroll
                for (int nt = 0; nt < 16; nt++) {
                    const int rB = nt*8 + g;
                    uint32_t v0 = lds32(pV + rB*FVS + kb2);
                    uint32_t v1 = lds32(pV + rB*FVS + kb2 + 16);
                    mma16816h(o[nt], ph[k4], v0, v1);
                }
            }
        }
        __syncthreads();
        if (kt + 2 < NT) LOAD_STAGE(kt + 2);
        else             CP_ASYNC_COMMIT();
    }

    // epilogue: write fp16 directly (feeds proj GEMM)
    const float inv0 = 1.0f / lI[0];
    const float inv1 = 1.0f / lI[1];
    __half* a0 = AH + ((size_t)(b*TT + row0g))*CC + h*DD;
    __half* a1 = AH + ((size_t)(b*TT + row1g))*CC + h*DD;
#pragma unroll
    for (int nt = 0; nt < 16; nt++) {
        const int col = nt*8 + 2*t;
        *(__half2*)(a0 + col) = __floats2half2_rn(o[nt][0]*inv0, o[nt][1]*inv0);
        *(__half2*)(a1 + col) = __floats2half2_rn(o[nt][2]*inv1, o[nt][3]*inv1);
    }
}

// ---------------------------------------------------------------------------
// Fused LayerNorm(z)*g+b + residual.  CVT=1 also emits fp16 of out.
// ---------------------------------------------------------------------------
template <int CVT>
__global__ __launch_bounds__(256) void ln_add_kernel(
    const float* __restrict__ z, const float* __restrict__ res,
    const float* __restrict__ gam, const float* __restrict__ bet,
    float* __restrict__ out, __half* __restrict__ ho)
{
    __shared__ float red[256];
    const int row = blockIdx.x;
    const int tid = threadIdx.x;
    const float* zr = z + (size_t)row * CC;

    float v[8];
#pragma unroll
    for (int i = 0; i < 2; i++) {
        float4 t4 = *(const float4*)(zr + i*1024 + tid*4);
        v[i*4+0] = t4.x; v[i*4+1] = t4.y; v[i*4+2] = t4.z; v[i*4+3] = t4.w;
    }

    float s = 0.f;
#pragma unroll
    for (int i = 0; i < 8; i++) s += v[i];
    red[tid] = s; __syncthreads();
#pragma unroll
    for (int off = 128; off; off >>= 1) {
        if (tid < off) red[tid] += red[tid + off];
        __syncthreads();
    }
    const float mean = red[0] * (1.0f / 2048.0f);
    __syncthreads();

    float vs = 0.f;
#pragma unroll
    for (int i = 0; i < 8; i++) { const float d = v[i] - mean; vs += d * d; }
    red[tid] = vs; __syncthreads();
#pragma unroll
    for (int off = 128; off; off >>= 1) {
        if (tid < off) red[tid] += red[tid + off];
        __syncthreads();
    }
    const float rstd = rsqrtf(red[0] * (1.0f / 2048.0f) + 1e-6f);

    const float* rr = res + (size_t)row * CC;
    float* orow = out + (size_t)row * CC;
#pragma unroll
    for (int i = 0; i < 2; i++) {
        const int c0 = i*1024 + tid*4;
        float4 g4 = *(const float4*)(gam + c0);
        float4 b4 = *(const float4*)(bet + c0);
        float4 r4 = *(const float4*)(rr + c0);
        float4 ov;
        ov.x = (v[i*4+0] - mean)*rstd*g4.x + b4.x + r4.x;
        ov.y = (v[i*4+1] - mean)*rstd*g4.y + b4.y + r4.y;
        ov.z = (v[i*4+2] - mean)*rstd*g4.z + b4.z + r4.z;
        ov.w = (v[i*4+3] - mean)*rstd*g4.w + b4.w + r4.w;
        *(float4*)(orow + c0) = ov;
        if (CVT) {
            union U { __half h[4]; uint2 u; } O;
            O.h[0] = __float2half_rn(ov.x); O.h[1] = __float2half_rn(ov.y);
            O.h[2] = __float2half_rn(ov.z); O.h[3] = __float2half_rn(ov.w);
            *(uint2*)(ho + (size_t)row*CC + c0) = O.u;
        }
    }
}

// ---------------------------------------------------------------------------
extern "C" void kernel_launch(void* const* d_in, const int* in_sizes, int n_in,
                              void* d_out, int out_size)
{
    const float* x    = (const float*)d_in[0];
    const float* mask = (const float*)d_in[1];
    const float* Wq   = (const float*)d_in[2];
    const float* bq   = (const float*)d_in[3];
    const float* Wk   = (const float*)d_in[4];
    const float* bk   = (const float*)d_in[5];
    const float* Wv   = (const float*)d_in[6];
    const float* bv   = (const float*)d_in[7];
    const float* Wp   = (const float*)d_in[8];
    const float* bp   = (const float*)d_in[9];
    const float* Wfc  = (const float*)d_in[10];
    const float* bfc  = (const float*)d_in[11];
    const float* ln_g = (const float*)d_in[12];
    const float* ln_b = (const float*)d_in[13];

    float *t0, *t1;
    __half *q, *k, *v, *xo, *a, *w;
    cudaGetSymbolAddress((void**)&q,  g_q);
    cudaGetSymbolAddress((void**)&k,  g_k);
    cudaGetSymbolAddress((void**)&v,  g_v);
    cudaGetSymbolAddress((void**)&t0, g_t0);
    cudaGetSymbolAddress((void**)&t1, g_t1);
    cudaGetSymbolAddress((void**)&xo, g_x);
    cudaGetSymbolAddress((void**)&a,  g_a);
    cudaGetSymbolAddress((void**)&w,  g_w);

    cudaFuncSetAttribute(gemm_mma_kernel<1>,
                         cudaFuncAttributeMaxDynamicSharedMemorySize, GEMM_SMEM);
    cudaFuncSetAttribute(gemm_mma_kernel<0>,
                         cudaFuncAttributeMaxDynamicSharedMemorySize, GEMM_SMEM);
    cudaFuncSetAttribute(flash_mma_kernel,
                         cudaFuncAttributeMaxDynamicSharedMemorySize, FLASH_SMEM);

    const dim3 gg(CC/64, MM/128);           // (32, 32)
    const dim3 gqkv(CC/64, MM/128, 3);      // fused QKV

    // fused convert: x (2 regions) + 5 weights (5 regions)
    cvt_all_kernel<<<7*4096, 256>>>(x, Wq, Wk, Wv, Wp, Wfc, xo, w);

    // fused QKV projections -> fp16; Q scaled; V transposed [B,H,D,T]
    gemm_mma_kernel<1><<<gqkv, 256, GEMM_SMEM>>>(
        xo, w, bq, bk, bv, nullptr, nullptr, q, k, v, QSCALE, 0);

    // causal flash attention (fp16) -> a
    flash_mma_kernel<<<dim3(TT/128, BB*HH), 256, FLASH_SMEM>>>(q, k, v, a);

    // output projection (+bias, *mask) -> t0
    gemm_mma_kernel<0><<<gg, 256, GEMM_SMEM>>>(
        a, w + 3*(size_t)CC*CC, bp, nullptr, nullptr, mask, t0,
        nullptr, nullptr, nullptr, 1.0f, 2);

    // x1 = LN(t0) + x -> t1 (+ fp16 to a for FC GEMM)
    ln_add_kernel<1><<<MM, 256>>>(t0, x, ln_g, ln_b, t1, a);

    // fc = x1 @ Wfc^T + bfc -> t0
    gemm_mma_kernel<0><<<gg, 256, GEMM_SMEM>>>(
        a, w + 4*(size_t)CC*CC, bfc, nullptr, nullptr, nullptr, t0,
        nullptr, nullptr, nullptr, 1.0f, 1);

    // out = LN(t0) + x1
    ln_add_kernel<0><<<MM, 256>>>(t0, t1, ln_g, ln_b, (float*)d_out, nullptr);
}

// round 17
// speedup vs baseline: 6.3387x; 1.2306x over previous
#include <cuda_runtime.h>
#include <cuda_fp16.h>
#include <math.h>
#include <cstdint>

// Problem constants (fixed shapes)
#define BB 2
#define TT 2048
#define CC 2048
#define HH 16
#define DD 128
#define MM (BB*TT)          // 4096 rows
#define KK 2048
#define QSCALE 0.08838834764831845f  // 1/sqrt(128)

// ---------------- scratch (device globals; no allocation allowed) ----------
__device__ __half g_q[BB*HH*TT*DD];   // [B,H,T,D]
__device__ __half g_k[BB*HH*TT*DD];   // [B,H,T,D]
__device__ __half g_v[BB*HH*TT*DD];   // [B,H,D,T] (transposed)
__device__ float  g_t0[MM*CC];        // proj out / fc out
__device__ float  g_t1[MM*CC];        // x1
__device__ __half g_x[MM*CC];         // x fp16
__device__ __half g_a[MM*CC];         // flash out fp16, then x1 fp16
__device__ __half g_w[5*CC*CC];       // Wq,Wk,Wv,Wp,Wfc fp16

// ============================ helpers ======================================
__device__ __forceinline__ uint32_t smem_u32(const void* p) {
    uint32_t a;
    asm("{ .reg .u64 t; cvta.to.shared.u64 t, %1; cvt.u32.u64 %0, t; }" : "=r"(a) : "l"(p));
    return a;
}

#define CP_ASYNC_16(dst_u32, src_ptr) \
    asm volatile("cp.async.cg.shared.global [%0], [%1], 16;" :: "r"(dst_u32), "l"(src_ptr))
#define CP_ASYNC_COMMIT() asm volatile("cp.async.commit_group;" ::: "memory")
#define CP_ASYNC_WAIT1()  asm volatile("cp.async.wait_group 1;" ::: "memory")

__device__ __forceinline__ void mma16816h(float* d, const uint32_t* a,
                                          uint32_t b0, uint32_t b1) {
    asm volatile(
        "mma.sync.aligned.m16n8k16.row.col.f32.f16.f16.f32 "
        "{%0,%1,%2,%3}, {%4,%5,%6,%7}, {%8,%9}, {%0,%1,%2,%3};"
        : "+f"(d[0]), "+f"(d[1]), "+f"(d[2]), "+f"(d[3])
        : "r"(a[0]), "r"(a[1]), "r"(a[2]), "r"(a[3]), "r"(b0), "r"(b1));
}

__device__ __forceinline__ uint32_t lds32(uint32_t addr) {
    uint32_t v;
    asm volatile("ld.shared.b32 %0, [%1];" : "=r"(v) : "r"(addr));
    return v;
}

__device__ __forceinline__ uint32_t pack_h2(float lo, float hi) {
    __half2 r = __floats2half2_rn(lo, hi);   // x=lo (low 16b), y=hi
    return *(uint32_t*)&r;
}

// ---------------------------------------------------------------------------
// fp16 NT GEMM. CTA tile 128x128, 8 warps (4x2), warp tile 32x64 (R12 shape).
// BKH=64 (32 stages). epilogues:
//  0: fp16 out -> outX [B,H,T,D] with *scale     (Q,K)
//  3: fp16 out -> outX [B,H,D,T] transposed      (V)
//  1: fp32 out[m*CC+n]                            (FC)
//  2: fp32 out[m*CC+n] * mask[m]                  (proj)
// QKV=1: blockIdx.z in {0,1,2} selects weight slab, bias, epi.
// ---------------------------------------------------------------------------
#define BKH 64
#define NST (KK/BKH)                 // 32
#define SRB 144                      // smem row stride bytes (128B payload + pad)
#define A_TERM_B (128*SRB)           // 18432
#define STAGE_B (2*A_TERM_B)         // 36864 (A + B, 128 rows each)
#define GEMM_SMEM (2*STAGE_B)        // 73728

template <int QKV>
__global__ __launch_bounds__(256, 2) void gemm_mma_kernel(
    const __half* __restrict__ A, const __half* __restrict__ B,
    const float* __restrict__ bias0, const float* __restrict__ bias1,
    const float* __restrict__ bias2, const float* __restrict__ mask,
    float* __restrict__ out,
    __half* __restrict__ oh0, __half* __restrict__ oh1, __half* __restrict__ oh2,
    float scale0, int epi0)
{
    extern __shared__ char sm_[];
    const uint32_t sb = smem_u32(sm_);
    const int tid    = threadIdx.x;
    const int wid    = tid >> 5;
    const int lane   = tid & 31;
    const int warp_m = wid & 3;        // 4 m-blocks of 32 rows
    const int warp_n = wid >> 2;       // 2 n-blocks of 64 cols
    const int g      = lane >> 2;
    const int t      = lane & 3;
    const int m0 = blockIdx.y * 128;
    const int n0 = blockIdx.x * 128;

    const int z = QKV ? blockIdx.z : 0;
    const float* bias = (z == 0) ? bias0 : (z == 1) ? bias1 : bias2;
    __half* outh = (z == 0) ? oh0 : (z == 1) ? oh1 : oh2;
    const float scale = (QKV && z != 0) ? 1.0f : scale0;
    const int epi     = (QKV) ? ((z == 2) ? 3 : 0) : epi0;
    const size_t woff = QKV ? (size_t)z * CC * CC : 0;

    const __half* srcA = A + (size_t)m0*KK;
    const __half* srcB = B + woff + (size_t)n0*KK;

    float acc[2][8][4];
#pragma unroll
    for (int mt = 0; mt < 2; mt++)
#pragma unroll
        for (int nt = 0; nt < 8; nt++)
#pragma unroll
            for (int r = 0; r < 4; r++) acc[mt][nt][r] = 0.f;

    // stage loader: A 1024 chunks (128 rows x 8x16B), B 1024 -> 8 per thread
    auto LOAD_STAGE = [&](int s) {
        const int k0 = s * BKH;
        const uint32_t base = sb + (uint32_t)(s & 1) * STAGE_B;
#pragma unroll
        for (int i = 0; i < 8; i++) {
            const int cid = i*256 + tid;
            uint32_t dst;
            const __half* srcp;
            if (cid < 1024) {                  // A chunks
                const int row = cid >> 3, c = cid & 7;
                dst  = base + (uint32_t)row*SRB + (uint32_t)c*16;
                srcp = srcA + (size_t)row*KK + k0 + c*8;
            } else {                           // B chunks
                const int cid2 = cid - 1024;
                const int row = cid2 >> 3, c = cid2 & 7;
                dst  = base + A_TERM_B + (uint32_t)row*SRB + (uint32_t)c*16;
                srcp = srcB + (size_t)row*KK + k0 + c*8;
            }
            CP_ASYNC_16(dst, srcp);
        }
        CP_ASYNC_COMMIT();
    };

    LOAD_STAGE(0);
    LOAD_STAGE(1);

    for (int s = 0; s < NST; s++) {
        CP_ASYNC_WAIT1();
        __syncthreads();

        const uint32_t base = sb + (uint32_t)(s & 1) * STAGE_B;
        const uint32_t pA = base;
        const uint32_t pB = base + A_TERM_B;

#pragma unroll
        for (int ks = 0; ks < 4; ks++) {
            const int kb = (ks * 16 + 2*t) * 2;
            uint32_t aF[2][4];
#pragma unroll
            for (int mt = 0; mt < 2; mt++) {
                const int r = warp_m*32 + mt*16 + g;
                aF[mt][0] = lds32(pA + r*SRB + kb);
                aF[mt][1] = lds32(pA + (r+8)*SRB + kb);
                aF[mt][2] = lds32(pA + r*SRB + kb + 16);
                aF[mt][3] = lds32(pA + (r+8)*SRB + kb + 16);
            }
#pragma unroll
            for (int nt = 0; nt < 8; nt++) {
                const int n = warp_n*64 + nt*8 + g;
                uint32_t b0 = lds32(pB + n*SRB + kb);
                uint32_t b1 = lds32(pB + n*SRB + kb + 16);
#pragma unroll
                for (int mt = 0; mt < 2; mt++)
                    mma16816h(acc[mt][nt], aF[mt], b0, b1);
            }
        }
        __syncthreads();
        if (s + 2 < NST) LOAD_STAGE(s + 2);
        else             CP_ASYNC_COMMIT();
    }

#pragma unroll
    for (int mt = 0; mt < 2; mt++) {
#pragma unroll
        for (int nt = 0; nt < 8; nt++) {
            const float* d = acc[mt][nt];
            const int r0 = m0 + warp_m*32 + mt*16 + g;
            const int r1 = r0 + 8;
            const int n  = n0 + warp_n*64 + nt*8 + 2*t;
            const float2 b2 = *(const float2*)(bias + n);
            float v00 = d[0] + b2.x, v01 = d[1] + b2.y;
            float v10 = d[2] + b2.x, v11 = d[3] + b2.y;
            if (epi == 0 || epi == 3) {
                v00 *= scale; v01 *= scale; v10 *= scale; v11 *= scale;
                const int hh  = n >> 7;
                const int dd  = n & (DD - 1);
                const int b0i = r0 >> 11, t0i = r0 & (TT-1);
                const int b1i = r1 >> 11, t1i = r1 & (TT-1);
                if (epi == 0) {   // [B,H,T,D]
                    const size_t i0 = (((size_t)(b0i*HH + hh))*TT + t0i)*DD + dd;
                    const size_t i1 = (((size_t)(b1i*HH + hh))*TT + t1i)*DD + dd;
                    *(__half2*)(outh + i0) = __floats2half2_rn(v00, v01);
                    *(__half2*)(outh + i1) = __floats2half2_rn(v10, v11);
                } else {          // [B,H,D,T] transposed
                    const size_t c0 = (((size_t)(b0i*HH + hh))*DD + dd)*TT + t0i;
                    const size_t c1 = (((size_t)(b1i*HH + hh))*DD + dd)*TT + t1i;
                    outh[c0] = __float2half_rn(v00); outh[c0 + TT] = __float2half_rn(v01);
                    outh[c1] = __float2half_rn(v10); outh[c1 + TT] = __float2half_rn(v11);
                }
            } else if (epi == 1) {
                *(float2*)(out + (size_t)r0*CC + n) = make_float2(v00, v01);
                *(float2*)(out + (size_t)r1*CC + n) = make_float2(v10, v11);
            } else {
                const float mk0 = mask[r0], mk1 = mask[r1];
                *(float2*)(out + (size_t)r0*CC + n) = make_float2(v00*mk0, v01*mk0);
                *(float2*)(out + (size_t)r1*CC + n) = make_float2(v10*mk1, v11*mk1);
            }
        }
    }
}

// ---------------------------------------------------------------------------
// Fused convert fp32 -> fp16: x (2 regions) + 5 weights (contiguous in g_w).
// ---------------------------------------------------------------------------
__global__ __launch_bounds__(256) void cvt_all_kernel(
    const float* __restrict__ x,
    const float* __restrict__ w0, const float* __restrict__ w1,
    const float* __restrict__ w2, const float* __restrict__ w3,
    const float* __restrict__ w4,
    __half* __restrict__ xo, __half* __restrict__ wo)
{
    const int region = blockIdx.x >> 12;            // 4096 blocks per region
    const int bi     = blockIdx.x & 4095;
    const int i      = bi * 256 + threadIdx.x;      // float4 index within region

    const float* src;
    __half* dst;
    if (region < 2) {
        src = x  + (size_t)region * (CC*CC);
        dst = xo + (size_t)region * (CC*CC);
    } else {
        const int w = region - 2;
        src = (w == 0) ? w0 : (w == 1) ? w1 : (w == 2) ? w2 : (w == 3) ? w3 : w4;
        dst = wo + (size_t)w * (CC*CC);
    }

    float4 v = ((const float4*)src)[i];
    union U { __half h[4]; uint2 u; } O;
    O.h[0] = __float2half_rn(v.x); O.h[1] = __float2half_rn(v.y);
    O.h[2] = __float2half_rn(v.z); O.h[3] = __float2half_rn(v.w);
    ((uint2*)dst)[i] = O.u;
}

// ---------------------------------------------------------------------------
// Causal flash attention on mma.sync, fp16 (unchanged — R16-validated).
// ---------------------------------------------------------------------------
#define FQS 272                      // Q/K smem row stride bytes
#define FVS 144                      // V^T smem row stride bytes
#define FQ_TILE (128*FQS)            // 34816
#define FK_TILE (64*FQS)             // 17408
#define FV_TILE (128*FVS)            // 18432
#define FKV_STAGE (FK_TILE + FV_TILE)       // 35840
#define FLASH_SMEM (FQ_TILE + 2*FKV_STAGE)  // 106496

__global__ __launch_bounds__(256) void flash_mma_kernel(
    const __half* __restrict__ q, const __half* __restrict__ k,
    const __half* __restrict__ v, __half* __restrict__ AH)
{
    extern __shared__ char sm_[];
    const uint32_t sb = smem_u32(sm_);
    const int tid  = threadIdx.x;
    const int wid  = tid >> 5;
    const int lane = tid & 31;
    const int g    = lane >> 2;
    const int t    = lane & 3;
    const int qt   = blockIdx.x;
    const int bh   = blockIdx.y;
    const int b    = bh >> 4;
    const int h    = bh & 15;

    const __half* Q = q + (size_t)bh*TT*DD + (size_t)qt*128*DD;
    const __half* K = k + (size_t)bh*TT*DD;
    const __half* V = v + (size_t)bh*DD*TT;   // [d][t]

    // Q tile: 128 rows x 16 chunks = 2048 chunks / 256 thr = 8 each
#pragma unroll
    for (int i = 0; i < 8; i++) {
        const int cid = i*256 + tid;
        const int row = cid >> 4, ch = cid & 15;
        CP_ASYNC_16(sb + (uint32_t)row*FQS + (uint32_t)ch*16,
                    Q + (size_t)row*DD + ch*8);
    }
    auto LOAD_STAGE = [&](int s) {
        const uint32_t base = sb + FQ_TILE + (uint32_t)(s & 1)*FKV_STAGE;
#pragma unroll
        for (int i = 0; i < 4; i++) {      // K: 64 rows x 16 chunks
            const int cid = i*256 + tid;
            const int row = cid >> 4, ch = cid & 15;
            CP_ASYNC_16(base + (uint32_t)row*FQS + (uint32_t)ch*16,
                        K + (size_t)(s*64 + row)*DD + ch*8);
        }
#pragma unroll
        for (int i = 0; i < 4; i++) {      // V: 128 rows x 8 chunks
            const int cid = i*256 + tid;
            const int row = cid >> 3, ch = cid & 7;
            CP_ASYNC_16(base + FK_TILE + (uint32_t)row*FVS + (uint32_t)ch*16,
                        V + (size_t)row*TT + s*64 + ch*8);
        }
        CP_ASYNC_COMMIT();
    };

    LOAD_STAGE(0);   // Q cps join stage-0's group
    LOAD_STAGE(1);

    const int NT = 2*qt + 2;
    float mI[2] = {-1e30f, -1e30f};
    float lI[2] = {0.f, 0.f};
    float o[16][4];
#pragma unroll
    for (int nt = 0; nt < 16; nt++)
#pragma unroll
        for (int e = 0; e < 4; e++) o[nt][e] = 0.f;

    const int row0g = qt*128 + wid*16 + g;
    const int row1g = row0g + 8;

    for (int kt = 0; kt < NT; kt++) {
        CP_ASYNC_WAIT1();
        __syncthreads();
        const uint32_t base = sb + FQ_TILE + (uint32_t)(kt & 1)*FKV_STAGE;
        const uint32_t pK = base;
        const uint32_t pV = base + FK_TILE;

        const bool active = (kt*64 <= qt*128 + wid*16 + 15);
        if (active) {
            float s[8][4];
#pragma unroll
            for (int nt = 0; nt < 8; nt++)
#pragma unroll
                for (int e = 0; e < 4; e++) s[nt][e] = 0.f;

#pragma unroll
            for (int k8 = 0; k8 < 8; k8++) {
                const int kb = k8*32 + 4*t;
                const int rA = wid*16 + g;
                uint32_t aF[4];
                aF[0] = lds32(sb + rA*FQS + kb);
                aF[1] = lds32(sb + (rA+8)*FQS + kb);
                aF[2] = lds32(sb + rA*FQS + kb + 16);
                aF[3] = lds32(sb + (rA+8)*FQS + kb + 16);
#pragma unroll
                for (int nt = 0; nt < 8; nt++) {
                    const int rB = nt*8 + g;
                    uint32_t k0 = lds32(pK + rB*FQS + kb);
                    uint32_t k1 = lds32(pK + rB*FQS + kb + 16);
                    mma16816h(s[nt], aF, k0, k1);
                }
            }

            if (kt >= 2*qt) {
#pragma unroll
                for (int nt = 0; nt < 8; nt++) {
                    const int c0 = kt*64 + nt*8 + 2*t;
                    const int c1 = c0 + 1;
                    if (c0 > row0g) s[nt][0] = -1e30f;
                    if (c1 > row0g) s[nt][1] = -1e30f;
                    if (c0 > row1g) s[nt][2] = -1e30f;
                    if (c1 > row1g) s[nt][3] = -1e30f;
                }
            }

            float mt0 = -1e30f, mt1 = -1e30f;
#pragma unroll
            for (int nt = 0; nt < 8; nt++) {
                mt0 = fmaxf(mt0, fmaxf(s[nt][0], s[nt][1]));
                mt1 = fmaxf(mt1, fmaxf(s[nt][2], s[nt][3]));
            }
            mt0 = fmaxf(mt0, __shfl_xor_sync(0xffffffffu, mt0, 1));
            mt0 = fmaxf(mt0, __shfl_xor_sync(0xffffffffu, mt0, 2));
            mt1 = fmaxf(mt1, __shfl_xor_sync(0xffffffffu, mt1, 1));
            mt1 = fmaxf(mt1, __shfl_xor_sync(0xffffffffu, mt1, 2));
            const float mn0 = fmaxf(mI[0], mt0);
            const float mn1 = fmaxf(mI[1], mt1);
            const float corr0 = __expf(mI[0] - mn0);
            const float corr1 = __expf(mI[1] - mn1);
            mI[0] = mn0; mI[1] = mn1;

            float rs0 = 0.f, rs1 = 0.f;
#pragma unroll
            for (int nt = 0; nt < 8; nt++) {
                s[nt][0] = __expf(s[nt][0] - mn0); rs0 += s[nt][0];
                s[nt][1] = __expf(s[nt][1] - mn0); rs0 += s[nt][1];
                s[nt][2] = __expf(s[nt][2] - mn1); rs1 += s[nt][2];
                s[nt][3] = __expf(s[nt][3] - mn1); rs1 += s[nt][3];
            }
            rs0 += __shfl_xor_sync(0xffffffffu, rs0, 1);
            rs0 += __shfl_xor_sync(0xffffffffu, rs0, 2);
            rs1 += __shfl_xor_sync(0xffffffffu, rs1, 1);
            rs1 += __shfl_xor_sync(0xffffffffu, rs1, 2);
            lI[0] = lI[0]*corr0 + rs0;
            lI[1] = lI[1]*corr1 + rs1;

#pragma unroll
            for (int nt = 0; nt < 16; nt++) {
                o[nt][0] *= corr0; o[nt][1] *= corr0;
                o[nt][2] *= corr1; o[nt][3] *= corr1;
            }

            // pack P frags (A-layout) fp16
            uint32_t ph[4][4];
#pragma unroll
            for (int k4 = 0; k4 < 4; k4++) {
                const int e0 = 2*k4, e1 = 2*k4 + 1;
                ph[k4][0] = pack_h2(s[e0][0], s[e0][1]);
                ph[k4][1] = pack_h2(s[e0][2], s[e0][3]);
                ph[k4][2] = pack_h2(s[e1][0], s[e1][1]);
                ph[k4][3] = pack_h2(s[e1][2], s[e1][3]);
            }

            // O += P V.  B operand: V^T smem [d][s]
#pragma unroll
            for (int k4 = 0; k4 < 4; k4++) {
                const int kb2 = k4*32 + 4*t;
#pragma unroll
                for (int nt = 0; nt < 16; nt++) {
                    const int rB = nt*8 + g;
                    uint32_t v0 = lds32(pV + rB*FVS + kb2);
                    uint32_t v1 = lds32(pV + rB*FVS + kb2 + 16);
                    mma16816h(o[nt], ph[k4], v0, v1);
                }
            }
        }
        __syncthreads();
        if (kt + 2 < NT) LOAD_STAGE(kt + 2);
        else             CP_ASYNC_COMMIT();
    }

    // epilogue: write fp16 directly (feeds proj GEMM)
    const float inv0 = 1.0f / lI[0];
    const float inv1 = 1.0f / lI[1];
    __half* a0 = AH + ((size_t)(b*TT + row0g))*CC + h*DD;
    __half* a1 = AH + ((size_t)(b*TT + row1g))*CC + h*DD;
#pragma unroll
    for (int nt = 0; nt < 16; nt++) {
        const int col = nt*8 + 2*t;
        *(__half2*)(a0 + col) = __floats2half2_rn(o[nt][0]*inv0, o[nt][1]*inv0);
        *(__half2*)(a1 + col) = __floats2half2_rn(o[nt][2]*inv1, o[nt][3]*inv1);
    }
}

// ---------------------------------------------------------------------------
// Fused LayerNorm(z)*g+b + residual.  CVT=1 also emits fp16 of out.
// ---------------------------------------------------------------------------
template <int CVT>
__global__ __launch_bounds__(256) void ln_add_kernel(
    const float* __restrict__ z, const float* __restrict__ res,
    const float* __restrict__ gam, const float* __restrict__ bet,
    float* __restrict__ out, __half* __restrict__ ho)
{
    __shared__ float red[256];
    const int row = blockIdx.x;
    const int tid = threadIdx.x;
    const float* zr = z + (size_t)row * CC;

    float v[8];
#pragma unroll
    for (int i = 0; i < 2; i++) {
        float4 t4 = *(const float4*)(zr + i*1024 + tid*4);
        v[i*4+0] = t4.x; v[i*4+1] = t4.y; v[i*4+2] = t4.z; v[i*4+3] = t4.w;
    }

    float s = 0.f;
#pragma unroll
    for (int i = 0; i < 8; i++) s += v[i];
    red[tid] = s; __syncthreads();
#pragma unroll
    for (int off = 128; off; off >>= 1) {
        if (tid < off) red[tid] += red[tid + off];
        __syncthreads();
    }
    const float mean = red[0] * (1.0f / 2048.0f);
    __syncthreads();

    float vs = 0.f;
#pragma unroll
    for (int i = 0; i < 8; i++) { const float d = v[i] - mean; vs += d * d; }
    red[tid] = vs; __syncthreads();
#pragma unroll
    for (int off = 128; off; off >>= 1) {
        if (tid < off) red[tid] += red[tid + off];
        __syncthreads();
    }
    const float rstd = rsqrtf(red[0] * (1.0f / 2048.0f) + 1e-6f);

    const float* rr = res + (size_t)row * CC;
    float* orow = out + (size_t)row * CC;
#pragma unroll
    for (int i = 0; i < 2; i++) {
        const int c0 = i*1024 + tid*4;
        float4 g4 = *(const float4*)(gam + c0);
        float4 b4 = *(const float4*)(bet + c0);
        float4 r4 = *(const float4*)(rr + c0);
        float4 ov;
        ov.x = (v[i*4+0] - mean)*rstd*g4.x + b4.x + r4.x;
        ov.y = (v[i*4+1] - mean)*rstd*g4.y + b4.y + r4.y;
        ov.z = (v[i*4+2] - mean)*rstd*g4.z + b4.z + r4.z;
        ov.w = (v[i*4+3] - mean)*rstd*g4.w + b4.w + r4.w;
        *(float4*)(orow + c0) = ov;
        if (CVT) {
            union U { __half h[4]; uint2 u; } O;
            O.h[0] = __float2half_rn(ov.x); O.h[1] = __float2half_rn(ov.y);
            O.h[2] = __float2half_rn(ov.z); O.h[3] = __float2half_rn(ov.w);
            *(uint2*)(ho + (size_t)row*CC + c0) = O.u;
        }
    }
}

// ---------------------------------------------------------------------------
extern "C" void kernel_launch(void* const* d_in, const int* in_sizes, int n_in,
                              void* d_out, int out_size)
{
    const float* x    = (const float*)d_in[0];
    const float* mask = (const float*)d_in[1];
    const float* Wq   = (const float*)d_in[2];
    const float* bq   = (const float*)d_in[3];
    const float* Wk   = (const float*)d_in[4];
    const float* bk   = (const float*)d_in[5];
    const float* Wv   = (const float*)d_in[6];
    const float* bv   = (const float*)d_in[7];
    const float* Wp   = (const float*)d_in[8];
    const float* bp   = (const float*)d_in[9];
    const float* Wfc  = (const float*)d_in[10];
    const float* bfc  = (const float*)d_in[11];
    const float* ln_g = (const float*)d_in[12];
    const float* ln_b = (const float*)d_in[13];

    float *t0, *t1;
    __half *q, *k, *v, *xo, *a, *w;
    cudaGetSymbolAddress((void**)&q,  g_q);
    cudaGetSymbolAddress((void**)&k,  g_k);
    cudaGetSymbolAddress((void**)&v,  g_v);
    cudaGetSymbolAddress((void**)&t0, g_t0);
    cudaGetSymbolAddress((void**)&t1, g_t1);
    cudaGetSymbolAddress((void**)&xo, g_x);
    cudaGetSymbolAddress((void**)&a,  g_a);
    cudaGetSymbolAddress((void**)&w,  g_w);

    cudaFuncSetAttribute(gemm_mma_kernel<1>,
                         cudaFuncAttributeMaxDynamicSharedMemorySize, GEMM_SMEM);
    cudaFuncSetAttribute(gemm_mma_kernel<0>,
                         cudaFuncAttributeMaxDynamicSharedMemorySize, GEMM_SMEM);
    cudaFuncSetAttribute(flash_mma_kernel,
                         cudaFuncAttributeMaxDynamicSharedMemorySize, FLASH_SMEM);

    const dim3 gg(CC/128, MM/128);          // (16, 32)
    const dim3 gqkv(CC/128, MM/128, 3);     // fused QKV

    // fused convert: x (2 regions) + 5 weights (5 regions)
    cvt_all_kernel<<<7*4096, 256>>>(x, Wq, Wk, Wv, Wp, Wfc, xo, w);

    // fused QKV projections -> fp16; Q scaled; V transposed [B,H,D,T]
    gemm_mma_kernel<1><<<gqkv, 256, GEMM_SMEM>>>(
        xo, w, bq, bk, bv, nullptr, nullptr, q, k, v, QSCALE, 0);

    // causal flash attention (fp16) -> a
    flash_mma_kernel<<<dim3(TT/128, BB*HH), 256, FLASH_SMEM>>>(q, k, v, a);

    // output projection (+bias, *mask) -> t0
    gemm_mma_kernel<0><<<gg, 256, GEMM_SMEM>>>(
        a, w + 3*(size_t)CC*CC, bp, nullptr, nullptr, mask, t0,
        nullptr, nullptr, nullptr, 1.0f, 2);

    // x1 = LN(t0) + x -> t1 (+ fp16 to a for FC GEMM)
    ln_add_kernel<1><<<MM, 256>>>(t0, x, ln_g, ln_b, t1, a);

    // fc = x1 @ Wfc^T + bfc -> t0
    gemm_mma_kernel<0><<<gg, 256, GEMM_SMEM>>>(
        a, w + 4*(size_t)CC*CC, bfc, nullptr, nullptr, nullptr, t0,
        nullptr, nullptr, nullptr, 1.0f, 1);

    // out = LN(t0) + x1
    ln_add_kernel<0><<<MM, 256>>>(t0, t1, ln_g, ln_b, (float*)d_out, nullptr);
}